// round 1
// baseline (speedup 1.0000x reference)
#include <cuda_runtime.h>
#include <cuda_bf16.h>
#include <math.h>

#define BATCH 4
#define NPTS  8192
#define DIM   128
#define DOUT  256
#define NH    4
#define HD    64
#define KNBR  16
#define ROWS  (BATCH*NPTS)          // 32768
#define NROWS (BATCH*NPTS*KNBR)     // 524288

// ---------------- scratch (device globals; no runtime alloc) ----------------
__device__ float4 g_xyzw[ROWS];
__device__ int    g_knn[NROWS];
__device__ float  g_lnf[ROWS*DIM];
__device__ float  g_qf [ROWS*DOUT];
__device__ float  g_kf [ROWS*DOUT];
__device__ float  g_vf [ROWS*DOUT];
__device__ float  g_lnq[ROWS*DOUT];
__device__ float  g_h1 [(size_t)NROWS*HD];
__device__ float  g_pos[(size_t)NROWS*HD];
__device__ float  g_mid[ROWS*DOUT];
__device__ float  g_fc1[ROWS*DOUT];
__device__ float  g_fc2[ROWS*DOUT];

// ---------------- pack xyz + squared norm ----------------
__global__ void k_pack(const float* __restrict__ xyz) {
    int i = blockIdx.x * 256 + threadIdx.x;
    if (i >= ROWS) return;
    float x = xyz[i*3+0], y = xyz[i*3+1], z = xyz[i*3+2];
    g_xyzw[i] = make_float4(x, y, z, x*x + y*y + z*z);
}

// ---------------- brute-force KNN (top-16, stable ties) ----------------
#define KNN_INSERT(kk, ii)                                              \
  do {                                                                  \
    bd[15] = (kk); bi[15] = (ii);                                       \
    _Pragma("unroll")                                                   \
    for (int s = 15; s > 0; --s) {                                      \
      if (bd[s] < bd[s-1]) {                                            \
        float tf = bd[s]; bd[s] = bd[s-1]; bd[s-1] = tf;                \
        int   ti = bi[s]; bi[s] = bi[s-1]; bi[s-1] = ti;                \
      }                                                                 \
    }                                                                   \
  } while (0)

__global__ void __launch_bounds__(128) k_knn() {
    __shared__ float4 cand[2048];
    int b = blockIdx.y;
    int q = blockIdx.x * 128 + threadIdx.x;
    float4 me = g_xyzw[b*NPTS + q];
    float qx2 = -2.f*me.x, qy2 = -2.f*me.y, qz2 = -2.f*me.z;
    float bd[16]; int bi[16];
    #pragma unroll
    for (int s = 0; s < 16; ++s) { bd[s] = 3.402823e38f; bi[s] = 0; }

    for (int tile = 0; tile < NPTS/2048; ++tile) {
        __syncthreads();
        for (int i = threadIdx.x; i < 2048; i += 128)
            cand[i] = g_xyzw[b*NPTS + tile*2048 + i];
        __syncthreads();
        int base = tile * 2048;
        #pragma unroll 1
        for (int j = 0; j < 2048; j += 4) {
            float4 c0 = cand[j+0], c1 = cand[j+1], c2 = cand[j+2], c3 = cand[j+3];
            float k0 = fmaf(qx2,c0.x,fmaf(qy2,c0.y,fmaf(qz2,c0.z,c0.w)));
            float k1 = fmaf(qx2,c1.x,fmaf(qy2,c1.y,fmaf(qz2,c1.z,c1.w)));
            float k2 = fmaf(qx2,c2.x,fmaf(qy2,c2.y,fmaf(qz2,c2.z,c2.w)));
            float k3 = fmaf(qx2,c3.x,fmaf(qy2,c3.y,fmaf(qz2,c3.z,c3.w)));
            float mn = fminf(fminf(k0,k1), fminf(k2,k3));
            if (mn < bd[15]) {
                if (k0 < bd[15]) KNN_INSERT(k0, base+j+0);
                if (k1 < bd[15]) KNN_INSERT(k1, base+j+1);
                if (k2 < bd[15]) KNN_INSERT(k2, base+j+2);
                if (k3 < bd[15]) KNN_INSERT(k3, base+j+3);
            }
        }
    }
    int o = (b*NPTS + q) * KNBR;
    #pragma unroll
    for (int s = 0; s < 16; ++s) g_knn[o+s] = bi[s];
}

// ---------------- LayerNorm over dim=128 (warp per row) ----------------
__global__ void k_ln1(const float* __restrict__ x, const float* __restrict__ g,
                      const float* __restrict__ bta) {
    int warp = (blockIdx.x * blockDim.x + threadIdx.x) >> 5;
    int lane = threadIdx.x & 31;
    const float4* row = (const float4*)(x + (size_t)warp * DIM);
    float4 v = row[lane];
    float s = v.x + v.y + v.z + v.w;
    #pragma unroll
    for (int o = 16; o; o >>= 1) s += __shfl_xor_sync(~0u, s, o);
    float mu = s * (1.f/128.f);
    float dx = v.x-mu, dy = v.y-mu, dz = v.z-mu, dw = v.w-mu;
    float s2 = dx*dx + dy*dy + dz*dz + dw*dw;
    #pragma unroll
    for (int o = 16; o; o >>= 1) s2 += __shfl_xor_sync(~0u, s2, o);
    float rs = rsqrtf(s2 * (1.f/128.f) + 1e-5f);
    float4 gg = ((const float4*)g)[lane];
    float4 bb = ((const float4*)bta)[lane];
    float4 r;
    r.x = dx*rs*gg.x + bb.x; r.y = dy*rs*gg.y + bb.y;
    r.z = dz*rs*gg.z + bb.z; r.w = dw*rs*gg.w + bb.w;
    ((float4*)g_lnf)[warp*32 + lane] = r;
}

// ---------------- generic tiled fp32 GEMM: C = act(A[MxK] @ W[KxN] + b) ----------------
__global__ void __launch_bounds__(256) k_gemm(const float* __restrict__ A,
                                              const float* __restrict__ W,
                                              const float* __restrict__ bias,
                                              float* __restrict__ C,
                                              int M, int N, int K, int relu) {
    __shared__ float As[16][68];
    __shared__ float Ws[16][64];
    int r0 = blockIdx.x * 64, c0 = blockIdx.y * 64;
    int t = threadIdx.x;
    int tx = t & 15, ty = t >> 4;
    int ar = t >> 2,  ac4 = (t & 3) * 4;
    int wr = t >> 4,  wc4 = (t & 15) * 4;
    const float* Ap = A + (size_t)(r0 + ar) * K + ac4;
    const float* Wp = W + (size_t)wr * N + c0 + wc4;
    float acc[4][4] = {};
    for (int k0 = 0; k0 < K; k0 += 16) {
        float4 av = *(const float4*)(Ap + k0);
        float4 wv = *(const float4*)(Wp + (size_t)k0 * N);
        __syncthreads();
        As[ac4+0][ar] = av.x; As[ac4+1][ar] = av.y;
        As[ac4+2][ar] = av.z; As[ac4+3][ar] = av.w;
        *(float4*)&Ws[wr][wc4] = wv;
        __syncthreads();
        #pragma unroll
        for (int k = 0; k < 16; ++k) {
            float4 a = *(const float4*)&As[k][ty*4];
            float4 w = *(const float4*)&Ws[k][tx*4];
            float aa[4] = {a.x, a.y, a.z, a.w};
            float ww[4] = {w.x, w.y, w.z, w.w};
            #pragma unroll
            for (int i = 0; i < 4; ++i)
                #pragma unroll
                for (int j = 0; j < 4; ++j)
                    acc[i][j] = fmaf(aa[i], ww[j], acc[i][j]);
        }
    }
    float4 bv = *(const float4*)(bias + c0 + tx*4);
    float bb[4] = {bv.x, bv.y, bv.z, bv.w};
    #pragma unroll
    for (int i = 0; i < 4; ++i) {
        float4 o;
        o.x = acc[i][0] + bb[0]; o.y = acc[i][1] + bb[1];
        o.z = acc[i][2] + bb[2]; o.w = acc[i][3] + bb[3];
        if (relu) {
            o.x = fmaxf(o.x, 0.f); o.y = fmaxf(o.y, 0.f);
            o.z = fmaxf(o.z, 0.f); o.w = fmaxf(o.w, 0.f);
        }
        *(float4*)(C + (size_t)(r0 + ty*4 + i) * N + c0 + tx*4) = o;
    }
}

// ---------------- h1 = relu(relpos @ Wp1 + bp1), relpos built from knn ----------------
__global__ void __launch_bounds__(256) k_h1(const float* __restrict__ xyz,
                                            const float* __restrict__ Wp1,
                                            const float* __restrict__ bp1) {
    __shared__ float w0[64], w1[64], w2[64], bb[64];
    int t = threadIdx.x;
    if (t < 64) { w0[t] = Wp1[t]; w1[t] = Wp1[64+t]; w2[t] = Wp1[128+t]; bb[t] = bp1[t]; }
    __syncthreads();
    int r  = blockIdx.x * 32 + (t >> 3);
    int c0 = (t & 7) * 8;
    int b  = r >> 17;                 // NPTS*KNBR = 131072
    int n  = (r >> 4) & (NPTS - 1);
    int idx = g_knn[r];
    const float* xb = xyz + (size_t)b * NPTS * 3;
    float rx = xb[idx*3+0] - xb[n*3+0];
    float ry = xb[idx*3+1] - xb[n*3+1];
    float rz = xb[idx*3+2] - xb[n*3+2];
    float o[8];
    #pragma unroll
    for (int c = 0; c < 8; ++c) {
        float h = fmaf(rx, w0[c0+c], fmaf(ry, w1[c0+c], fmaf(rz, w2[c0+c], bb[c0+c])));
        o[c] = fmaxf(h, 0.f);
    }
    float4* dst = (float4*)(g_h1 + (size_t)r * HD + c0);
    dst[0] = make_float4(o[0], o[1], o[2], o[3]);
    dst[1] = make_float4(o[4], o[5], o[6], o[7]);
}

// ---------------- fused attention: gather k/v, logits, softmax, weighted sum ----------------
__global__ void __launch_bounds__(128) k_attn(float* __restrict__ attn_out) {
    __shared__ int   idx_s[16];
    __shared__ float pos_s[16][68];
    __shared__ float k_s[16][260];
    __shared__ float v_s[16][260];
    __shared__ float q_s[256];
    __shared__ float logit_s[64];
    __shared__ float attn_s[64];
    int t  = threadIdx.x;
    int gp = blockIdx.x;                   // b*NPTS + n
    int b  = gp >> 13, n = gp & (NPTS-1);

    if (t < 16) idx_s[t] = g_knn[gp*KNBR + t];
    if (t < 64) ((float4*)q_s)[t] = ((const float4*)(g_qf + (size_t)gp * DOUT))[t];
    {
        const float4* ps = (const float4*)(g_pos + (size_t)gp * KNBR * HD);
        #pragma unroll
        for (int e = t; e < 256; e += 128) {
            int jj = e >> 4, cc = e & 15;
            *(float4*)&pos_s[jj][cc*4] = ps[e];
        }
    }
    __syncthreads();
    #pragma unroll
    for (int e = t; e < 1024; e += 128) {
        int jj = e >> 6, cc = e & 63;
        size_t rowb = ((size_t)b * NPTS + idx_s[jj]) * DOUT;
        *(float4*)&k_s[jj][cc*4] = *(const float4*)(g_kf + rowb + cc*4);
        *(float4*)&v_s[jj][cc*4] = *(const float4*)(g_vf + rowb + cc*4);
    }
    __syncthreads();
    {
        int p = t >> 1, half = t & 1;
        int jj = p & 15, h = p >> 4;
        float s = 0.f;
        int cb = half * 32;
        #pragma unroll
        for (int c = 0; c < 32; ++c) {
            int cc = cb + c;
            s = fmaf(q_s[h*64+cc], k_s[jj][h*64+cc] + pos_s[jj][cc], s);
        }
        s += __shfl_xor_sync(~0u, s, 1);
        if (half == 0) logit_s[h*16 + jj] = s * 0.125f;
    }
    __syncthreads();
    if (t < 4) {
        int h = t;
        float l[16], mx = -3.402823e38f;
        #pragma unroll
        for (int j = 0; j < 16; ++j) { l[j] = logit_s[h*16+j]; mx = fmaxf(mx, l[j]); }
        float sum = 0.f;
        #pragma unroll
        for (int j = 0; j < 16; ++j) { l[j] = expf(l[j] - mx); sum += l[j]; }
        float inv = 1.f / sum;
        size_t ob = (((size_t)b*NH + h) * NPTS + n) * KNBR;
        #pragma unroll
        for (int j = 0; j < 16; ++j) {
            float a = l[j] * inv;
            attn_s[h*16+j] = a;
            attn_out[ob + j] = a;
        }
    }
    __syncthreads();
    #pragma unroll
    for (int e = t; e < 256; e += 128) {
        int h = e >> 6, c = e & 63;
        float s = 0.f;
        #pragma unroll
        for (int j = 0; j < 16; ++j)
            s = fmaf(attn_s[h*16+j], v_s[j][e] + pos_s[j][c], s);
        g_mid[(size_t)gp * DOUT + e] = s;
    }
}

// ---------------- final: LN(fc2)*g2+b2 + lnq -> out ----------------
__global__ void k_final(const float* __restrict__ g2, const float* __restrict__ b2,
                        float* __restrict__ out) {
    int warp = (blockIdx.x * blockDim.x + threadIdx.x) >> 5;
    int lane = threadIdx.x & 31;
    const float4* row = (const float4*)(g_fc2 + (size_t)warp * DOUT);
    float4 v0 = row[lane*2], v1 = row[lane*2+1];
    float s = v0.x+v0.y+v0.z+v0.w + v1.x+v1.y+v1.z+v1.w;
    #pragma unroll
    for (int o = 16; o; o >>= 1) s += __shfl_xor_sync(~0u, s, o);
    float mu = s * (1.f/256.f);
    float d0x=v0.x-mu, d0y=v0.y-mu, d0z=v0.z-mu, d0w=v0.w-mu;
    float d1x=v1.x-mu, d1y=v1.y-mu, d1z=v1.z-mu, d1w=v1.w-mu;
    float s2 = d0x*d0x+d0y*d0y+d0z*d0z+d0w*d0w + d1x*d1x+d1y*d1y+d1z*d1z+d1w*d1w;
    #pragma unroll
    for (int o = 16; o; o >>= 1) s2 += __shfl_xor_sync(~0u, s2, o);
    float rs = rsqrtf(s2 * (1.f/256.f) + 1e-5f);
    float4 gA = ((const float4*)g2)[lane*2],  gB = ((const float4*)g2)[lane*2+1];
    float4 bA = ((const float4*)b2)[lane*2],  bB = ((const float4*)b2)[lane*2+1];
    const float4* lq = (const float4*)(g_lnq + (size_t)warp * DOUT);
    float4 qA = lq[lane*2], qB = lq[lane*2+1];
    float4 oA, oB;
    oA.x = d0x*rs*gA.x + bA.x + qA.x; oA.y = d0y*rs*gA.y + bA.y + qA.y;
    oA.z = d0z*rs*gA.z + bA.z + qA.z; oA.w = d0w*rs*gA.w + bA.w + qA.w;
    oB.x = d1x*rs*gB.x + bB.x + qB.x; oB.y = d1y*rs*gB.y + bB.y + qB.y;
    oB.z = d1z*rs*gB.z + bB.z + qB.z; oB.w = d1w*rs*gB.w + bB.w + qB.w;
    float4* dst = (float4*)(out + (size_t)warp * DOUT);
    dst[lane*2]   = oA;
    dst[lane*2+1] = oB;
}

// ---------------- host launcher ----------------
extern "C" void kernel_launch(void* const* d_in, const int* in_sizes, int n_in,
                              void* d_out, int out_size) {
    const float* xyz      = (const float*)d_in[0];
    const float* features = (const float*)d_in[1];
    const float* Wq  = (const float*)d_in[2];
    const float* bq  = (const float*)d_in[3];
    const float* Wk  = (const float*)d_in[4];
    const float* bk  = (const float*)d_in[5];
    const float* Wv  = (const float*)d_in[6];
    const float* bv  = (const float*)d_in[7];
    const float* Wp1 = (const float*)d_in[8];
    const float* bp1 = (const float*)d_in[9];
    const float* Wp2 = (const float*)d_in[10];
    const float* bp2 = (const float*)d_in[11];
    const float* Wf1 = (const float*)d_in[12];
    const float* bf1 = (const float*)d_in[13];
    const float* Wf2 = (const float*)d_in[14];
    const float* bf2 = (const float*)d_in[15];
    const float* g1  = (const float*)d_in[16];
    const float* b1  = (const float*)d_in[17];
    const float* g2  = (const float*)d_in[18];
    const float* b2  = (const float*)d_in[19];

    float* out      = (float*)d_out;
    float* attn_out = out + (size_t)ROWS * DOUT;

    float *p_lnf, *p_qf, *p_kf, *p_vf, *p_lnq, *p_h1, *p_pos, *p_mid, *p_fc1, *p_fc2;
    cudaGetSymbolAddress((void**)&p_lnf, g_lnf);
    cudaGetSymbolAddress((void**)&p_qf,  g_qf);
    cudaGetSymbolAddress((void**)&p_kf,  g_kf);
    cudaGetSymbolAddress((void**)&p_vf,  g_vf);
    cudaGetSymbolAddress((void**)&p_lnq, g_lnq);
    cudaGetSymbolAddress((void**)&p_h1,  g_h1);
    cudaGetSymbolAddress((void**)&p_pos, g_pos);
    cudaGetSymbolAddress((void**)&p_mid, g_mid);
    cudaGetSymbolAddress((void**)&p_fc1, g_fc1);
    cudaGetSymbolAddress((void**)&p_fc2, g_fc2);

    k_pack<<<ROWS/256, 256>>>(xyz);
    {
        dim3 kg(NPTS/128, BATCH);
        k_knn<<<kg, 128>>>();
    }
    k_ln1<<<ROWS/8, 256>>>(features, g1, b1);

    auto G = [&](const float* A, const float* W, const float* bias, float* C,
                 int M, int N, int K, int relu) {
        dim3 grid(M/64, N/64);
        k_gemm<<<grid, 256>>>(A, W, bias, C, M, N, K, relu);
    };
    G(features, Wq, bq, p_qf,  ROWS,  DOUT, DIM, 0);
    G(features, Wk, bk, p_kf,  ROWS,  DOUT, DIM, 0);
    G(features, Wv, bv, p_vf,  ROWS,  DOUT, DIM, 0);
    G(p_lnf,    Wq, bq, p_lnq, ROWS,  DOUT, DIM, 0);

    k_h1<<<NROWS/32, 256>>>(xyz, Wp1, bp1);
    G(p_h1, Wp2, bp2, p_pos, NROWS, HD, HD, 0);

    k_attn<<<ROWS, 128>>>(attn_out);

    G(p_mid, Wf1, bf1, p_fc1, ROWS, DOUT, DOUT, 1);
    G(p_fc1, Wf2, bf2, p_fc2, ROWS, DOUT, DOUT, 0);

    k_final<<<ROWS/8, 256>>>(g2, b2, out);
}

// round 3
// speedup vs baseline: 1.0160x; 1.0160x over previous
#include <cuda_runtime.h>
#include <cuda_bf16.h>
#include <cstdint>
#include <math.h>

#define BATCH 4
#define NPTS  8192
#define DIM   128
#define DOUT  256
#define NH    4
#define HD    64
#define KNBR  16
#define ROWS  (BATCH*NPTS)          // 32768
#define NROWS (BATCH*NPTS*KNBR)     // 524288

// ---------------- scratch (device globals; no runtime alloc) ----------------
__device__ float4 g_xyzw[ROWS];
__device__ int    g_knn[NROWS];
__device__ __nv_bfloat16 g_feat_h[ROWS*DIM];
__device__ __nv_bfloat16 g_feat_l[ROWS*DIM];
__device__ __nv_bfloat16 g_lnf_h[ROWS*DIM];
__device__ __nv_bfloat16 g_lnf_l[ROWS*DIM];
__device__ float  g_qkv[(size_t)ROWS*768];     // [q|k|v] per row
__device__ float  g_lnq[ROWS*DOUT];
__device__ __nv_bfloat16 g_h1_h[(size_t)NROWS*HD];
__device__ __nv_bfloat16 g_h1_l[(size_t)NROWS*HD];
__device__ float  g_pos[(size_t)NROWS*HD];
__device__ __nv_bfloat16 g_mid_h[ROWS*DOUT];
__device__ __nv_bfloat16 g_mid_l[ROWS*DOUT];
__device__ __nv_bfloat16 g_fc1_h[ROWS*DOUT];
__device__ __nv_bfloat16 g_fc1_l[ROWS*DOUT];
__device__ float  g_fc2[ROWS*DOUT];
// transposed bf16-split weights
__device__ __nv_bfloat16 g_wqkvT_h[768*DIM];
__device__ __nv_bfloat16 g_wqkvT_l[768*DIM];
__device__ __nv_bfloat16 g_wp2T_h[HD*HD];
__device__ __nv_bfloat16 g_wp2T_l[HD*HD];
__device__ __nv_bfloat16 g_wf1T_h[DOUT*DOUT];
__device__ __nv_bfloat16 g_wf1T_l[DOUT*DOUT];
__device__ __nv_bfloat16 g_wf2T_h[DOUT*DOUT];
__device__ __nv_bfloat16 g_wf2T_l[DOUT*DOUT];
__device__ float g_bqkv[768];

// ---------------- small helpers ----------------
__device__ __forceinline__ unsigned pk2(float a, float b) {
    __nv_bfloat162 t = __floats2bfloat162_rn(a, b);
    return *(unsigned*)&t;
}
__device__ __forceinline__ float rndbf(float x) {
    return __bfloat162float(__float2bfloat16_rn(x));
}
__device__ __forceinline__ uint32_t smem_u32(const void* p) {
    uint32_t a;
    asm("{ .reg .u64 t; cvta.to.shared.u64 t, %1; cvt.u32.u64 %0, t; }" : "=r"(a) : "l"(p));
    return a;
}
__device__ __forceinline__ uint32_t swz(uint32_t x) { return x ^ ((x >> 3) & 0x70); }

__device__ __forceinline__ void ldsm4(uint32_t* r, uint32_t addr) {
    asm volatile("ldmatrix.sync.aligned.m8n8.x4.shared.b16 {%0,%1,%2,%3}, [%4];"
        : "=r"(r[0]), "=r"(r[1]), "=r"(r[2]), "=r"(r[3]) : "r"(addr));
}
__device__ __forceinline__ void mma16816(float* c, const uint32_t* a, uint32_t b0, uint32_t b1) {
    asm volatile("mma.sync.aligned.m16n8k16.row.col.f32.bf16.bf16.f32 "
        "{%0,%1,%2,%3}, {%4,%5,%6,%7}, {%8,%9}, {%0,%1,%2,%3};"
        : "+f"(c[0]), "+f"(c[1]), "+f"(c[2]), "+f"(c[3])
        : "r"(a[0]), "r"(a[1]), "r"(a[2]), "r"(a[3]), "r"(b0), "r"(b1));
}

// ---------------- pack xyz + squared norm ----------------
__global__ void k_pack(const float* __restrict__ xyz) {
    int i = blockIdx.x * 256 + threadIdx.x;
    if (i >= ROWS) return;
    float x = xyz[i*3+0], y = xyz[i*3+1], z = xyz[i*3+2];
    g_xyzw[i] = make_float4(x, y, z, x*x + y*y + z*z);
}

// ---------------- brute-force KNN, 4 threads per query ----------------
#define KNN_INSERT(kk, ii)                                              \
  do {                                                                  \
    bd[15] = (kk); bi[15] = (ii);                                       \
    _Pragma("unroll")                                                   \
    for (int ss = 15; ss > 0; --ss) {                                   \
      if (bd[ss] < bd[ss-1]) {                                          \
        float tf = bd[ss]; bd[ss] = bd[ss-1]; bd[ss-1] = tf;            \
        int   ti = bi[ss]; bi[ss] = bi[ss-1]; bi[ss-1] = ti;            \
      }                                                                 \
    }                                                                   \
  } while (0)

__global__ void __launch_bounds__(256) k_knn() {
    __shared__ float4 cand[2048];   // reused as merge lists afterwards
    int t = threadIdx.x;
    int q = t & 63, s = t >> 6;
    int b = blockIdx.y;
    int qg = blockIdx.x * 64 + q;
    float4 me = g_xyzw[b*NPTS + qg];
    float qx2 = -2.f*me.x, qy2 = -2.f*me.y, qz2 = -2.f*me.z;
    float bd[16]; int bi[16];
    #pragma unroll
    for (int i = 0; i < 16; ++i) { bd[i] = 3.402823e38f; bi[i] = 0x7fffffff; }

    for (int tile = 0; tile < 4; ++tile) {
        __syncthreads();
        for (int i = t; i < 2048; i += 256)
            cand[i] = g_xyzw[b*NPTS + tile*2048 + i];
        __syncthreads();
        int sb = s * 512;
        int base = tile * 2048 + sb;
        #pragma unroll 1
        for (int j = 0; j < 512; j += 4) {
            float4 c0 = cand[sb+j+0], c1 = cand[sb+j+1], c2 = cand[sb+j+2], c3 = cand[sb+j+3];
            float k0 = fmaf(qx2,c0.x,fmaf(qy2,c0.y,fmaf(qz2,c0.z,c0.w)));
            float k1 = fmaf(qx2,c1.x,fmaf(qy2,c1.y,fmaf(qz2,c1.z,c1.w)));
            float k2 = fmaf(qx2,c2.x,fmaf(qy2,c2.y,fmaf(qz2,c2.z,c2.w)));
            float k3 = fmaf(qx2,c3.x,fmaf(qy2,c3.y,fmaf(qz2,c3.z,c3.w)));
            float mn = fminf(fminf(k0,k1), fminf(k2,k3));
            if (mn < bd[15]) {
                if (k0 < bd[15]) KNN_INSERT(k0, base+j+0);
                if (k1 < bd[15]) KNN_INSERT(k1, base+j+1);
                if (k2 < bd[15]) KNN_INSERT(k2, base+j+2);
                if (k3 < bd[15]) KNN_INSERT(k3, base+j+3);
            }
        }
    }
    __syncthreads();
    float* lk = (float*)cand;
    int*   li = (int*)(lk + 4096);
    int lo_ = (q*4 + s) * 16;
    #pragma unroll
    for (int i = 0; i < 16; ++i) { lk[lo_+i] = bd[i]; li[lo_+i] = bi[i]; }
    __syncthreads();
    if (t < 64) {
        int b0 = (t*4+0)*16, b1 = (t*4+1)*16, b2 = (t*4+2)*16, b3 = (t*4+3)*16;
        int p0 = 0, p1 = 0, p2 = 0, p3 = 0;
        size_t o = ((size_t)b*NPTS + blockIdx.x*64 + t) * KNBR;
        const float INF = 3.402823e38f;
        for (int r = 0; r < 16; ++r) {
            float k0 = p0 < 16 ? lk[b0+p0] : INF; int i0 = p0 < 16 ? li[b0+p0] : 0x7fffffff;
            float k1 = p1 < 16 ? lk[b1+p1] : INF; int i1 = p1 < 16 ? li[b1+p1] : 0x7fffffff;
            float k2 = p2 < 16 ? lk[b2+p2] : INF; int i2 = p2 < 16 ? li[b2+p2] : 0x7fffffff;
            float k3 = p3 < 16 ? lk[b3+p3] : INF; int i3 = p3 < 16 ? li[b3+p3] : 0x7fffffff;
            float mk = k0; int mi = i0; int sel = 0;
            if (k1 < mk || (k1 == mk && i1 < mi)) { mk = k1; mi = i1; sel = 1; }
            if (k2 < mk || (k2 == mk && i2 < mi)) { mk = k2; mi = i2; sel = 2; }
            if (k3 < mk || (k3 == mk && i3 < mi)) { mk = k3; mi = i3; sel = 3; }
            g_knn[o + r] = mi;
            if (sel == 0) p0++; else if (sel == 1) p1++; else if (sel == 2) p2++; else p3++;
        }
    }
}

// ---------------- split fp32 -> bf16 hi/lo ----------------
__global__ void k_cvt_split(const float* __restrict__ x, __nv_bfloat16* __restrict__ h,
                            __nv_bfloat16* __restrict__ l, int n4) {
    int i = blockIdx.x * 256 + threadIdx.x;
    if (i >= n4) return;
    float4 v = ((const float4*)x)[i];
    float hx = rndbf(v.x), hy = rndbf(v.y), hz = rndbf(v.z), hw = rndbf(v.w);
    uint2 hh = { pk2(v.x, v.y), pk2(v.z, v.w) };
    uint2 ll = { pk2(v.x - hx, v.y - hy), pk2(v.z - hz, v.w - hw) };
    ((uint2*)h)[i] = hh;
    ((uint2*)l)[i] = ll;
}

// ---------------- transpose + split weight: W[K,N] -> T[N,K] bf16 hi/lo ----------------
__global__ void k_cvt_wT(const float* __restrict__ W, __nv_bfloat16* __restrict__ Th,
                         __nv_bfloat16* __restrict__ Tl, int Kd, int Nd) {
    int i = blockIdx.x * 256 + threadIdx.x;
    if (i >= Kd * Nd) return;
    int n = i / Kd, k = i % Kd;
    float x = W[(size_t)k * Nd + n];
    float hx = rndbf(x);
    Th[i] = __float2bfloat16_rn(x);
    Tl[i] = __float2bfloat16_rn(x - hx);
}

__global__ void k_bpack(const float* __restrict__ a, const float* __restrict__ b,
                        const float* __restrict__ c) {
    int t = threadIdx.x + blockIdx.x * 256;
    if (t < 256)      g_bqkv[t] = a[t];
    else if (t < 512) g_bqkv[t] = b[t-256];
    else if (t < 768) g_bqkv[t] = c[t-512];
}

// ---------------- LayerNorm dim=128 -> bf16 hi/lo ----------------
__global__ void k_ln1(const float* __restrict__ x, const float* __restrict__ g,
                      const float* __restrict__ bta) {
    int warp = (blockIdx.x * blockDim.x + threadIdx.x) >> 5;
    int lane = threadIdx.x & 31;
    const float4* row = (const float4*)(x + (size_t)warp * DIM);
    float4 v = row[lane];
    float s = v.x + v.y + v.z + v.w;
    #pragma unroll
    for (int o = 16; o; o >>= 1) s += __shfl_xor_sync(~0u, s, o);
    float mu = s * (1.f/128.f);
    float dx = v.x-mu, dy = v.y-mu, dz = v.z-mu, dw = v.w-mu;
    float s2 = dx*dx + dy*dy + dz*dz + dw*dw;
    #pragma unroll
    for (int o = 16; o; o >>= 1) s2 += __shfl_xor_sync(~0u, s2, o);
    float rs = rsqrtf(s2 * (1.f/128.f) + 1e-5f);
    float4 gg = ((const float4*)g)[lane];
    float4 bb = ((const float4*)bta)[lane];
    float rx = dx*rs*gg.x + bb.x, ry = dy*rs*gg.y + bb.y;
    float rz = dz*rs*gg.z + bb.z, rw = dw*rs*gg.w + bb.w;
    float hx = rndbf(rx), hy = rndbf(ry), hz = rndbf(rz), hw = rndbf(rw);
    int idx = warp*32 + lane;   // uint2 index (4 bf16 per uint2)
    ((uint2*)g_lnf_h)[idx] = make_uint2(pk2(rx, ry), pk2(rz, rw));
    ((uint2*)g_lnf_l)[idx] = make_uint2(pk2(rx-hx, ry-hy), pk2(rz-hz, rw-hw));
}

// ---------------- mma.sync GEMM (bf16 split x3), C = act(A@B^T + bias) ----------------
// A: [M,K] bf16 hi/lo row-major. B: [Ntot,K] bf16 hi/lo row-major (transposed weights).
// CTA 256 threads, tile M=128 x NT. Warps 4(M) x 2(N); warp tile 32 x NT/2.
#define SM_AH 0
#define SM_AL 16384
#define SM_BH 32768
#define SM_BL 49152
#define SMEM_MG 65536

template<int NT>
__global__ void __launch_bounds__(256) k_mgemm(
    const __nv_bfloat16* __restrict__ Ah, const __nv_bfloat16* __restrict__ Al,
    const __nv_bfloat16* __restrict__ Bh, const __nv_bfloat16* __restrict__ Bl,
    const float* __restrict__ bias,
    float* __restrict__ Cf, __nv_bfloat16* __restrict__ Ch, __nv_bfloat16* __restrict__ Cl,
    int K, int ldc, int relu)
{
    constexpr int WN = NT / 2;       // warp n-tile (64 or 32)
    constexpr int NB = WN / 16;      // x4-ldmatrix groups per warp
    extern __shared__ char sm[];
    uint32_t smb = smem_u32(sm);
    int t = threadIdx.x, lane = t & 31, w = t >> 5;
    int wm = w & 3, wn = w >> 2;
    int r0 = blockIdx.x * 128, c0 = blockIdx.y * NT;

    float acc[2][2*NB][4];
    #pragma unroll
    for (int i = 0; i < 2; ++i)
        #pragma unroll
        for (int j = 0; j < 2*NB; ++j)
            #pragma unroll
            for (int e = 0; e < 4; ++e) acc[i][j][e] = 0.f;

    int lrow = lane & 15;
    int lcolb = (lane >> 4) * 16;    // byte offset within k-chunk row

    for (int kc = 0; kc < K; kc += 64) {
        #pragma unroll 2
        for (int e = t; e < 1024; e += 256) {
            int row = e >> 3, vo = e & 7;
            uint32_t d = swz(row*128 + vo*16);
            *(uint4*)(sm + SM_AH + d) = *(const uint4*)(Ah + (size_t)(r0+row)*K + kc + vo*8);
            *(uint4*)(sm + SM_AL + d) = *(const uint4*)(Al + (size_t)(r0+row)*K + kc + vo*8);
        }
        #pragma unroll 2
        for (int e = t; e < NT*8; e += 256) {
            int row = e >> 3, vo = e & 7;
            uint32_t d = swz(row*128 + vo*16);
            *(uint4*)(sm + SM_BH + d) = *(const uint4*)(Bh + (size_t)(c0+row)*K + kc + vo*8);
            *(uint4*)(sm + SM_BL + d) = *(const uint4*)(Bl + (size_t)(c0+row)*K + kc + vo*8);
        }
        __syncthreads();
        #pragma unroll
        for (int s = 0; s < 4; ++s) {
            int kb = s*32 + lcolb;
            uint32_t ah[2][4], al[2][4];
            #pragma unroll
            for (int mb = 0; mb < 2; ++mb) {
                uint32_t off = swz((uint32_t)(wm*32 + mb*16 + lrow)*128 + kb);
                ldsm4(ah[mb], smb + SM_AH + off);
                ldsm4(al[mb], smb + SM_AL + off);
            }
            #pragma unroll
            for (int nb = 0; nb < NB; ++nb) {
                uint32_t bh[4], bl[4];
                uint32_t off = swz((uint32_t)(wn*WN + nb*16 + lrow)*128 + kb);
                ldsm4(bh, smb + SM_BH + off);
                ldsm4(bl, smb + SM_BL + off);
                #pragma unroll
                for (int mb = 0; mb < 2; ++mb) {
                    float* cA = acc[mb][nb*2];
                    float* cB = acc[mb][nb*2+1];
                    mma16816(cA, ah[mb], bh[0], bh[2]);
                    mma16816(cB, ah[mb], bh[1], bh[3]);
                    mma16816(cA, ah[mb], bl[0], bl[2]);
                    mma16816(cB, ah[mb], bl[1], bl[3]);
                    mma16816(cA, al[mb], bh[0], bh[2]);
                    mma16816(cB, al[mb], bh[1], bh[3]);
                }
            }
        }
        __syncthreads();
    }

    int rbase = r0 + wm*32 + (lane >> 2);
    int cb = c0 + wn*WN + (lane & 3)*2;
    #pragma unroll
    for (int mb = 0; mb < 2; ++mb) {
        #pragma unroll
        for (int nn = 0; nn < 2*NB; ++nn) {
            int col = cb + nn*8;
            float b0 = bias[col], b1 = bias[col+1];
            float v0 = acc[mb][nn][0] + b0, v1 = acc[mb][nn][1] + b1;
            float v2 = acc[mb][nn][2] + b0, v3 = acc[mb][nn][3] + b1;
            if (relu) {
                v0 = fmaxf(v0, 0.f); v1 = fmaxf(v1, 0.f);
                v2 = fmaxf(v2, 0.f); v3 = fmaxf(v3, 0.f);
            }
            size_t ra = (size_t)(rbase + mb*16) * ldc + col;
            size_t rb = (size_t)(rbase + mb*16 + 8) * ldc + col;
            if (Cf) {
                *(float2*)(Cf + ra) = make_float2(v0, v1);
                *(float2*)(Cf + rb) = make_float2(v2, v3);
            }
            if (Ch) {
                float h0 = rndbf(v0), h1 = rndbf(v1), h2 = rndbf(v2), h3 = rndbf(v3);
                *(unsigned*)(Ch + ra) = pk2(v0, v1);
                *(unsigned*)(Cl + ra) = pk2(v0-h0, v1-h1);
                *(unsigned*)(Ch + rb) = pk2(v2, v3);
                *(unsigned*)(Cl + rb) = pk2(v2-h2, v3-h3);
            }
        }
    }
}

// ---------------- h1 = relu(relpos @ Wp1 + bp1) -> bf16 hi/lo ----------------
__global__ void __launch_bounds__(256) k_h1(const float* __restrict__ xyz,
                                            const float* __restrict__ Wp1,
                                            const float* __restrict__ bp1) {
    __shared__ float w0[64], w1[64], w2[64], bb[64];
    int t = threadIdx.x;
    if (t < 64) { w0[t] = Wp1[t]; w1[t] = Wp1[64+t]; w2[t] = Wp1[128+t]; bb[t] = bp1[t]; }
    __syncthreads();
    int r  = blockIdx.x * 32 + (t >> 3);
    int c0 = (t & 7) * 8;
    int b  = r >> 17;
    int n  = (r >> 4) & (NPTS - 1);
    int idx = g_knn[r];
    const float* xb = xyz + (size_t)b * NPTS * 3;
    float rx = xb[idx*3+0] - xb[n*3+0];
    float ry = xb[idx*3+1] - xb[n*3+1];
    float rz = xb[idx*3+2] - xb[n*3+2];
    float o[8];
    #pragma unroll
    for (int c = 0; c < 8; ++c) {
        float h = fmaf(rx, w0[c0+c], fmaf(ry, w1[c0+c], fmaf(rz, w2[c0+c], bb[c0+c])));
        o[c] = fmaxf(h, 0.f);
    }
    uint4 hv, lv;
    float h0 = rndbf(o[0]), h1v = rndbf(o[1]), h2 = rndbf(o[2]), h3 = rndbf(o[3]);
    float h4 = rndbf(o[4]), h5 = rndbf(o[5]), h6 = rndbf(o[6]), h7 = rndbf(o[7]);
    hv.x = pk2(o[0], o[1]); hv.y = pk2(o[2], o[3]); hv.z = pk2(o[4], o[5]); hv.w = pk2(o[6], o[7]);
    lv.x = pk2(o[0]-h0, o[1]-h1v); lv.y = pk2(o[2]-h2, o[3]-h3);
    lv.z = pk2(o[4]-h4, o[5]-h5);  lv.w = pk2(o[6]-h6, o[7]-h7);
    *(uint4*)(g_h1_h + (size_t)r * HD + c0) = hv;
    *(uint4*)(g_h1_l + (size_t)r * HD + c0) = lv;
}

// ---------------- fused attention ----------------
__global__ void __launch_bounds__(128) k_attn(float* __restrict__ attn_out) {
    __shared__ int   idx_s[16];
    __shared__ float pos_s[16][68];
    __shared__ float k_s[16][260];
    __shared__ float v_s[16][260];
    __shared__ float q_s[256];
    __shared__ float logit_s[64];
    __shared__ float attn_s[64];
    int t  = threadIdx.x;
    int gp = blockIdx.x;
    int b  = gp >> 13, n = gp & (NPTS-1);

    if (t < 16) idx_s[t] = g_knn[gp*KNBR + t];
    if (t < 64) ((float4*)q_s)[t] = ((const float4*)(g_qkv + (size_t)gp * 768))[t];
    {
        const float4* ps = (const float4*)(g_pos + (size_t)gp * KNBR * HD);
        #pragma unroll
        for (int e = t; e < 256; e += 128) {
            int jj = e >> 4, cc = e & 15;
            *(float4*)&pos_s[jj][cc*4] = ps[e];
        }
    }
    __syncthreads();
    #pragma unroll
    for (int e = t; e < 1024; e += 128) {
        int jj = e >> 6, cc = e & 63;
        size_t rowb = ((size_t)b * NPTS + idx_s[jj]) * 768;
        *(float4*)&k_s[jj][cc*4] = *(const float4*)(g_qkv + rowb + 256 + cc*4);
        *(float4*)&v_s[jj][cc*4] = *(const float4*)(g_qkv + rowb + 512 + cc*4);
    }
    __syncthreads();
    {
        int p = t >> 1, half = t & 1;
        int jj = p & 15, h = p >> 4;
        float s = 0.f;
        int cbs = half * 32;
        #pragma unroll
        for (int c = 0; c < 32; ++c) {
            int cc = cbs + c;
            s = fmaf(q_s[h*64+cc], k_s[jj][h*64+cc] + pos_s[jj][cc], s);
        }
        s += __shfl_xor_sync(~0u, s, 1);
        if (half == 0) logit_s[h*16 + jj] = s * 0.125f;
    }
    __syncthreads();
    if (t < 4) {
        int h = t;
        float l[16], mx = -3.402823e38f;
        #pragma unroll
        for (int j = 0; j < 16; ++j) { l[j] = logit_s[h*16+j]; mx = fmaxf(mx, l[j]); }
        float sum = 0.f;
        #pragma unroll
        for (int j = 0; j < 16; ++j) { l[j] = expf(l[j] - mx); sum += l[j]; }
        float inv = 1.f / sum;
        size_t ob = (((size_t)b*NH + h) * NPTS + n) * KNBR;
        #pragma unroll
        for (int j = 0; j < 16; ++j) {
            float a = l[j] * inv;
            attn_s[h*16+j] = a;
            attn_out[ob + j] = a;
        }
    }
    __syncthreads();
    #pragma unroll
    for (int e = t; e < 256; e += 128) {
        int h = e >> 6, c = e & 63;
        float s = 0.f;
        #pragma unroll
        for (int j = 0; j < 16; ++j)
            s = fmaf(attn_s[h*16+j], v_s[j][e] + pos_s[j][c], s);
        float hs = rndbf(s);
        g_mid_h[(size_t)gp * DOUT + e] = __float2bfloat16_rn(s);
        g_mid_l[(size_t)gp * DOUT + e] = __float2bfloat16_rn(s - hs);
    }
}

// ---------------- final: LN(fc2)*g2+b2 + lnq -> out ----------------
__global__ void k_final(const float* __restrict__ g2, const float* __restrict__ b2,
                        float* __restrict__ out) {
    int warp = (blockIdx.x * blockDim.x + threadIdx.x) >> 5;
    int lane = threadIdx.x & 31;
    const float4* row = (const float4*)(g_fc2 + (size_t)warp * DOUT);
    float4 v0 = row[lane*2], v1 = row[lane*2+1];
    float s = v0.x+v0.y+v0.z+v0.w + v1.x+v1.y+v1.z+v1.w;
    #pragma unroll
    for (int o = 16; o; o >>= 1) s += __shfl_xor_sync(~0u, s, o);
    float mu = s * (1.f/256.f);
    float d0x=v0.x-mu, d0y=v0.y-mu, d0z=v0.z-mu, d0w=v0.w-mu;
    float d1x=v1.x-mu, d1y=v1.y-mu, d1z=v1.z-mu, d1w=v1.w-mu;
    float s2 = d0x*d0x+d0y*d0y+d0z*d0z+d0w*d0w + d1x*d1x+d1y*d1y+d1z*d1z+d1w*d1w;
    #pragma unroll
    for (int o = 16; o; o >>= 1) s2 += __shfl_xor_sync(~0u, s2, o);
    float rs = rsqrtf(s2 * (1.f/256.f) + 1e-5f);
    float4 gA = ((const float4*)g2)[lane*2],  gB = ((const float4*)g2)[lane*2+1];
    float4 bA = ((const float4*)b2)[lane*2],  bB = ((const float4*)b2)[lane*2+1];
    const float4* lq = (const float4*)(g_lnq + (size_t)warp * DOUT);
    float4 qA = lq[lane*2], qB = lq[lane*2+1];
    float4 oA, oB;
    oA.x = d0x*rs*gA.x + bA.x + qA.x; oA.y = d0y*rs*gA.y + bA.y + qA.y;
    oA.z = d0z*rs*gA.z + bA.z + qA.z; oA.w = d0w*rs*gA.w + bA.w + qA.w;
    oB.x = d1x*rs*gB.x + bB.x + qB.x; oB.y = d1y*rs*gB.y + bB.y + qB.y;
    oB.z = d1z*rs*gB.z + bB.z + qB.z; oB.w = d1w*rs*gB.w + bB.w + qB.w;
    float4* dst = (float4*)(out + (size_t)warp * DOUT);
    dst[lane*2]   = oA;
    dst[lane*2+1] = oB;
}

// ---------------- host launcher ----------------
extern "C" void kernel_launch(void* const* d_in, const int* in_sizes, int n_in,
                              void* d_out, int out_size) {
    const float* xyz      = (const float*)d_in[0];
    const float* features = (const float*)d_in[1];
    const float* Wq  = (const float*)d_in[2];
    const float* bq  = (const float*)d_in[3];
    const float* Wk  = (const float*)d_in[4];
    const float* bk  = (const float*)d_in[5];
    const float* Wv  = (const float*)d_in[6];
    const float* bv  = (const float*)d_in[7];
    const float* Wp1 = (const float*)d_in[8];
    const float* bp1 = (const float*)d_in[9];
    const float* Wp2 = (const float*)d_in[10];
    const float* bp2 = (const float*)d_in[11];
    const float* Wf1 = (const float*)d_in[12];
    const float* bf1 = (const float*)d_in[13];
    const float* Wf2 = (const float*)d_in[14];
    const float* bf2 = (const float*)d_in[15];
    const float* g1  = (const float*)d_in[16];
    const float* b1  = (const float*)d_in[17];
    const float* g2  = (const float*)d_in[18];
    const float* b2  = (const float*)d_in[19];

    float* out      = (float*)d_out;
    float* attn_out = out + (size_t)ROWS * DOUT;

    #define SYM(p, s) float* p; cudaGetSymbolAddress((void**)&p, s)
    #define SYMB(p, s) __nv_bfloat16* p; cudaGetSymbolAddress((void**)&p, s)
    SYMB(p_feat_h, g_feat_h); SYMB(p_feat_l, g_feat_l);
    SYMB(p_lnf_h,  g_lnf_h);  SYMB(p_lnf_l,  g_lnf_l);
    SYM(p_qkv, g_qkv); SYM(p_lnq, g_lnq); SYM(p_pos, g_pos); SYM(p_fc2, g_fc2);
    SYMB(p_h1_h, g_h1_h); SYMB(p_h1_l, g_h1_l);
    SYMB(p_mid_h, g_mid_h); SYMB(p_mid_l, g_mid_l);
    SYMB(p_fc1_h, g_fc1_h); SYMB(p_fc1_l, g_fc1_l);
    SYMB(p_wqkvT_h, g_wqkvT_h); SYMB(p_wqkvT_l, g_wqkvT_l);
    SYMB(p_wp2T_h, g_wp2T_h);   SYMB(p_wp2T_l, g_wp2T_l);
    SYMB(p_wf1T_h, g_wf1T_h);   SYMB(p_wf1T_l, g_wf1T_l);
    SYMB(p_wf2T_h, g_wf2T_h);   SYMB(p_wf2T_l, g_wf2T_l);
    SYM(p_bqkv, g_bqkv);

    static bool attr_done = false;
    if (!attr_done) {
        cudaFuncSetAttribute(k_mgemm<128>, cudaFuncAttributeMaxDynamicSharedMemorySize, SMEM_MG);
        cudaFuncSetAttribute(k_mgemm<64>,  cudaFuncAttributeMaxDynamicSharedMemorySize, SMEM_MG);
        attr_done = true;
    }

    k_pack<<<ROWS/256, 256>>>(xyz);
    {
        dim3 kg(NPTS/64, BATCH);
        k_knn<<<kg, 256>>>();
    }
    k_cvt_split<<<(ROWS*DIM/4)/256, 256>>>(features, p_feat_h, p_feat_l, ROWS*DIM/4);
    k_ln1<<<ROWS/8, 256>>>(features, g1, b1);

    k_cvt_wT<<<(DIM*DOUT+255)/256, 256>>>(Wq, p_wqkvT_h,           p_wqkvT_l,           DIM, DOUT);
    k_cvt_wT<<<(DIM*DOUT+255)/256, 256>>>(Wk, p_wqkvT_h + 256*DIM, p_wqkvT_l + 256*DIM, DIM, DOUT);
    k_cvt_wT<<<(DIM*DOUT+255)/256, 256>>>(Wv, p_wqkvT_h + 512*DIM, p_wqkvT_l + 512*DIM, DIM, DOUT);
    k_cvt_wT<<<(HD*HD+255)/256,    256>>>(Wp2, p_wp2T_h, p_wp2T_l, HD, HD);
    k_cvt_wT<<<(DOUT*DOUT+255)/256,256>>>(Wf1, p_wf1T_h, p_wf1T_l, DOUT, DOUT);
    k_cvt_wT<<<(DOUT*DOUT+255)/256,256>>>(Wf2, p_wf2T_h, p_wf2T_l, DOUT, DOUT);
    k_bpack<<<3, 256>>>(bq, bk, bv);

    // qkv: [32768,128] @ [768,128]^T
    {
        dim3 g(ROWS/128, 6);
        k_mgemm<128><<<g, 256, SMEM_MG>>>(p_feat_h, p_feat_l, p_wqkvT_h, p_wqkvT_l,
                                          p_bqkv, p_qkv, nullptr, nullptr, DIM, 768, 0);
    }
    // lnq: LN(features) @ Wq
    {
        dim3 g(ROWS/128, 2);
        k_mgemm<128><<<g, 256, SMEM_MG>>>(p_lnf_h, p_lnf_l, p_wqkvT_h, p_wqkvT_l,
                                          bq, p_lnq, nullptr, nullptr, DIM, DOUT, 0);
    }

    k_h1<<<NROWS/32, 256>>>(xyz, Wp1, bp1);
    // pos: [524288,64] @ [64,64]^T
    {
        dim3 g(NROWS/128, 1);
        k_mgemm<64><<<g, 256, SMEM_MG>>>(p_h1_h, p_h1_l, p_wp2T_h, p_wp2T_l,
                                         bp2, p_pos, nullptr, nullptr, HD, HD, 0);
    }

    k_attn<<<ROWS, 128>>>(attn_out);

    // fc1 (relu, bf16-pair out), fc2 (fp32 out)
    {
        dim3 g(ROWS/128, 2);
        k_mgemm<128><<<g, 256, SMEM_MG>>>(p_mid_h, p_mid_l, p_wf1T_h, p_wf1T_l,
                                          bf1, nullptr, p_fc1_h, p_fc1_l, DOUT, DOUT, 1);
        k_mgemm<128><<<g, 256, SMEM_MG>>>(p_fc1_h, p_fc1_l, p_wf2T_h, p_wf2T_l,
                                          bf2, p_fc2, nullptr, nullptr, DOUT, DOUT, 0);
    }

    k_final<<<ROWS/8, 256>>>(g2, b2, out);
}

// round 4
// speedup vs baseline: 1.6804x; 1.6539x over previous
#include <cuda_runtime.h>
#include <cuda_bf16.h>
#include <cstdint>
#include <math.h>

#define BATCH 4
#define NPTS  8192
#define DIM   128
#define DOUT  256
#define NH    4
#define HD    64
#define KNBR  16
#define ROWS  (BATCH*NPTS)          // 32768
#define NROWS (BATCH*NPTS*KNBR)     // 524288

// ---------------- scratch (device globals; no runtime alloc) ----------------
__device__ float4 g_xyzw[ROWS];
__device__ int    g_knn[NROWS];
__device__ __nv_bfloat16 g_feat_h[ROWS*DIM];
__device__ __nv_bfloat16 g_feat_l[ROWS*DIM];
__device__ __nv_bfloat16 g_lnf_h[ROWS*DIM];
__device__ __nv_bfloat16 g_lnf_l[ROWS*DIM];
__device__ float  g_qkv[(size_t)ROWS*768];     // [q|k|v] per row
__device__ float  g_lnq[ROWS*DOUT];
__device__ float  g_pos[(size_t)NROWS*HD];
__device__ __nv_bfloat16 g_mid_h[ROWS*DOUT];
__device__ __nv_bfloat16 g_mid_l[ROWS*DOUT];
__device__ __nv_bfloat16 g_fc1_h[ROWS*DOUT];
__device__ __nv_bfloat16 g_fc1_l[ROWS*DOUT];
__device__ float  g_fc2[ROWS*DOUT];
// transposed bf16-split weights
__device__ __nv_bfloat16 g_wqkvT_h[768*DIM];
__device__ __nv_bfloat16 g_wqkvT_l[768*DIM];
__device__ __nv_bfloat16 g_wp2T_h[HD*HD];
__device__ __nv_bfloat16 g_wp2T_l[HD*HD];
__device__ __nv_bfloat16 g_wf1T_h[DOUT*DOUT];
__device__ __nv_bfloat16 g_wf1T_l[DOUT*DOUT];
__device__ __nv_bfloat16 g_wf2T_h[DOUT*DOUT];
__device__ __nv_bfloat16 g_wf2T_l[DOUT*DOUT];
__device__ float g_bqkv[768];

// ---------------- small helpers ----------------
__device__ __forceinline__ unsigned pk2(float a, float b) {
    __nv_bfloat162 t = __floats2bfloat162_rn(a, b);
    return *(unsigned*)&t;
}
__device__ __forceinline__ float rndbf(float x) {
    return __bfloat162float(__float2bfloat16_rn(x));
}
__device__ __forceinline__ uint32_t smem_u32(const void* p) {
    uint32_t a;
    asm("{ .reg .u64 t; cvta.to.shared.u64 t, %1; cvt.u32.u64 %0, t; }" : "=r"(a) : "l"(p));
    return a;
}
__device__ __forceinline__ uint32_t swz(uint32_t x) { return x ^ ((x >> 3) & 0x70); }

__device__ __forceinline__ void ldsm4(uint32_t* r, uint32_t addr) {
    asm volatile("ldmatrix.sync.aligned.m8n8.x4.shared.b16 {%0,%1,%2,%3}, [%4];"
        : "=r"(r[0]), "=r"(r[1]), "=r"(r[2]), "=r"(r[3]) : "r"(addr));
}
__device__ __forceinline__ void mma16816(float* c, const uint32_t* a, uint32_t b0, uint32_t b1) {
    asm volatile("mma.sync.aligned.m16n8k16.row.col.f32.bf16.bf16.f32 "
        "{%0,%1,%2,%3}, {%4,%5,%6,%7}, {%8,%9}, {%0,%1,%2,%3};"
        : "+f"(c[0]), "+f"(c[1]), "+f"(c[2]), "+f"(c[3])
        : "r"(a[0]), "r"(a[1]), "r"(a[2]), "r"(a[3]), "r"(b0), "r"(b1));
}

// ---------------- pack xyz + squared norm ----------------
__global__ void k_pack(const float* __restrict__ xyz) {
    int i = blockIdx.x * 256 + threadIdx.x;
    if (i >= ROWS) return;
    float x = xyz[i*3+0], y = xyz[i*3+1], z = xyz[i*3+2];
    g_xyzw[i] = make_float4(x, y, z, x*x + y*y + z*z);
}

// ---------------- KNN: warp/query, sample-threshold + collect + 16x argmin ----------------
// smem: tile 2048*float4 (32KB) + 16 warps * 384 * (key+idx) (48KB) = 80KB
#define KNN_CAP 384
#define SMEM_KNN (32768 + 16*KNN_CAP*8)

__global__ void __launch_bounds__(512) k_knn2() {
    extern __shared__ char sk[];
    float4* tile = (float4*)sk;
    float*  bkey = (float*)(sk + 32768);
    int*    bidx = (int*)(sk + 32768 + 16*KNN_CAP*4);
    int t = threadIdx.x, lane = t & 31, w = t >> 5;
    int b = blockIdx.y;
    int q = blockIdx.x * 16 + w;
    const float INF = 3.402823e38f;

    float4 me = g_xyzw[b*NPTS + q];
    float qx2 = -2.f*me.x, qy2 = -2.f*me.y, qz2 = -2.f*me.z;

    float T = 0.f;
    int base = 0;
    float* mk = bkey + w*KNN_CAP;
    int*   mi = bidx + w*KNN_CAP;

    for (int ti = 0; ti < 4; ++ti) {
        __syncthreads();
        for (int i = t; i < 2048; i += 512)
            tile[i] = g_xyzw[b*NPTS + ti*2048 + i];
        __syncthreads();

        if (ti == 0) {
            // Phase A: lane-min over 64 strided samples (j = i*32+lane)
            float mn = INF;
            #pragma unroll 8
            for (int i = 0; i < 64; ++i) {
                float4 p = tile[i*32 + lane];
                float d = fmaf(qx2,p.x,fmaf(qy2,p.y,fmaf(qz2,p.z,p.w)));
                mn = fminf(mn, d);
            }
            // warp bitonic sort ascending across lanes
            float v = mn;
            #pragma unroll
            for (int k = 2; k <= 32; k <<= 1) {
                #pragma unroll
                for (int j = k >> 1; j > 0; j >>= 1) {
                    float o = __shfl_xor_sync(~0u, v, j);
                    bool up = ((lane & k) == 0);
                    bool lower = ((lane & j) == 0);
                    v = (lower == up) ? fminf(v, o) : fmaxf(v, o);
                }
            }
            T = __shfl_sync(~0u, v, 15);   // rank-16 of lane-mins >= true 16th dist
        }

        // Phase B: collect d <= T
        #pragma unroll 4
        for (int c = 0; c < 64; ++c) {
            int j = c*32 + lane;
            float4 p = tile[j];
            float d = fmaf(qx2,p.x,fmaf(qy2,p.y,fmaf(qz2,p.z,p.w)));
            bool pass = (d <= T);
            unsigned m = __ballot_sync(~0u, pass);
            if (pass) {
                int pos = base + __popc(m & ((1u << lane) - 1u));
                if (pos < KNN_CAP) { mk[pos] = d; mi[pos] = ti*2048 + j; }
            }
            base += __popc(m);
        }
    }
    if (base > KNN_CAP) base = KNN_CAP;
    __syncwarp();

    // Phase C: 16 argmin rounds, lexicographic (d, idx)
    size_t ob = ((size_t)b*NPTS + q) * KNBR;
    for (int r = 0; r < KNBR; ++r) {
        float bk = INF; int bi = 0x7fffffff; int bp = -1;
        for (int i = lane; i < base; i += 32) {
            float kk = mk[i];
            int   ii = mi[i];
            if (kk < bk || (kk == bk && ii < bi)) { bk = kk; bi = ii; bp = i; }
        }
        #pragma unroll
        for (int o = 16; o; o >>= 1) {
            float ok = __shfl_xor_sync(~0u, bk, o);
            int   oi = __shfl_xor_sync(~0u, bi, o);
            int   op = __shfl_xor_sync(~0u, bp, o);
            if (ok < bk || (ok == bk && oi < bi)) { bk = ok; bi = oi; bp = op; }
        }
        if (lane == 0) {
            g_knn[ob + r] = bi;
            if (bp >= 0) mk[bp] = INF;
        }
        __syncwarp();
    }
}

// ---------------- split fp32 -> bf16 hi/lo ----------------
__global__ void k_cvt_split(const float* __restrict__ x, __nv_bfloat16* __restrict__ h,
                            __nv_bfloat16* __restrict__ l, int n4) {
    int i = blockIdx.x * 256 + threadIdx.x;
    if (i >= n4) return;
    float4 v = ((const float4*)x)[i];
    float hx = rndbf(v.x), hy = rndbf(v.y), hz = rndbf(v.z), hw = rndbf(v.w);
    uint2 hh = { pk2(v.x, v.y), pk2(v.z, v.w) };
    uint2 ll = { pk2(v.x - hx, v.y - hy), pk2(v.z - hz, v.w - hw) };
    ((uint2*)h)[i] = hh;
    ((uint2*)l)[i] = ll;
}

// ---------------- transpose + split weight: W[K,N] -> T[N,K] bf16 hi/lo ----------------
__global__ void k_cvt_wT(const float* __restrict__ W, __nv_bfloat16* __restrict__ Th,
                         __nv_bfloat16* __restrict__ Tl, int Kd, int Nd) {
    int i = blockIdx.x * 256 + threadIdx.x;
    if (i >= Kd * Nd) return;
    int n = i / Kd, k = i % Kd;
    float x = W[(size_t)k * Nd + n];
    float hx = rndbf(x);
    Th[i] = __float2bfloat16_rn(x);
    Tl[i] = __float2bfloat16_rn(x - hx);
}

__global__ void k_bpack(const float* __restrict__ a, const float* __restrict__ b,
                        const float* __restrict__ c) {
    int t = threadIdx.x + blockIdx.x * 256;
    if (t < 256)      g_bqkv[t] = a[t];
    else if (t < 512) g_bqkv[t] = b[t-256];
    else if (t < 768) g_bqkv[t] = c[t-512];
}

// ---------------- LayerNorm dim=128 -> bf16 hi/lo ----------------
__global__ void k_ln1(const float* __restrict__ x, const float* __restrict__ g,
                      const float* __restrict__ bta) {
    int warp = (blockIdx.x * blockDim.x + threadIdx.x) >> 5;
    int lane = threadIdx.x & 31;
    const float4* row = (const float4*)(x + (size_t)warp * DIM);
    float4 v = row[lane];
    float s = v.x + v.y + v.z + v.w;
    #pragma unroll
    for (int o = 16; o; o >>= 1) s += __shfl_xor_sync(~0u, s, o);
    float mu = s * (1.f/128.f);
    float dx = v.x-mu, dy = v.y-mu, dz = v.z-mu, dw = v.w-mu;
    float s2 = dx*dx + dy*dy + dz*dz + dw*dw;
    #pragma unroll
    for (int o = 16; o; o >>= 1) s2 += __shfl_xor_sync(~0u, s2, o);
    float rs = rsqrtf(s2 * (1.f/128.f) + 1e-5f);
    float4 gg = ((const float4*)g)[lane];
    float4 bb = ((const float4*)bta)[lane];
    float rx = dx*rs*gg.x + bb.x, ry = dy*rs*gg.y + bb.y;
    float rz = dz*rs*gg.z + bb.z, rw = dw*rs*gg.w + bb.w;
    float hx = rndbf(rx), hy = rndbf(ry), hz = rndbf(rz), hw = rndbf(rw);
    int idx = warp*32 + lane;
    ((uint2*)g_lnf_h)[idx] = make_uint2(pk2(rx, ry), pk2(rz, rw));
    ((uint2*)g_lnf_l)[idx] = make_uint2(pk2(rx-hx, ry-hy), pk2(rz-hz, rw-hw));
}

// ---------------- mma.sync GEMM (bf16 split x3), C = act(A@B^T + bias) ----------------
#define SM_AH 0
#define SM_AL 16384
#define SM_BH 32768
#define SM_BL 49152
#define SMEM_MG 65536

template<int NT>
__global__ void __launch_bounds__(256) k_mgemm(
    const __nv_bfloat16* __restrict__ Ah, const __nv_bfloat16* __restrict__ Al,
    const __nv_bfloat16* __restrict__ Bh, const __nv_bfloat16* __restrict__ Bl,
    const float* __restrict__ bias,
    float* __restrict__ Cf, __nv_bfloat16* __restrict__ Ch, __nv_bfloat16* __restrict__ Cl,
    int K, int ldc, int relu)
{
    constexpr int WN = NT / 2;
    constexpr int NB = WN / 16;
    extern __shared__ char sm[];
    uint32_t smb = smem_u32(sm);
    int t = threadIdx.x, lane = t & 31, w = t >> 5;
    int wm = w & 3, wn = w >> 2;
    int r0 = blockIdx.x * 128, c0 = blockIdx.y * NT;

    float acc[2][2*NB][4];
    #pragma unroll
    for (int i = 0; i < 2; ++i)
        #pragma unroll
        for (int j = 0; j < 2*NB; ++j)
            #pragma unroll
            for (int e = 0; e < 4; ++e) acc[i][j][e] = 0.f;

    int lrow = lane & 15;
    int lcolb = (lane >> 4) * 16;

    for (int kc = 0; kc < K; kc += 64) {
        #pragma unroll 2
        for (int e = t; e < 1024; e += 256) {
            int row = e >> 3, vo = e & 7;
            uint32_t d = swz(row*128 + vo*16);
            *(uint4*)(sm + SM_AH + d) = *(const uint4*)(Ah + (size_t)(r0+row)*K + kc + vo*8);
            *(uint4*)(sm + SM_AL + d) = *(const uint4*)(Al + (size_t)(r0+row)*K + kc + vo*8);
        }
        #pragma unroll 2
        for (int e = t; e < NT*8; e += 256) {
            int row = e >> 3, vo = e & 7;
            uint32_t d = swz(row*128 + vo*16);
            *(uint4*)(sm + SM_BH + d) = *(const uint4*)(Bh + (size_t)(c0+row)*K + kc + vo*8);
            *(uint4*)(sm + SM_BL + d) = *(const uint4*)(Bl + (size_t)(c0+row)*K + kc + vo*8);
        }
        __syncthreads();
        #pragma unroll
        for (int s = 0; s < 4; ++s) {
            int kb = s*32 + lcolb;
            uint32_t ah[2][4], al[2][4];
            #pragma unroll
            for (int mb = 0; mb < 2; ++mb) {
                uint32_t off = swz((uint32_t)(wm*32 + mb*16 + lrow)*128 + kb);
                ldsm4(ah[mb], smb + SM_AH + off);
                ldsm4(al[mb], smb + SM_AL + off);
            }
            #pragma unroll
            for (int nb = 0; nb < NB; ++nb) {
                uint32_t bh[4], bl[4];
                uint32_t off = swz((uint32_t)(wn*WN + nb*16 + lrow)*128 + kb);
                ldsm4(bh, smb + SM_BH + off);
                ldsm4(bl, smb + SM_BL + off);
                #pragma unroll
                for (int mb = 0; mb < 2; ++mb) {
                    float* cA = acc[mb][nb*2];
                    float* cB = acc[mb][nb*2+1];
                    mma16816(cA, ah[mb], bh[0], bh[2]);
                    mma16816(cB, ah[mb], bh[1], bh[3]);
                    mma16816(cA, ah[mb], bl[0], bl[2]);
                    mma16816(cB, ah[mb], bl[1], bl[3]);
                    mma16816(cA, al[mb], bh[0], bh[2]);
                    mma16816(cB, al[mb], bh[1], bh[3]);
                }
            }
        }
        __syncthreads();
    }

    int rbase = r0 + wm*32 + (lane >> 2);
    int cb = c0 + wn*WN + (lane & 3)*2;
    #pragma unroll
    for (int mb = 0; mb < 2; ++mb) {
        #pragma unroll
        for (int nn = 0; nn < 2*NB; ++nn) {
            int col = cb + nn*8;
            float b0 = bias[col], b1 = bias[col+1];
            float v0 = acc[mb][nn][0] + b0, v1 = acc[mb][nn][1] + b1;
            float v2 = acc[mb][nn][2] + b0, v3 = acc[mb][nn][3] + b1;
            if (relu) {
                v0 = fmaxf(v0, 0.f); v1 = fmaxf(v1, 0.f);
                v2 = fmaxf(v2, 0.f); v3 = fmaxf(v3, 0.f);
            }
            size_t ra = (size_t)(rbase + mb*16) * ldc + col;
            size_t rb = (size_t)(rbase + mb*16 + 8) * ldc + col;
            if (Cf) {
                *(float2*)(Cf + ra) = make_float2(v0, v1);
                *(float2*)(Cf + rb) = make_float2(v2, v3);
            }
            if (Ch) {
                float h0 = rndbf(v0), h1 = rndbf(v1), h2 = rndbf(v2), h3 = rndbf(v3);
                *(unsigned*)(Ch + ra) = pk2(v0, v1);
                *(unsigned*)(Cl + ra) = pk2(v0-h0, v1-h1);
                *(unsigned*)(Ch + rb) = pk2(v2, v3);
                *(unsigned*)(Cl + rb) = pk2(v2-h2, v3-h3);
            }
        }
    }
}

// ---------------- fused pos GEMM: A = relu(relpos@Wp1+bp1) computed in-kernel ----------------
// tile: 128 rows x 64 cols, K = 64 (single chunk)
#define PG_AH 0
#define PG_AL 16384
#define PG_BH 32768
#define PG_BL 40960
#define SMEM_PG 49152

__global__ void __launch_bounds__(256) k_pgemm(
    const float* __restrict__ xyz, const float* __restrict__ Wp1,
    const float* __restrict__ bp1, const float* __restrict__ bias)
{
    extern __shared__ char sm[];
    uint32_t smb = smem_u32(sm);
    int t = threadIdx.x, lane = t & 31, w = t >> 5;
    int wm = w & 3, wn = w >> 2;
    int r0 = blockIdx.x * 128;

    // load Wp2T splits (64 rows x 128B)
    #pragma unroll 2
    for (int e = t; e < 512; e += 256) {
        int row = e >> 3, vo = e & 7;
        uint32_t d = swz(row*128 + vo*16);
        *(uint4*)(sm + PG_BH + d) = *(const uint4*)(g_wp2T_h + row*64 + vo*8);
        *(uint4*)(sm + PG_BL + d) = *(const uint4*)(g_wp2T_l + row*64 + vo*8);
    }

    // compute A rows: 2 threads/row, 32 cols each
    {
        int row = t >> 1, ch = t & 1;
        int rr = r0 + row;
        int b = rr >> 17, n = (rr >> 4) & (NPTS - 1);
        int idx = g_knn[rr];
        const float* xb = xyz + (size_t)b * NPTS * 3;
        float rx = xb[idx*3+0] - xb[n*3+0];
        float ry = xb[idx*3+1] - xb[n*3+1];
        float rz = xb[idx*3+2] - xb[n*3+2];
        uint32_t hp[16], lp[16];
        #pragma unroll
        for (int cc = 0; cc < 32; cc += 2) {
            int c = ch*32 + cc;
            float v0 = fmaf(rx, Wp1[c],   fmaf(ry, Wp1[64+c],   fmaf(rz, Wp1[128+c],   bp1[c])));
            float v1 = fmaf(rx, Wp1[c+1], fmaf(ry, Wp1[64+c+1], fmaf(rz, Wp1[128+c+1], bp1[c+1])));
            v0 = fmaxf(v0, 0.f); v1 = fmaxf(v1, 0.f);
            float h0 = rndbf(v0), h1 = rndbf(v1);
            hp[cc>>1] = pk2(v0, v1);
            lp[cc>>1] = pk2(v0-h0, v1-h1);
        }
        uint32_t rbyte = (uint32_t)row*128 + ch*64;
        #pragma unroll
        for (int i = 0; i < 4; ++i) {
            uint32_t d = swz(rbyte + i*16);
            *(uint4*)(sm + PG_AH + d) = *(uint4*)&hp[i*4];
            *(uint4*)(sm + PG_AL + d) = *(uint4*)&lp[i*4];
        }
    }
    __syncthreads();

    // mma: NT=64 path (WN=32, NB=2), K=64 single chunk
    float acc[2][4][4];
    #pragma unroll
    for (int i = 0; i < 2; ++i)
        #pragma unroll
        for (int j = 0; j < 4; ++j)
            #pragma unroll
            for (int e = 0; e < 4; ++e) acc[i][j][e] = 0.f;
    int lrow = lane & 15, lcolb = (lane >> 4) * 16;
    #pragma unroll
    for (int s = 0; s < 4; ++s) {
        int kb = s*32 + lcolb;
        uint32_t ah[2][4], al[2][4];
        #pragma unroll
        for (int mb = 0; mb < 2; ++mb) {
            uint32_t off = swz((uint32_t)(wm*32 + mb*16 + lrow)*128 + kb);
            ldsm4(ah[mb], smb + PG_AH + off);
            ldsm4(al[mb], smb + PG_AL + off);
        }
        #pragma unroll
        for (int nb = 0; nb < 2; ++nb) {
            uint32_t bh[4], bl[4];
            uint32_t off = swz((uint32_t)(wn*32 + nb*16 + lrow)*128 + kb);
            ldsm4(bh, smb + PG_BH + off);
            ldsm4(bl, smb + PG_BL + off);
            #pragma unroll
            for (int mb = 0; mb < 2; ++mb) {
                float* cA = acc[mb][nb*2];
                float* cB = acc[mb][nb*2+1];
                mma16816(cA, ah[mb], bh[0], bh[2]);
                mma16816(cB, ah[mb], bh[1], bh[3]);
                mma16816(cA, ah[mb], bl[0], bl[2]);
                mma16816(cB, ah[mb], bl[1], bl[3]);
                mma16816(cA, al[mb], bh[0], bh[2]);
                mma16816(cB, al[mb], bh[1], bh[3]);
            }
        }
    }

    int rbase = r0 + wm*32 + (lane >> 2);
    int cb = wn*32 + (lane & 3)*2;
    #pragma unroll
    for (int mb = 0; mb < 2; ++mb) {
        #pragma unroll
        for (int nn = 0; nn < 4; ++nn) {
            int col = cb + nn*8;
            float b0 = bias[col], b1 = bias[col+1];
            size_t ra = (size_t)(rbase + mb*16) * HD + col;
            size_t rb = (size_t)(rbase + mb*16 + 8) * HD + col;
            *(float2*)(g_pos + ra) = make_float2(acc[mb][nn][0] + b0, acc[mb][nn][1] + b1);
            *(float2*)(g_pos + rb) = make_float2(acc[mb][nn][2] + b0, acc[mb][nn][3] + b1);
        }
    }
}

// ---------------- fused attention ----------------
__global__ void __launch_bounds__(128) k_attn(float* __restrict__ attn_out) {
    __shared__ int   idx_s[16];
    __shared__ float pos_s[16][68];
    __shared__ float k_s[16][260];
    __shared__ float v_s[16][260];
    __shared__ float q_s[256];
    __shared__ float logit_s[64];
    __shared__ float attn_s[64];
    int t  = threadIdx.x;
    int gp = blockIdx.x;
    int b  = gp >> 13, n = gp & (NPTS-1);

    if (t < 16) idx_s[t] = g_knn[gp*KNBR + t];
    if (t < 64) ((float4*)q_s)[t] = ((const float4*)(g_qkv + (size_t)gp * 768))[t];
    {
        const float4* ps = (const float4*)(g_pos + (size_t)gp * KNBR * HD);
        #pragma unroll
        for (int e = t; e < 256; e += 128) {
            int jj = e >> 4, cc = e & 15;
            *(float4*)&pos_s[jj][cc*4] = ps[e];
        }
    }
    __syncthreads();
    #pragma unroll
    for (int e = t; e < 1024; e += 128) {
        int jj = e >> 6, cc = e & 63;
        size_t rowb = ((size_t)b * NPTS + idx_s[jj]) * 768;
        *(float4*)&k_s[jj][cc*4] = *(const float4*)(g_qkv + rowb + 256 + cc*4);
        *(float4*)&v_s[jj][cc*4] = *(const float4*)(g_qkv + rowb + 512 + cc*4);
    }
    __syncthreads();
    {
        int p = t >> 1, half = t & 1;
        int jj = p & 15, h = p >> 4;
        float s = 0.f;
        int cbs = half * 32;
        #pragma unroll
        for (int c = 0; c < 32; ++c) {
            int cc = cbs + c;
            s = fmaf(q_s[h*64+cc], k_s[jj][h*64+cc] + pos_s[jj][cc], s);
        }
        s += __shfl_xor_sync(~0u, s, 1);
        if (half == 0) logit_s[h*16 + jj] = s * 0.125f;
    }
    __syncthreads();
    if (t < 4) {
        int h = t;
        float l[16], mx = -3.402823e38f;
        #pragma unroll
        for (int j = 0; j < 16; ++j) { l[j] = logit_s[h*16+j]; mx = fmaxf(mx, l[j]); }
        float sum = 0.f;
        #pragma unroll
        for (int j = 0; j < 16; ++j) { l[j] = expf(l[j] - mx); sum += l[j]; }
        float inv = 1.f / sum;
        size_t ob = (((size_t)b*NH + h) * NPTS + n) * KNBR;
        #pragma unroll
        for (int j = 0; j < 16; ++j) {
            float a = l[j] * inv;
            attn_s[h*16+j] = a;
            attn_out[ob + j] = a;
        }
    }
    __syncthreads();
    #pragma unroll
    for (int e = t; e < 256; e += 128) {
        int h = e >> 6, c = e & 63;
        float s = 0.f;
        #pragma unroll
        for (int j = 0; j < 16; ++j)
            s = fmaf(attn_s[h*16+j], v_s[j][e] + pos_s[j][c], s);
        float hs = rndbf(s);
        g_mid_h[(size_t)gp * DOUT + e] = __float2bfloat16_rn(s);
        g_mid_l[(size_t)gp * DOUT + e] = __float2bfloat16_rn(s - hs);
    }
}

// ---------------- final: LN(fc2)*g2+b2 + lnq -> out ----------------
__global__ void k_final(const float* __restrict__ g2, const float* __restrict__ b2,
                        float* __restrict__ out) {
    int warp = (blockIdx.x * blockDim.x + threadIdx.x) >> 5;
    int lane = threadIdx.x & 31;
    const float4* row = (const float4*)(g_fc2 + (size_t)warp * DOUT);
    float4 v0 = row[lane*2], v1 = row[lane*2+1];
    float s = v0.x+v0.y+v0.z+v0.w + v1.x+v1.y+v1.z+v1.w;
    #pragma unroll
    for (int o = 16; o; o >>= 1) s += __shfl_xor_sync(~0u, s, o);
    float mu = s * (1.f/256.f);
    float d0x=v0.x-mu, d0y=v0.y-mu, d0z=v0.z-mu, d0w=v0.w-mu;
    float d1x=v1.x-mu, d1y=v1.y-mu, d1z=v1.z-mu, d1w=v1.w-mu;
    float s2 = d0x*d0x+d0y*d0y+d0z*d0z+d0w*d0w + d1x*d1x+d1y*d1y+d1z*d1z+d1w*d1w;
    #pragma unroll
    for (int o = 16; o; o >>= 1) s2 += __shfl_xor_sync(~0u, s2, o);
    float rs = rsqrtf(s2 * (1.f/256.f) + 1e-5f);
    float4 gA = ((const float4*)g2)[lane*2],  gB = ((const float4*)g2)[lane*2+1];
    float4 bA = ((const float4*)b2)[lane*2],  bB = ((const float4*)b2)[lane*2+1];
    const float4* lq = (const float4*)(g_lnq + (size_t)warp * DOUT);
    float4 qA = lq[lane*2], qB = lq[lane*2+1];
    float4 oA, oB;
    oA.x = d0x*rs*gA.x + bA.x + qA.x; oA.y = d0y*rs*gA.y + bA.y + qA.y;
    oA.z = d0z*rs*gA.z + bA.z + qA.z; oA.w = d0w*rs*gA.w + bA.w + qA.w;
    oB.x = d1x*rs*gB.x + bB.x + qB.x; oB.y = d1y*rs*gB.y + bB.y + qB.y;
    oB.z = d1z*rs*gB.z + bB.z + qB.z; oB.w = d1w*rs*gB.w + bB.w + qB.w;
    float4* dst = (float4*)(out + (size_t)warp * DOUT);
    dst[lane*2]   = oA;
    dst[lane*2+1] = oB;
}

// ---------------- host launcher ----------------
extern "C" void kernel_launch(void* const* d_in, const int* in_sizes, int n_in,
                              void* d_out, int out_size) {
    const float* xyz      = (const float*)d_in[0];
    const float* features = (const float*)d_in[1];
    const float* Wq  = (const float*)d_in[2];
    const float* bq  = (const float*)d_in[3];
    const float* Wk  = (const float*)d_in[4];
    const float* bk  = (const float*)d_in[5];
    const float* Wv  = (const float*)d_in[6];
    const float* bv  = (const float*)d_in[7];
    const float* Wp1 = (const float*)d_in[8];
    const float* bp1 = (const float*)d_in[9];
    const float* Wp2 = (const float*)d_in[10];
    const float* bp2 = (const float*)d_in[11];
    const float* Wf1 = (const float*)d_in[12];
    const float* bf1 = (const float*)d_in[13];
    const float* Wf2 = (const float*)d_in[14];
    const float* bf2 = (const float*)d_in[15];
    const float* g1  = (const float*)d_in[16];
    const float* b1  = (const float*)d_in[17];
    const float* g2  = (const float*)d_in[18];
    const float* b2  = (const float*)d_in[19];

    float* out      = (float*)d_out;
    float* attn_out = out + (size_t)ROWS * DOUT;

    #define SYM(p, s) float* p; cudaGetSymbolAddress((void**)&p, s)
    #define SYMB(p, s) __nv_bfloat16* p; cudaGetSymbolAddress((void**)&p, s)
    SYMB(p_feat_h, g_feat_h); SYMB(p_feat_l, g_feat_l);
    SYMB(p_lnf_h,  g_lnf_h);  SYMB(p_lnf_l,  g_lnf_l);
    SYM(p_qkv, g_qkv); SYM(p_lnq, g_lnq); SYM(p_fc2, g_fc2);
    SYMB(p_mid_h, g_mid_h); SYMB(p_mid_l, g_mid_l);
    SYMB(p_fc1_h, g_fc1_h); SYMB(p_fc1_l, g_fc1_l);
    SYMB(p_wqkvT_h, g_wqkvT_h); SYMB(p_wqkvT_l, g_wqkvT_l);
    SYMB(p_wp2T_h, g_wp2T_h);   SYMB(p_wp2T_l, g_wp2T_l);
    SYMB(p_wf1T_h, g_wf1T_h);   SYMB(p_wf1T_l, g_wf1T_l);
    SYMB(p_wf2T_h, g_wf2T_h);   SYMB(p_wf2T_l, g_wf2T_l);
    SYM(p_bqkv, g_bqkv);

    static bool attr_done = false;
    if (!attr_done) {
        cudaFuncSetAttribute(k_mgemm<128>, cudaFuncAttributeMaxDynamicSharedMemorySize, SMEM_MG);
        cudaFuncSetAttribute(k_mgemm<64>,  cudaFuncAttributeMaxDynamicSharedMemorySize, SMEM_MG);
        cudaFuncSetAttribute(k_pgemm,      cudaFuncAttributeMaxDynamicSharedMemorySize, SMEM_PG);
        cudaFuncSetAttribute(k_knn2,       cudaFuncAttributeMaxDynamicSharedMemorySize, SMEM_KNN);
        attr_done = true;
    }

    k_pack<<<ROWS/256, 256>>>(xyz);
    {
        dim3 kg(NPTS/16, BATCH);
        k_knn2<<<kg, 512, SMEM_KNN>>>();
    }
    k_cvt_split<<<(ROWS*DIM/4)/256, 256>>>(features, p_feat_h, p_feat_l, ROWS*DIM/4);
    k_ln1<<<ROWS/8, 256>>>(features, g1, b1);

    k_cvt_wT<<<(DIM*DOUT+255)/256, 256>>>(Wq, p_wqkvT_h,           p_wqkvT_l,           DIM, DOUT);
    k_cvt_wT<<<(DIM*DOUT+255)/256, 256>>>(Wk, p_wqkvT_h + 256*DIM, p_wqkvT_l + 256*DIM, DIM, DOUT);
    k_cvt_wT<<<(DIM*DOUT+255)/256, 256>>>(Wv, p_wqkvT_h + 512*DIM, p_wqkvT_l + 512*DIM, DIM, DOUT);
    k_cvt_wT<<<(HD*HD+255)/256,    256>>>(Wp2, p_wp2T_h, p_wp2T_l, HD, HD);
    k_cvt_wT<<<(DOUT*DOUT+255)/256,256>>>(Wf1, p_wf1T_h, p_wf1T_l, DOUT, DOUT);
    k_cvt_wT<<<(DOUT*DOUT+255)/256,256>>>(Wf2, p_wf2T_h, p_wf2T_l, DOUT, DOUT);
    k_bpack<<<3, 256>>>(bq, bk, bv);

    // qkv: [32768,128] @ [768,128]^T
    {
        dim3 g(ROWS/128, 6);
        k_mgemm<128><<<g, 256, SMEM_MG>>>(p_feat_h, p_feat_l, p_wqkvT_h, p_wqkvT_l,
                                          p_bqkv, p_qkv, nullptr, nullptr, DIM, 768, 0);
    }
    // lnq: LN(features) @ Wq
    {
        dim3 g(ROWS/128, 2);
        k_mgemm<128><<<g, 256, SMEM_MG>>>(p_lnf_h, p_lnf_l, p_wqkvT_h, p_wqkvT_l,
                                          bq, p_lnq, nullptr, nullptr, DIM, DOUT, 0);
    }

    // pos: fused h1 + [524288,64] @ [64,64]^T
    k_pgemm<<<NROWS/128, 256, SMEM_PG>>>(xyz, Wp1, bp1, bp2);

    k_attn<<<ROWS, 128>>>(attn_out);

    // fc1 (relu, bf16-pair out), fc2 (fp32 out)
    {
        dim3 g(ROWS/128, 2);
        k_mgemm<128><<<g, 256, SMEM_MG>>>(p_mid_h, p_mid_l, p_wf1T_h, p_wf1T_l,
                                          bf1, nullptr, p_fc1_h, p_fc1_l, DOUT, DOUT, 1);
        k_mgemm<128><<<g, 256, SMEM_MG>>>(p_fc1_h, p_fc1_l, p_wf2T_h, p_wf2T_l,
                                          bf2, p_fc2, nullptr, nullptr, DOUT, DOUT, 0);
    }

    k_final<<<ROWS/8, 256>>>(g2, b2, out);
}

// round 5
// speedup vs baseline: 1.7212x; 1.0243x over previous
#include <cuda_runtime.h>
#include <cuda_bf16.h>
#include <cstdint>
#include <math.h>

#define BATCH 4
#define NPTS  8192
#define DIM   128
#define DOUT  256
#define NH    4
#define HD    64
#define KNBR  16
#define ROWS  (BATCH*NPTS)          // 32768
#define NROWS (BATCH*NPTS*KNBR)     // 524288

// ---------------- scratch (device globals; no runtime alloc) ----------------
__device__ float4 g_xyzw[ROWS];
__device__ int    g_knn[NROWS];
__device__ __nv_bfloat16 g_feat_h[ROWS*DIM];
__device__ __nv_bfloat16 g_feat_l[ROWS*DIM];
__device__ __nv_bfloat16 g_lnf_h[ROWS*DIM];
__device__ __nv_bfloat16 g_lnf_l[ROWS*DIM];
__device__ float  g_qkv[(size_t)ROWS*768];     // [q|k|v] per row
__device__ float  g_lnq[ROWS*DOUT];
__device__ float  g_pos[(size_t)NROWS*HD];
__device__ __nv_bfloat16 g_mid_h[ROWS*DOUT];
__device__ __nv_bfloat16 g_mid_l[ROWS*DOUT];
__device__ __nv_bfloat16 g_fc1_h[ROWS*DOUT];
__device__ __nv_bfloat16 g_fc1_l[ROWS*DOUT];
__device__ float  g_fc2[ROWS*DOUT];
// transposed bf16-split weights
__device__ __nv_bfloat16 g_wqkvT_h[768*DIM];
__device__ __nv_bfloat16 g_wqkvT_l[768*DIM];
__device__ __nv_bfloat16 g_wp2T_h[HD*HD];
__device__ __nv_bfloat16 g_wp2T_l[HD*HD];
__device__ __nv_bfloat16 g_wf1T_h[DOUT*DOUT];
__device__ __nv_bfloat16 g_wf1T_l[DOUT*DOUT];
__device__ __nv_bfloat16 g_wf2T_h[DOUT*DOUT];
__device__ __nv_bfloat16 g_wf2T_l[DOUT*DOUT];
__device__ float g_bqkv[768];

// ---------------- small helpers ----------------
__device__ __forceinline__ unsigned pk2(float a, float b) {
    __nv_bfloat162 t = __floats2bfloat162_rn(a, b);
    return *(unsigned*)&t;
}
__device__ __forceinline__ float rndbf(float x) {
    return __bfloat162float(__float2bfloat16_rn(x));
}
__device__ __forceinline__ uint32_t smem_u32(const void* p) {
    uint32_t a;
    asm("{ .reg .u64 t; cvta.to.shared.u64 t, %1; cvt.u32.u64 %0, t; }" : "=r"(a) : "l"(p));
    return a;
}
__device__ __forceinline__ uint32_t swz(uint32_t x) { return x ^ ((x >> 3) & 0x70); }

__device__ __forceinline__ void ldsm4(uint32_t* r, uint32_t addr) {
    asm volatile("ldmatrix.sync.aligned.m8n8.x4.shared.b16 {%0,%1,%2,%3}, [%4];"
        : "=r"(r[0]), "=r"(r[1]), "=r"(r[2]), "=r"(r[3]) : "r"(addr));
}
__device__ __forceinline__ void mma16816(float* c, const uint32_t* a, uint32_t b0, uint32_t b1) {
    asm volatile("mma.sync.aligned.m16n8k16.row.col.f32.bf16.bf16.f32 "
        "{%0,%1,%2,%3}, {%4,%5,%6,%7}, {%8,%9}, {%0,%1,%2,%3};"
        : "+f"(c[0]), "+f"(c[1]), "+f"(c[2]), "+f"(c[3])
        : "r"(a[0]), "r"(a[1]), "r"(a[2]), "r"(a[3]), "r"(b0), "r"(b1));
}
#define CP16(dst, src) asm volatile("cp.async.cg.shared.global [%0], [%1], 16;" :: "r"(dst), "l"(src))
#define CP_COMMIT()    asm volatile("cp.async.commit_group;" ::: "memory")
#define CP_WAIT1()     asm volatile("cp.async.wait_group 1;" ::: "memory")

// ---------------- pack xyz + squared norm ----------------
__global__ void k_pack(const float* __restrict__ xyz) {
    int i = blockIdx.x * 256 + threadIdx.x;
    if (i >= ROWS) return;
    float x = xyz[i*3+0], y = xyz[i*3+1], z = xyz[i*3+2];
    g_xyzw[i] = make_float4(x, y, z, x*x + y*y + z*z);
}

// ---------------- KNN: warp/query, sample-threshold + collect + 16x argmin ----------------
#define KNN_CAP 256
#define SMEM_KNN (32768 + 16*KNN_CAP*8)

__global__ void __launch_bounds__(512) k_knn2() {
    extern __shared__ char sk[];
    float4* tile = (float4*)sk;
    float*  bkey = (float*)(sk + 32768);
    int*    bidx = (int*)(sk + 32768 + 16*KNN_CAP*4);
    int t = threadIdx.x, lane = t & 31, w = t >> 5;
    int b = blockIdx.y;
    int q = blockIdx.x * 16 + w;
    const float INF = 3.402823e38f;

    float4 me = g_xyzw[b*NPTS + q];
    float qx2 = -2.f*me.x, qy2 = -2.f*me.y, qz2 = -2.f*me.z;

    float T = 0.f;
    int base = 0;
    float* mk = bkey + w*KNN_CAP;
    int*   mi = bidx + w*KNN_CAP;

    for (int ti = 0; ti < 4; ++ti) {
        __syncthreads();
        for (int i = t; i < 2048; i += 512)
            tile[i] = g_xyzw[b*NPTS + ti*2048 + i];
        __syncthreads();

        if (ti == 0) {
            float mn = INF;
            #pragma unroll 8
            for (int i = 0; i < 64; ++i) {
                float4 p = tile[i*32 + lane];
                float d = fmaf(qx2,p.x,fmaf(qy2,p.y,fmaf(qz2,p.z,p.w)));
                mn = fminf(mn, d);
            }
            float v = mn;
            #pragma unroll
            for (int k = 2; k <= 32; k <<= 1) {
                #pragma unroll
                for (int j = k >> 1; j > 0; j >>= 1) {
                    float o = __shfl_xor_sync(~0u, v, j);
                    bool up = ((lane & k) == 0);
                    bool lower = ((lane & j) == 0);
                    v = (lower == up) ? fminf(v, o) : fmaxf(v, o);
                }
            }
            T = __shfl_sync(~0u, v, 15);
        }

        #pragma unroll 4
        for (int c = 0; c < 64; ++c) {
            int j = c*32 + lane;
            float4 p = tile[j];
            float d = fmaf(qx2,p.x,fmaf(qy2,p.y,fmaf(qz2,p.z,p.w)));
            bool pass = (d <= T);
            unsigned m = __ballot_sync(~0u, pass);
            if (pass) {
                int pos = base + __popc(m & ((1u << lane) - 1u));
                if (pos < KNN_CAP) { mk[pos] = d; mi[pos] = ti*2048 + j; }
            }
            base += __popc(m);
        }
    }
    if (base > KNN_CAP) base = KNN_CAP;
    __syncwarp();

    size_t ob = ((size_t)b*NPTS + q) * KNBR;
    for (int r = 0; r < KNBR; ++r) {
        float bk = INF; int bi = 0x7fffffff; int bp = -1;
        for (int i = lane; i < base; i += 32) {
            float kk = mk[i];
            int   ii = mi[i];
            if (kk < bk || (kk == bk && ii < bi)) { bk = kk; bi = ii; bp = i; }
        }
        #pragma unroll
        for (int o = 16; o; o >>= 1) {
            float ok = __shfl_xor_sync(~0u, bk, o);
            int   oi = __shfl_xor_sync(~0u, bi, o);
            int   op = __shfl_xor_sync(~0u, bp, o);
            if (ok < bk || (ok == bk && oi < bi)) { bk = ok; bi = oi; bp = op; }
        }
        if (lane == 0) {
            g_knn[ob + r] = bi;
            if (bp >= 0) mk[bp] = INF;
        }
        __syncwarp();
    }
}

// ---------------- split fp32 -> bf16 hi/lo ----------------
__global__ void k_cvt_split(const float* __restrict__ x, __nv_bfloat16* __restrict__ h,
                            __nv_bfloat16* __restrict__ l, int n4) {
    int i = blockIdx.x * 256 + threadIdx.x;
    if (i >= n4) return;
    float4 v = ((const float4*)x)[i];
    float hx = rndbf(v.x), hy = rndbf(v.y), hz = rndbf(v.z), hw = rndbf(v.w);
    uint2 hh = { pk2(v.x, v.y), pk2(v.z, v.w) };
    uint2 ll = { pk2(v.x - hx, v.y - hy), pk2(v.z - hz, v.w - hw) };
    ((uint2*)h)[i] = hh;
    ((uint2*)l)[i] = ll;
}

// ---------------- transpose + split weight: W[K,N] -> T[N,K] bf16 hi/lo ----------------
__global__ void k_cvt_wT(const float* __restrict__ W, __nv_bfloat16* __restrict__ Th,
                         __nv_bfloat16* __restrict__ Tl, int Kd, int Nd) {
    int i = blockIdx.x * 256 + threadIdx.x;
    if (i >= Kd * Nd) return;
    int n = i / Kd, k = i % Kd;
    float x = W[(size_t)k * Nd + n];
    float hx = rndbf(x);
    Th[i] = __float2bfloat16_rn(x);
    Tl[i] = __float2bfloat16_rn(x - hx);
}

__global__ void k_bpack(const float* __restrict__ a, const float* __restrict__ b,
                        const float* __restrict__ c) {
    int t = threadIdx.x + blockIdx.x * 256;
    if (t < 256)      g_bqkv[t] = a[t];
    else if (t < 512) g_bqkv[t] = b[t-256];
    else if (t < 768) g_bqkv[t] = c[t-512];
}

// ---------------- LayerNorm dim=128 -> bf16 hi/lo ----------------
__global__ void k_ln1(const float* __restrict__ x, const float* __restrict__ g,
                      const float* __restrict__ bta) {
    int warp = (blockIdx.x * blockDim.x + threadIdx.x) >> 5;
    int lane = threadIdx.x & 31;
    const float4* row = (const float4*)(x + (size_t)warp * DIM);
    float4 v = row[lane];
    float s = v.x + v.y + v.z + v.w;
    #pragma unroll
    for (int o = 16; o; o >>= 1) s += __shfl_xor_sync(~0u, s, o);
    float mu = s * (1.f/128.f);
    float dx = v.x-mu, dy = v.y-mu, dz = v.z-mu, dw = v.w-mu;
    float s2 = dx*dx + dy*dy + dz*dz + dw*dw;
    #pragma unroll
    for (int o = 16; o; o >>= 1) s2 += __shfl_xor_sync(~0u, s2, o);
    float rs = rsqrtf(s2 * (1.f/128.f) + 1e-5f);
    float4 gg = ((const float4*)g)[lane];
    float4 bb = ((const float4*)bta)[lane];
    float rx = dx*rs*gg.x + bb.x, ry = dy*rs*gg.y + bb.y;
    float rz = dz*rs*gg.z + bb.z, rw = dw*rs*gg.w + bb.w;
    float hx = rndbf(rx), hy = rndbf(ry), hz = rndbf(rz), hw = rndbf(rw);
    int idx = warp*32 + lane;
    ((uint2*)g_lnf_h)[idx] = make_uint2(pk2(rx, ry), pk2(rz, rw));
    ((uint2*)g_lnf_l)[idx] = make_uint2(pk2(rx-hx, ry-hy), pk2(rz-hz, rw-hw));
}

// ---------------- cp.async pipelined mma GEMM (bf16 split x3) ----------------
// SMEM row layout (128B): [hi 64B | lo 64B] per 32-fp32-col chunk.
// 2 stages; stage = A(128 rows) + B(NT rows).
template<int NT>
__global__ void __launch_bounds__(256) k_mgemm(
    const __nv_bfloat16* __restrict__ Ah, const __nv_bfloat16* __restrict__ Al,
    const __nv_bfloat16* __restrict__ Bh, const __nv_bfloat16* __restrict__ Bl,
    const float* __restrict__ bias,
    float* __restrict__ Cf, __nv_bfloat16* __restrict__ Ch, __nv_bfloat16* __restrict__ Cl,
    int K, int ldc, int relu)
{
    constexpr int WN = NT / 2;
    constexpr int NB = WN / 16;
    constexpr int STGB = 16384 + NT*128;
    extern __shared__ char sm[];
    uint32_t smb = smem_u32(sm);
    int t = threadIdx.x, lane = t & 31, w = t >> 5;
    int wm = w & 3, wn = w >> 2;
    int r0 = blockIdx.x * 128, c0 = blockIdx.y * NT;
    int nch = K >> 5;

    float acc[2][2*NB][4];
    #pragma unroll
    for (int i = 0; i < 2; ++i)
        #pragma unroll
        for (int j = 0; j < 2*NB; ++j)
            #pragma unroll
            for (int e = 0; e < 4; ++e) acc[i][j][e] = 0.f;

    int lrow = lane & 15;
    int lcb  = (lane >> 4) * 16;

    // stage loader
    auto issue = [&](int c, int stg) {
        int kc = c * 32;
        uint32_t Ab = smb + stg*STGB;
        uint32_t Bb = Ab + 16384;
        #pragma unroll
        for (int i = 0; i < 4; ++i) {
            int e = t + i*256;
            int row = e >> 3, seg = e & 7;
            const __nv_bfloat16* src = (seg < 4 ? Ah : Al) + (size_t)(r0+row)*K + kc + (seg & 3)*8;
            CP16(Ab + swz((uint32_t)row*128 + seg*16), src);
        }
        #pragma unroll
        for (int i = 0; i < NT/32; ++i) {
            int e = t + i*256;
            int row = e >> 3, seg = e & 7;
            const __nv_bfloat16* src = (seg < 4 ? Bh : Bl) + (size_t)(c0+row)*K + kc + (seg & 3)*8;
            CP16(Bb + swz((uint32_t)row*128 + seg*16), src);
        }
    };

    issue(0, 0); CP_COMMIT();
    issue(1, 1); CP_COMMIT();

    for (int c = 0; c < nch; ++c) {
        CP_WAIT1();
        __syncthreads();
        uint32_t Ab = smb + (c & 1)*STGB;
        uint32_t Bb = Ab + 16384;
        #pragma unroll
        for (int s = 0; s < 2; ++s) {
            int kb = s*32 + lcb;
            uint32_t ah[2][4], al[2][4];
            #pragma unroll
            for (int mb = 0; mb < 2; ++mb) {
                uint32_t ro = (uint32_t)(wm*32 + mb*16 + lrow)*128;
                ldsm4(ah[mb], Ab + swz(ro + kb));
                ldsm4(al[mb], Ab + swz(ro + 64 + kb));
            }
            #pragma unroll
            for (int nb = 0; nb < NB; ++nb) {
                uint32_t bh[4], bl[4];
                uint32_t ro = (uint32_t)(wn*WN + nb*16 + lrow)*128;
                ldsm4(bh, Bb + swz(ro + kb));
                ldsm4(bl, Bb + swz(ro + 64 + kb));
                #pragma unroll
                for (int mb = 0; mb < 2; ++mb) {
                    float* cA = acc[mb][nb*2];
                    float* cB = acc[mb][nb*2+1];
                    mma16816(cA, ah[mb], bh[0], bh[2]);
                    mma16816(cB, ah[mb], bh[1], bh[3]);
                    mma16816(cA, ah[mb], bl[0], bl[2]);
                    mma16816(cB, ah[mb], bl[1], bl[3]);
                    mma16816(cA, al[mb], bh[0], bh[2]);
                    mma16816(cB, al[mb], bh[1], bh[3]);
                }
            }
        }
        __syncthreads();
        if (c + 2 < nch) issue(c + 2, c & 1);
        CP_COMMIT();
    }

    int rbase = r0 + wm*32 + (lane >> 2);
    int cb = c0 + wn*WN + (lane & 3)*2;
    #pragma unroll
    for (int mb = 0; mb < 2; ++mb) {
        #pragma unroll
        for (int nn = 0; nn < 2*NB; ++nn) {
            int col = cb + nn*8;
            float b0 = bias[col], b1 = bias[col+1];
            float v0 = acc[mb][nn][0] + b0, v1 = acc[mb][nn][1] + b1;
            float v2 = acc[mb][nn][2] + b0, v3 = acc[mb][nn][3] + b1;
            if (relu) {
                v0 = fmaxf(v0, 0.f); v1 = fmaxf(v1, 0.f);
                v2 = fmaxf(v2, 0.f); v3 = fmaxf(v3, 0.f);
            }
            size_t ra = (size_t)(rbase + mb*16) * ldc + col;
            size_t rb = (size_t)(rbase + mb*16 + 8) * ldc + col;
            if (Cf) {
                *(float2*)(Cf + ra) = make_float2(v0, v1);
                *(float2*)(Cf + rb) = make_float2(v2, v3);
            }
            if (Ch) {
                float h0 = rndbf(v0), h1 = rndbf(v1), h2 = rndbf(v2), h3 = rndbf(v3);
                *(unsigned*)(Ch + ra) = pk2(v0, v1);
                *(unsigned*)(Cl + ra) = pk2(v0-h0, v1-h1);
                *(unsigned*)(Ch + rb) = pk2(v2, v3);
                *(unsigned*)(Cl + rb) = pk2(v2-h2, v3-h3);
            }
        }
    }
}
#define MG_SMEM(NT) (2 * (16384 + (NT)*128))

// ---------------- fused pos GEMM: A = relu(relpos@Wp1+bp1) computed in-kernel ----------------
#define PG_AH 0
#define PG_AL 16384
#define PG_BH 32768
#define PG_BL 40960
#define SMEM_PG 49152

__global__ void __launch_bounds__(256) k_pgemm(
    const float* __restrict__ xyz, const float* __restrict__ Wp1,
    const float* __restrict__ bp1, const float* __restrict__ bias)
{
    extern __shared__ char sm[];
    uint32_t smb = smem_u32(sm);
    int t = threadIdx.x, lane = t & 31, w = t >> 5;
    int wm = w & 3, wn = w >> 2;
    int r0 = blockIdx.x * 128;

    #pragma unroll 2
    for (int e = t; e < 512; e += 256) {
        int row = e >> 3, vo = e & 7;
        uint32_t d = swz(row*128 + vo*16);
        *(uint4*)(sm + PG_BH + d) = *(const uint4*)(g_wp2T_h + row*64 + vo*8);
        *(uint4*)(sm + PG_BL + d) = *(const uint4*)(g_wp2T_l + row*64 + vo*8);
    }

    {
        int row = t >> 1, ch = t & 1;
        int rr = r0 + row;
        int b = rr >> 17, n = (rr >> 4) & (NPTS - 1);
        int idx = g_knn[rr];
        const float* xb = xyz + (size_t)b * NPTS * 3;
        float rx = xb[idx*3+0] - xb[n*3+0];
        float ry = xb[idx*3+1] - xb[n*3+1];
        float rz = xb[idx*3+2] - xb[n*3+2];
        uint32_t hp[16], lp[16];
        #pragma unroll
        for (int cc = 0; cc < 32; cc += 2) {
            int c = ch*32 + cc;
            float v0 = fmaf(rx, Wp1[c],   fmaf(ry, Wp1[64+c],   fmaf(rz, Wp1[128+c],   bp1[c])));
            float v1 = fmaf(rx, Wp1[c+1], fmaf(ry, Wp1[64+c+1], fmaf(rz, Wp1[128+c+1], bp1[c+1])));
            v0 = fmaxf(v0, 0.f); v1 = fmaxf(v1, 0.f);
            float h0 = rndbf(v0), h1 = rndbf(v1);
            hp[cc>>1] = pk2(v0, v1);
            lp[cc>>1] = pk2(v0-h0, v1-h1);
        }
        uint32_t rbyte = (uint32_t)row*128 + ch*64;
        #pragma unroll
        for (int i = 0; i < 4; ++i) {
            uint32_t d = swz(rbyte + i*16);
            *(uint4*)(sm + PG_AH + d) = *(uint4*)&hp[i*4];
            *(uint4*)(sm + PG_AL + d) = *(uint4*)&lp[i*4];
        }
    }
    __syncthreads();

    float acc[2][4][4];
    #pragma unroll
    for (int i = 0; i < 2; ++i)
        #pragma unroll
        for (int j = 0; j < 4; ++j)
            #pragma unroll
            for (int e = 0; e < 4; ++e) acc[i][j][e] = 0.f;
    int lrow = lane & 15, lcolb = (lane >> 4) * 16;
    #pragma unroll
    for (int s = 0; s < 4; ++s) {
        int kb = s*32 + lcolb;
        uint32_t ah[2][4], al[2][4];
        #pragma unroll
        for (int mb = 0; mb < 2; ++mb) {
            uint32_t off = swz((uint32_t)(wm*32 + mb*16 + lrow)*128 + kb);
            ldsm4(ah[mb], smb + PG_AH + off);
            ldsm4(al[mb], smb + PG_AL + off);
        }
        #pragma unroll
        for (int nb = 0; nb < 2; ++nb) {
            uint32_t bh[4], bl[4];
            uint32_t off = swz((uint32_t)(wn*32 + nb*16 + lrow)*128 + kb);
            ldsm4(bh, smb + PG_BH + off);
            ldsm4(bl, smb + PG_BL + off);
            #pragma unroll
            for (int mb = 0; mb < 2; ++mb) {
                float* cA = acc[mb][nb*2];
                float* cB = acc[mb][nb*2+1];
                mma16816(cA, ah[mb], bh[0], bh[2]);
                mma16816(cB, ah[mb], bh[1], bh[3]);
                mma16816(cA, ah[mb], bl[0], bl[2]);
                mma16816(cB, ah[mb], bl[1], bl[3]);
                mma16816(cA, al[mb], bh[0], bh[2]);
                mma16816(cB, al[mb], bh[1], bh[3]);
            }
        }
    }

    int rbase = r0 + wm*32 + (lane >> 2);
    int cb = wn*32 + (lane & 3)*2;
    #pragma unroll
    for (int mb = 0; mb < 2; ++mb) {
        #pragma unroll
        for (int nn = 0; nn < 4; ++nn) {
            int col = cb + nn*8;
            float b0 = bias[col], b1 = bias[col+1];
            size_t ra = (size_t)(rbase + mb*16) * HD + col;
            size_t rb = (size_t)(rbase + mb*16 + 8) * HD + col;
            *(float2*)(g_pos + ra) = make_float2(acc[mb][nn][0] + b0, acc[mb][nn][1] + b1);
            *(float2*)(g_pos + rb) = make_float2(acc[mb][nn][2] + b0, acc[mb][nn][3] + b1);
        }
    }
}

// ---------------- fused attention ----------------
__global__ void __launch_bounds__(128) k_attn(float* __restrict__ attn_out) {
    __shared__ int   idx_s[16];
    __shared__ float pos_s[16][68];
    __shared__ float k_s[16][260];
    __shared__ float v_s[16][260];
    __shared__ float q_s[256];
    __shared__ float logit_s[64];
    __shared__ float attn_s[64];
    int t  = threadIdx.x;
    int gp = blockIdx.x;
    int b  = gp >> 13, n = gp & (NPTS-1);

    if (t < 16) idx_s[t] = g_knn[gp*KNBR + t];
    if (t < 64) ((float4*)q_s)[t] = ((const float4*)(g_qkv + (size_t)gp * 768))[t];
    {
        const float4* ps = (const float4*)(g_pos + (size_t)gp * KNBR * HD);
        #pragma unroll
        for (int e = t; e < 256; e += 128) {
            int jj = e >> 4, cc = e & 15;
            *(float4*)&pos_s[jj][cc*4] = ps[e];
        }
    }
    __syncthreads();
    #pragma unroll
    for (int e = t; e < 1024; e += 128) {
        int jj = e >> 6, cc = e & 63;
        size_t rowb = ((size_t)b * NPTS + idx_s[jj]) * 768;
        *(float4*)&k_s[jj][cc*4] = *(const float4*)(g_qkv + rowb + 256 + cc*4);
        *(float4*)&v_s[jj][cc*4] = *(const float4*)(g_qkv + rowb + 512 + cc*4);
    }
    __syncthreads();
    {
        int p = t >> 1, half = t & 1;
        int jj = p & 15, h = p >> 4;
        float s = 0.f;
        int cbs = half * 32;
        #pragma unroll
        for (int c = 0; c < 32; ++c) {
            int cc = cbs + c;
            s = fmaf(q_s[h*64+cc], k_s[jj][h*64+cc] + pos_s[jj][cc], s);
        }
        s += __shfl_xor_sync(~0u, s, 1);
        if (half == 0) logit_s[h*16 + jj] = s * 0.125f;
    }
    __syncthreads();
    if (t < 4) {
        int h = t;
        float l[16], mx = -3.402823e38f;
        #pragma unroll
        for (int j = 0; j < 16; ++j) { l[j] = logit_s[h*16+j]; mx = fmaxf(mx, l[j]); }
        float sum = 0.f;
        #pragma unroll
        for (int j = 0; j < 16; ++j) { l[j] = expf(l[j] - mx); sum += l[j]; }
        float inv = 1.f / sum;
        size_t ob = (((size_t)b*NH + h) * NPTS + n) * KNBR;
        #pragma unroll
        for (int j = 0; j < 16; ++j) {
            float a = l[j] * inv;
            attn_s[h*16+j] = a;
            attn_out[ob + j] = a;
        }
    }
    __syncthreads();
    #pragma unroll
    for (int e = t; e < 256; e += 128) {
        int h = e >> 6, c = e & 63;
        float s = 0.f;
        #pragma unroll
        for (int j = 0; j < 16; ++j)
            s = fmaf(attn_s[h*16+j], v_s[j][e] + pos_s[j][c], s);
        float hs = rndbf(s);
        g_mid_h[(size_t)gp * DOUT + e] = __float2bfloat16_rn(s);
        g_mid_l[(size_t)gp * DOUT + e] = __float2bfloat16_rn(s - hs);
    }
}

// ---------------- final: LN(fc2)*g2+b2 + lnq -> out ----------------
__global__ void k_final(const float* __restrict__ g2, const float* __restrict__ b2,
                        float* __restrict__ out) {
    int warp = (blockIdx.x * blockDim.x + threadIdx.x) >> 5;
    int lane = threadIdx.x & 31;
    const float4* row = (const float4*)(g_fc2 + (size_t)warp * DOUT);
    float4 v0 = row[lane*2], v1 = row[lane*2+1];
    float s = v0.x+v0.y+v0.z+v0.w + v1.x+v1.y+v1.z+v1.w;
    #pragma unroll
    for (int o = 16; o; o >>= 1) s += __shfl_xor_sync(~0u, s, o);
    float mu = s * (1.f/256.f);
    float d0x=v0.x-mu, d0y=v0.y-mu, d0z=v0.z-mu, d0w=v0.w-mu;
    float d1x=v1.x-mu, d1y=v1.y-mu, d1z=v1.z-mu, d1w=v1.w-mu;
    float s2 = d0x*d0x+d0y*d0y+d0z*d0z+d0w*d0w + d1x*d1x+d1y*d1y+d1z*d1z+d1w*d1w;
    #pragma unroll
    for (int o = 16; o; o >>= 1) s2 += __shfl_xor_sync(~0u, s2, o);
    float rs = rsqrtf(s2 * (1.f/256.f) + 1e-5f);
    float4 gA = ((const float4*)g2)[lane*2],  gB = ((const float4*)g2)[lane*2+1];
    float4 bA = ((const float4*)b2)[lane*2],  bB = ((const float4*)b2)[lane*2+1];
    const float4* lq = (const float4*)(g_lnq + (size_t)warp * DOUT);
    float4 qA = lq[lane*2], qB = lq[lane*2+1];
    float4 oA, oB;
    oA.x = d0x*rs*gA.x + bA.x + qA.x; oA.y = d0y*rs*gA.y + bA.y + qA.y;
    oA.z = d0z*rs*gA.z + bA.z + qA.z; oA.w = d0w*rs*gA.w + bA.w + qA.w;
    oB.x = d1x*rs*gB.x + bB.x + qB.x; oB.y = d1y*rs*gB.y + bB.y + qB.y;
    oB.z = d1z*rs*gB.z + bB.z + qB.z; oB.w = d1w*rs*gB.w + bB.w + qB.w;
    float4* dst = (float4*)(out + (size_t)warp * DOUT);
    dst[lane*2]   = oA;
    dst[lane*2+1] = oB;
}

// ---------------- host launcher ----------------
extern "C" void kernel_launch(void* const* d_in, const int* in_sizes, int n_in,
                              void* d_out, int out_size) {
    const float* xyz      = (const float*)d_in[0];
    const float* features = (const float*)d_in[1];
    const float* Wq  = (const float*)d_in[2];
    const float* bq  = (const float*)d_in[3];
    const float* Wk  = (const float*)d_in[4];
    const float* bk  = (const float*)d_in[5];
    const float* Wv  = (const float*)d_in[6];
    const float* bv  = (const float*)d_in[7];
    const float* Wp1 = (const float*)d_in[8];
    const float* bp1 = (const float*)d_in[9];
    const float* Wp2 = (const float*)d_in[10];
    const float* bp2 = (const float*)d_in[11];
    const float* Wf1 = (const float*)d_in[12];
    const float* bf1 = (const float*)d_in[13];
    const float* Wf2 = (const float*)d_in[14];
    const float* bf2 = (const float*)d_in[15];
    const float* g1  = (const float*)d_in[16];
    const float* b1  = (const float*)d_in[17];
    const float* g2  = (const float*)d_in[18];
    const float* b2  = (const float*)d_in[19];

    float* out      = (float*)d_out;
    float* attn_out = out + (size_t)ROWS * DOUT;

    #define SYM(p, s) float* p; cudaGetSymbolAddress((void**)&p, s)
    #define SYMB(p, s) __nv_bfloat16* p; cudaGetSymbolAddress((void**)&p, s)
    SYMB(p_feat_h, g_feat_h); SYMB(p_feat_l, g_feat_l);
    SYMB(p_lnf_h,  g_lnf_h);  SYMB(p_lnf_l,  g_lnf_l);
    SYM(p_qkv, g_qkv); SYM(p_lnq, g_lnq); SYM(p_fc2, g_fc2);
    SYMB(p_mid_h, g_mid_h); SYMB(p_mid_l, g_mid_l);
    SYMB(p_fc1_h, g_fc1_h); SYMB(p_fc1_l, g_fc1_l);
    SYMB(p_wqkvT_h, g_wqkvT_h); SYMB(p_wqkvT_l, g_wqkvT_l);
    SYMB(p_wp2T_h, g_wp2T_h);   SYMB(p_wp2T_l, g_wp2T_l);
    SYMB(p_wf1T_h, g_wf1T_h);   SYMB(p_wf1T_l, g_wf1T_l);
    SYMB(p_wf2T_h, g_wf2T_h);   SYMB(p_wf2T_l, g_wf2T_l);
    SYM(p_bqkv, g_bqkv);

    static bool attr_done = false;
    if (!attr_done) {
        cudaFuncSetAttribute(k_mgemm<128>, cudaFuncAttributeMaxDynamicSharedMemorySize, MG_SMEM(128));
        cudaFuncSetAttribute(k_mgemm<64>,  cudaFuncAttributeMaxDynamicSharedMemorySize, MG_SMEM(64));
        cudaFuncSetAttribute(k_pgemm,      cudaFuncAttributeMaxDynamicSharedMemorySize, SMEM_PG);
        cudaFuncSetAttribute(k_knn2,       cudaFuncAttributeMaxDynamicSharedMemorySize, SMEM_KNN);
        attr_done = true;
    }

    k_pack<<<ROWS/256, 256>>>(xyz);
    {
        dim3 kg(NPTS/16, BATCH);
        k_knn2<<<kg, 512, SMEM_KNN>>>();
    }
    k_cvt_split<<<(ROWS*DIM/4)/256, 256>>>(features, p_feat_h, p_feat_l, ROWS*DIM/4);
    k_ln1<<<ROWS/8, 256>>>(features, g1, b1);

    k_cvt_wT<<<(DIM*DOUT+255)/256, 256>>>(Wq, p_wqkvT_h,           p_wqkvT_l,           DIM, DOUT);
    k_cvt_wT<<<(DIM*DOUT+255)/256, 256>>>(Wk, p_wqkvT_h + 256*DIM, p_wqkvT_l + 256*DIM, DIM, DOUT);
    k_cvt_wT<<<(DIM*DOUT+255)/256, 256>>>(Wv, p_wqkvT_h + 512*DIM, p_wqkvT_l + 512*DIM, DIM, DOUT);
    k_cvt_wT<<<(HD*HD+255)/256,    256>>>(Wp2, p_wp2T_h, p_wp2T_l, HD, HD);
    k_cvt_wT<<<(DOUT*DOUT+255)/256,256>>>(Wf1, p_wf1T_h, p_wf1T_l, DOUT, DOUT);
    k_cvt_wT<<<(DOUT*DOUT+255)/256,256>>>(Wf2, p_wf2T_h, p_wf2T_l, DOUT, DOUT);
    k_bpack<<<3, 256>>>(bq, bk, bv);

    // qkv: [32768,128] @ [768,128]^T
    {
        dim3 g(ROWS/128, 6);
        k_mgemm<128><<<g, 256, MG_SMEM(128)>>>(p_feat_h, p_feat_l, p_wqkvT_h, p_wqkvT_l,
                                               p_bqkv, p_qkv, nullptr, nullptr, DIM, 768, 0);
    }
    // lnq: LN(features) @ Wq
    {
        dim3 g(ROWS/128, 2);
        k_mgemm<128><<<g, 256, MG_SMEM(128)>>>(p_lnf_h, p_lnf_l, p_wqkvT_h, p_wqkvT_l,
                                               bq, p_lnq, nullptr, nullptr, DIM, DOUT, 0);
    }

    // pos: fused h1 + [524288,64] @ [64,64]^T
    k_pgemm<<<NROWS/128, 256, SMEM_PG>>>(xyz, Wp1, bp1, bp2);

    k_attn<<<ROWS, 128>>>(attn_out);

    // fc1 (relu, bf16-pair out), fc2 (fp32 out)
    {
        dim3 g(ROWS/128, 2);
        k_mgemm<128><<<g, 256, MG_SMEM(128)>>>(p_mid_h, p_mid_l, p_wf1T_h, p_wf1T_l,
                                               bf1, nullptr, p_fc1_h, p_fc1_l, DOUT, DOUT, 1);
        k_mgemm<128><<<g, 256, MG_SMEM(128)>>>(p_fc1_h, p_fc1_l, p_wf2T_h, p_wf2T_l,
                                               bf2, p_fc2, nullptr, nullptr, DOUT, DOUT, 0);
    }

    k_final<<<ROWS/8, 256>>>(g2, b2, out);
}

// round 6
// speedup vs baseline: 1.7880x; 1.0388x over previous
#include <cuda_runtime.h>
#include <cuda_bf16.h>
#include <cstdint>
#include <math.h>

#define BATCH 4
#define NPTS  8192
#define DIM   128
#define DOUT  256
#define NH    4
#define HD    64
#define KNBR  16
#define ROWS  (BATCH*NPTS)          // 32768
#define NROWS (BATCH*NPTS*KNBR)     // 524288

// ---------------- scratch (device globals; no runtime alloc) ----------------
__device__ float4 g_xyzw[ROWS];
__device__ int    g_knn[NROWS];
__device__ __nv_bfloat16 g_feat_h[ROWS*DIM];
__device__ __nv_bfloat16 g_feat_l[ROWS*DIM];
__device__ __nv_bfloat16 g_lnf_h[ROWS*DIM];
__device__ __nv_bfloat16 g_lnf_l[ROWS*DIM];
__device__ float  g_qkv[(size_t)ROWS*768];
__device__ float  g_lnq[ROWS*DOUT];
__device__ float  g_pos[(size_t)NROWS*HD];
__device__ __nv_bfloat16 g_mid_h[ROWS*DOUT];
__device__ __nv_bfloat16 g_mid_l[ROWS*DOUT];
__device__ __nv_bfloat16 g_fc1_h[ROWS*DOUT];
__device__ __nv_bfloat16 g_fc1_l[ROWS*DOUT];
__device__ float  g_fc2[ROWS*DOUT];
__device__ __nv_bfloat16 g_wqkvT_h[768*DIM];
__device__ __nv_bfloat16 g_wqkvT_l[768*DIM];
__device__ __nv_bfloat16 g_wp2T_h[HD*HD];
__device__ __nv_bfloat16 g_wf1T_h[DOUT*DOUT];
__device__ __nv_bfloat16 g_wf1T_l[DOUT*DOUT];
__device__ __nv_bfloat16 g_wf2T_h[DOUT*DOUT];
__device__ __nv_bfloat16 g_wf2T_l[DOUT*DOUT];
__device__ float g_bqkv[768];

// ---------------- small helpers ----------------
__device__ __forceinline__ unsigned pk2(float a, float b) {
    __nv_bfloat162 t = __floats2bfloat162_rn(a, b);
    return *(unsigned*)&t;
}
__device__ __forceinline__ float rndbf(float x) {
    return __bfloat162float(__float2bfloat16_rn(x));
}
__device__ __forceinline__ uint32_t smem_u32(const void* p) {
    uint32_t a;
    asm("{ .reg .u64 t; cvta.to.shared.u64 t, %1; cvt.u32.u64 %0, t; }" : "=r"(a) : "l"(p));
    return a;
}
__device__ __forceinline__ uint32_t swz(uint32_t x) { return x ^ ((x >> 3) & 0x70); }

__device__ __forceinline__ void ldsm4(uint32_t* r, uint32_t addr) {
    asm volatile("ldmatrix.sync.aligned.m8n8.x4.shared.b16 {%0,%1,%2,%3}, [%4];"
        : "=r"(r[0]), "=r"(r[1]), "=r"(r[2]), "=r"(r[3]) : "r"(addr));
}
__device__ __forceinline__ void mma16816(float* c, const uint32_t* a, uint32_t b0, uint32_t b1) {
    asm volatile("mma.sync.aligned.m16n8k16.row.col.f32.bf16.bf16.f32 "
        "{%0,%1,%2,%3}, {%4,%5,%6,%7}, {%8,%9}, {%0,%1,%2,%3};"
        : "+f"(c[0]), "+f"(c[1]), "+f"(c[2]), "+f"(c[3])
        : "r"(a[0]), "r"(a[1]), "r"(a[2]), "r"(a[3]), "r"(b0), "r"(b1));
}
#define CP16(dst, src) asm volatile("cp.async.cg.shared.global [%0], [%1], 16;" :: "r"(dst), "l"(src))
#define CP_COMMIT()    asm volatile("cp.async.commit_group;" ::: "memory")
#define CP_WAIT1()     asm volatile("cp.async.wait_group 1;" ::: "memory")

// ---------------- merged prep: pack | feat-split | ln1 | weightT | bias ----------------
// sections by blockIdx.x:
//   [0,128)        pack xyz
//   [128,4224)     cvt_split features
//   [4224,8320)    ln1
//   [8320,8448)    Wq^T   [8448,8576) Wk^T   [8576,8704) Wv^T
//   [8704,8720)    Wp2^T (hi only used later; writes hi+ignored lo)
//   [8720,8976)    Wf1^T  [8976,9232) Wf2^T
//   [9232,9235)    bias pack
#define PREP_BLOCKS 9235

__global__ void __launch_bounds__(256) k_prep(
    const float* __restrict__ xyz, const float* __restrict__ features,
    const float* __restrict__ Wq, const float* __restrict__ Wk, const float* __restrict__ Wv,
    const float* __restrict__ Wp2, const float* __restrict__ Wf1, const float* __restrict__ Wf2,
    const float* __restrict__ g1, const float* __restrict__ b1,
    const float* __restrict__ bq, const float* __restrict__ bk, const float* __restrict__ bv)
{
    int bid = blockIdx.x, tid = threadIdx.x;
    if (bid < 128) {
        int i = bid * 256 + tid;
        float x = xyz[i*3+0], y = xyz[i*3+1], z = xyz[i*3+2];
        g_xyzw[i] = make_float4(x, y, z, x*x + y*y + z*z);
    } else if (bid < 4224) {
        int i = (bid - 128) * 256 + tid;
        float4 v = ((const float4*)features)[i];
        float hx = rndbf(v.x), hy = rndbf(v.y), hz = rndbf(v.z), hw = rndbf(v.w);
        ((uint2*)g_feat_h)[i] = make_uint2(pk2(v.x, v.y), pk2(v.z, v.w));
        ((uint2*)g_feat_l)[i] = make_uint2(pk2(v.x-hx, v.y-hy), pk2(v.z-hz, v.w-hw));
    } else if (bid < 8320) {
        int warp = ((bid - 4224) * 256 + tid) >> 5;
        int lane = tid & 31;
        float4 v = ((const float4*)(features + (size_t)warp * DIM))[lane];
        float s = v.x + v.y + v.z + v.w;
        #pragma unroll
        for (int o = 16; o; o >>= 1) s += __shfl_xor_sync(~0u, s, o);
        float mu = s * (1.f/128.f);
        float dx = v.x-mu, dy = v.y-mu, dz = v.z-mu, dw = v.w-mu;
        float s2 = dx*dx + dy*dy + dz*dz + dw*dw;
        #pragma unroll
        for (int o = 16; o; o >>= 1) s2 += __shfl_xor_sync(~0u, s2, o);
        float rs = rsqrtf(s2 * (1.f/128.f) + 1e-5f);
        float4 gg = ((const float4*)g1)[lane];
        float4 bb = ((const float4*)b1)[lane];
        float rx = dx*rs*gg.x + bb.x, ry = dy*rs*gg.y + bb.y;
        float rz = dz*rs*gg.z + bb.z, rw = dw*rs*gg.w + bb.w;
        float hx = rndbf(rx), hy = rndbf(ry), hz = rndbf(rz), hw = rndbf(rw);
        int idx = warp*32 + lane;
        ((uint2*)g_lnf_h)[idx] = make_uint2(pk2(rx, ry), pk2(rz, rw));
        ((uint2*)g_lnf_l)[idx] = make_uint2(pk2(rx-hx, ry-hy), pk2(rz-hz, rw-hw));
    } else if (bid < 8704) {
        int sec = (bid - 8320) >> 7;           // 0:Wq 1:Wk 2:Wv
        int i = ((bid - 8320) & 127) * 256 + tid;
        const float* W = sec == 0 ? Wq : (sec == 1 ? Wk : Wv);
        int n = i / DIM, k = i % DIM;
        float x = W[(size_t)k * DOUT + n];
        float hx = rndbf(x);
        g_wqkvT_h[sec*256*DIM + i] = __float2bfloat16_rn(x);
        g_wqkvT_l[sec*256*DIM + i] = __float2bfloat16_rn(x - hx);
    } else if (bid < 8720) {
        int i = (bid - 8704) * 256 + tid;
        int n = i / HD, k = i % HD;
        g_wp2T_h[i] = __float2bfloat16_rn(Wp2[(size_t)k * HD + n]);
    } else if (bid < 8976) {
        int i = (bid - 8720) * 256 + tid;
        int n = i / DOUT, k = i % DOUT;
        float x = Wf1[(size_t)k * DOUT + n];
        float hx = rndbf(x);
        g_wf1T_h[i] = __float2bfloat16_rn(x);
        g_wf1T_l[i] = __float2bfloat16_rn(x - hx);
    } else if (bid < 9232) {
        int i = (bid - 8976) * 256 + tid;
        int n = i / DOUT, k = i % DOUT;
        float x = Wf2[(size_t)k * DOUT + n];
        float hx = rndbf(x);
        g_wf2T_h[i] = __float2bfloat16_rn(x);
        g_wf2T_l[i] = __float2bfloat16_rn(x - hx);
    } else {
        int t = (bid - 9232) * 256 + tid;
        if (t < 256)      g_bqkv[t] = bq[t];
        else if (t < 512) g_bqkv[t] = bk[t-256];
        else              g_bqkv[t] = bv[t-512];
    }
}

// ---------------- KNN: warp/query, sample-threshold + collect + 16x argmin ----------------
#define KNN_CAP 256
#define SMEM_KNN (32768 + 16*KNN_CAP*8)

__global__ void __launch_bounds__(512) k_knn2() {
    extern __shared__ char sk[];
    float4* tile = (float4*)sk;
    float*  bkey = (float*)(sk + 32768);
    int*    bidx = (int*)(sk + 32768 + 16*KNN_CAP*4);
    int t = threadIdx.x, lane = t & 31, w = t >> 5;
    int b = blockIdx.y;
    int q = blockIdx.x * 16 + w;
    const float INF = 3.402823e38f;

    float4 me = g_xyzw[b*NPTS + q];
    float qx2 = -2.f*me.x, qy2 = -2.f*me.y, qz2 = -2.f*me.z;

    float T = 0.f;
    int base = 0;
    float* mk = bkey + w*KNN_CAP;
    int*   mi = bidx + w*KNN_CAP;

    for (int ti = 0; ti < 4; ++ti) {
        __syncthreads();
        for (int i = t; i < 2048; i += 512)
            tile[i] = g_xyzw[b*NPTS + ti*2048 + i];
        __syncthreads();

        if (ti == 0) {
            float mn = INF;
            #pragma unroll 8
            for (int i = 0; i < 64; ++i) {
                float4 p = tile[i*32 + lane];
                float d = fmaf(qx2,p.x,fmaf(qy2,p.y,fmaf(qz2,p.z,p.w)));
                mn = fminf(mn, d);
            }
            float v = mn;
            #pragma unroll
            for (int k = 2; k <= 32; k <<= 1) {
                #pragma unroll
                for (int j = k >> 1; j > 0; j >>= 1) {
                    float o = __shfl_xor_sync(~0u, v, j);
                    bool up = ((lane & k) == 0);
                    bool lower = ((lane & j) == 0);
                    v = (lower == up) ? fminf(v, o) : fmaxf(v, o);
                }
            }
            T = __shfl_sync(~0u, v, 15);
        }

        #pragma unroll 4
        for (int c = 0; c < 64; ++c) {
            int j = c*32 + lane;
            float4 p = tile[j];
            float d = fmaf(qx2,p.x,fmaf(qy2,p.y,fmaf(qz2,p.z,p.w)));
            bool pass = (d <= T);
            unsigned m = __ballot_sync(~0u, pass);
            if (pass) {
                int pos = base + __popc(m & ((1u << lane) - 1u));
                if (pos < KNN_CAP) { mk[pos] = d; mi[pos] = ti*2048 + j; }
            }
            base += __popc(m);
        }
    }
    if (base > KNN_CAP) base = KNN_CAP;
    __syncwarp();

    size_t ob = ((size_t)b*NPTS + q) * KNBR;
    for (int r = 0; r < KNBR; ++r) {
        float bk = INF; int bi = 0x7fffffff; int bp = -1;
        for (int i = lane; i < base; i += 32) {
            float kk = mk[i];
            int   ii = mi[i];
            if (kk < bk || (kk == bk && ii < bi)) { bk = kk; bi = ii; bp = i; }
        }
        #pragma unroll
        for (int o = 16; o; o >>= 1) {
            float ok = __shfl_xor_sync(~0u, bk, o);
            int   oi = __shfl_xor_sync(~0u, bi, o);
            int   op = __shfl_xor_sync(~0u, bp, o);
            if (ok < bk || (ok == bk && oi < bi)) { bk = ok; bi = oi; bp = op; }
        }
        if (lane == 0) {
            g_knn[ob + r] = bi;
            if (bp >= 0) mk[bp] = INF;
        }
        __syncwarp();
    }
}

// ---------------- cp.async pipelined mma GEMM (bf16 split x3) ----------------
template<int NT>
__global__ void __launch_bounds__(256) k_mgemm(
    const __nv_bfloat16* __restrict__ Ah, const __nv_bfloat16* __restrict__ Al,
    const __nv_bfloat16* __restrict__ Bh, const __nv_bfloat16* __restrict__ Bl,
    const float* __restrict__ bias,
    float* __restrict__ Cf, __nv_bfloat16* __restrict__ Ch, __nv_bfloat16* __restrict__ Cl,
    int K, int ldc, int relu)
{
    constexpr int WN = NT / 2;
    constexpr int NB = WN / 16;
    constexpr int STGB = 16384 + NT*128;
    extern __shared__ char sm[];
    uint32_t smb = smem_u32(sm);
    int t = threadIdx.x, lane = t & 31, w = t >> 5;
    int wm = w & 3, wn = w >> 2;
    int r0 = blockIdx.x * 128, c0 = blockIdx.y * NT;
    int nch = K >> 5;

    float acc[2][2*NB][4];
    #pragma unroll
    for (int i = 0; i < 2; ++i)
        #pragma unroll
        for (int j = 0; j < 2*NB; ++j)
            #pragma unroll
            for (int e = 0; e < 4; ++e) acc[i][j][e] = 0.f;

    int lrow = lane & 15;
    int lcb  = (lane >> 4) * 16;

    auto issue = [&](int c, int stg) {
        int kc = c * 32;
        uint32_t Ab = smb + stg*STGB;
        uint32_t Bb = Ab + 16384;
        #pragma unroll
        for (int i = 0; i < 4; ++i) {
            int e = t + i*256;
            int row = e >> 3, seg = e & 7;
            const __nv_bfloat16* src = (seg < 4 ? Ah : Al) + (size_t)(r0+row)*K + kc + (seg & 3)*8;
            CP16(Ab + swz((uint32_t)row*128 + seg*16), src);
        }
        #pragma unroll
        for (int i = 0; i < NT/32; ++i) {
            int e = t + i*256;
            int row = e >> 3, seg = e & 7;
            const __nv_bfloat16* src = (seg < 4 ? Bh : Bl) + (size_t)(c0+row)*K + kc + (seg & 3)*8;
            CP16(Bb + swz((uint32_t)row*128 + seg*16), src);
        }
    };

    issue(0, 0); CP_COMMIT();
    issue(1, 1); CP_COMMIT();

    for (int c = 0; c < nch; ++c) {
        CP_WAIT1();
        __syncthreads();
        uint32_t Ab = smb + (c & 1)*STGB;
        uint32_t Bb = Ab + 16384;
        #pragma unroll
        for (int s = 0; s < 2; ++s) {
            int kb = s*32 + lcb;
            uint32_t ah[2][4], al[2][4];
            #pragma unroll
            for (int mb = 0; mb < 2; ++mb) {
                uint32_t ro = (uint32_t)(wm*32 + mb*16 + lrow)*128;
                ldsm4(ah[mb], Ab + swz(ro + kb));
                ldsm4(al[mb], Ab + swz(ro + 64 + kb));
            }
            #pragma unroll
            for (int nb = 0; nb < NB; ++nb) {
                uint32_t bh[4], bl[4];
                uint32_t ro = (uint32_t)(wn*WN + nb*16 + lrow)*128;
                ldsm4(bh, Bb + swz(ro + kb));
                ldsm4(bl, Bb + swz(ro + 64 + kb));
                #pragma unroll
                for (int mb = 0; mb < 2; ++mb) {
                    float* cA = acc[mb][nb*2];
                    float* cB = acc[mb][nb*2+1];
                    mma16816(cA, ah[mb], bh[0], bh[2]);
                    mma16816(cB, ah[mb], bh[1], bh[3]);
                    mma16816(cA, ah[mb], bl[0], bl[2]);
                    mma16816(cB, ah[mb], bl[1], bl[3]);
                    mma16816(cA, al[mb], bh[0], bh[2]);
                    mma16816(cB, al[mb], bh[1], bh[3]);
                }
            }
        }
        __syncthreads();
        if (c + 2 < nch) issue(c + 2, c & 1);
        CP_COMMIT();
    }

    int rbase = r0 + wm*32 + (lane >> 2);
    int cb = c0 + wn*WN + (lane & 3)*2;
    #pragma unroll
    for (int mb = 0; mb < 2; ++mb) {
        #pragma unroll
        for (int nn = 0; nn < 2*NB; ++nn) {
            int col = cb + nn*8;
            float b0 = bias[col], b1 = bias[col+1];
            float v0 = acc[mb][nn][0] + b0, v1 = acc[mb][nn][1] + b1;
            float v2 = acc[mb][nn][2] + b0, v3 = acc[mb][nn][3] + b1;
            if (relu) {
                v0 = fmaxf(v0, 0.f); v1 = fmaxf(v1, 0.f);
                v2 = fmaxf(v2, 0.f); v3 = fmaxf(v3, 0.f);
            }
            size_t ra = (size_t)(rbase + mb*16) * ldc + col;
            size_t rb = (size_t)(rbase + mb*16 + 8) * ldc + col;
            if (Cf) {
                *(float2*)(Cf + ra) = make_float2(v0, v1);
                *(float2*)(Cf + rb) = make_float2(v2, v3);
            }
            if (Ch) {
                float h0 = rndbf(v0), h1 = rndbf(v1), h2 = rndbf(v2), h3 = rndbf(v3);
                *(unsigned*)(Ch + ra) = pk2(v0, v1);
                *(unsigned*)(Cl + ra) = pk2(v0-h0, v1-h1);
                *(unsigned*)(Ch + rb) = pk2(v2, v3);
                *(unsigned*)(Cl + rb) = pk2(v2-h2, v3-h3);
            }
        }
    }
}
#define MG_SMEM(NT) (2 * (16384 + (NT)*128))

// ---------------- fused pos GEMM, single-bf16 (pos is a small additive term) ----------------
#define PG_A 0
#define PG_B 16384
#define SMEM_PG 24576

__global__ void __launch_bounds__(256) k_pgemm(
    const float* __restrict__ xyz, const float* __restrict__ Wp1,
    const float* __restrict__ bp1, const float* __restrict__ bias)
{
    extern __shared__ char sm[];
    uint32_t smb = smem_u32(sm);
    int t = threadIdx.x, lane = t & 31, w = t >> 5;
    int wm = w & 3, wn = w >> 2;
    int r0 = blockIdx.x * 128;

    #pragma unroll 2
    for (int e = t; e < 512; e += 256) {
        int row = e >> 3, vo = e & 7;
        *(uint4*)(sm + PG_B + swz(row*128 + vo*16)) = *(const uint4*)(g_wp2T_h + row*64 + vo*8);
    }

    {
        int row = t >> 1, ch = t & 1;
        int rr = r0 + row;
        int b = rr >> 17, n = (rr >> 4) & (NPTS - 1);
        int idx = g_knn[rr];
        const float* xb = xyz + (size_t)b * NPTS * 3;
        float rx = xb[idx*3+0] - xb[n*3+0];
        float ry = xb[idx*3+1] - xb[n*3+1];
        float rz = xb[idx*3+2] - xb[n*3+2];
        uint32_t hp[16];
        #pragma unroll
        for (int cc = 0; cc < 32; cc += 2) {
            int c = ch*32 + cc;
            float v0 = fmaf(rx, Wp1[c],   fmaf(ry, Wp1[64+c],   fmaf(rz, Wp1[128+c],   bp1[c])));
            float v1 = fmaf(rx, Wp1[c+1], fmaf(ry, Wp1[64+c+1], fmaf(rz, Wp1[128+c+1], bp1[c+1])));
            hp[cc>>1] = pk2(fmaxf(v0, 0.f), fmaxf(v1, 0.f));
        }
        uint32_t rbyte = (uint32_t)row*128 + ch*64;
        #pragma unroll
        for (int i = 0; i < 4; ++i)
            *(uint4*)(sm + PG_A + swz(rbyte + i*16)) = *(uint4*)&hp[i*4];
    }
    __syncthreads();

    float acc[2][4][4];
    #pragma unroll
    for (int i = 0; i < 2; ++i)
        #pragma unroll
        for (int j = 0; j < 4; ++j)
            #pragma unroll
            for (int e = 0; e < 4; ++e) acc[i][j][e] = 0.f;
    int lrow = lane & 15, lcolb = (lane >> 4) * 16;
    #pragma unroll
    for (int s = 0; s < 4; ++s) {
        int kb = s*32 + lcolb;
        uint32_t ah[2][4];
        #pragma unroll
        for (int mb = 0; mb < 2; ++mb)
            ldsm4(ah[mb], smb + PG_A + swz((uint32_t)(wm*32 + mb*16 + lrow)*128 + kb));
        #pragma unroll
        for (int nb = 0; nb < 2; ++nb) {
            uint32_t bh[4];
            ldsm4(bh, smb + PG_B + swz((uint32_t)(wn*32 + nb*16 + lrow)*128 + kb));
            #pragma unroll
            for (int mb = 0; mb < 2; ++mb) {
                mma16816(acc[mb][nb*2],   ah[mb], bh[0], bh[2]);
                mma16816(acc[mb][nb*2+1], ah[mb], bh[1], bh[3]);
            }
        }
    }

    int rbase = r0 + wm*32 + (lane >> 2);
    int cb = wn*32 + (lane & 3)*2;
    #pragma unroll
    for (int mb = 0; mb < 2; ++mb) {
        #pragma unroll
        for (int nn = 0; nn < 4; ++nn) {
            int col = cb + nn*8;
            float b0 = bias[col], b1 = bias[col+1];
            size_t ra = (size_t)(rbase + mb*16) * HD + col;
            size_t rb = (size_t)(rbase + mb*16 + 8) * HD + col;
            *(float2*)(g_pos + ra) = make_float2(acc[mb][nn][0] + b0, acc[mb][nn][1] + b1);
            *(float2*)(g_pos + rb) = make_float2(acc[mb][nn][2] + b0, acc[mb][nn][3] + b1);
        }
    }
}

// ---------------- fused attention ----------------
__global__ void __launch_bounds__(128) k_attn(float* __restrict__ attn_out) {
    __shared__ int   idx_s[16];
    __shared__ float pos_s[16][68];
    __shared__ float k_s[16][260];
    __shared__ float v_s[16][260];
    __shared__ float q_s[256];
    __shared__ float logit_s[64];
    __shared__ float attn_s[64];
    int t  = threadIdx.x;
    int gp = blockIdx.x;
    int b  = gp >> 13, n = gp & (NPTS-1);

    if (t < 16) idx_s[t] = g_knn[gp*KNBR + t];
    if (t < 64) ((float4*)q_s)[t] = ((const float4*)(g_qkv + (size_t)gp * 768))[t];
    {
        const float4* ps = (const float4*)(g_pos + (size_t)gp * KNBR * HD);
        #pragma unroll
        for (int e = t; e < 256; e += 128) {
            int jj = e >> 4, cc = e & 15;
            *(float4*)&pos_s[jj][cc*4] = ps[e];
        }
    }
    __syncthreads();
    #pragma unroll
    for (int e = t; e < 1024; e += 128) {
        int jj = e >> 6, cc = e & 63;
        size_t rowb = ((size_t)b * NPTS + idx_s[jj]) * 768;
        *(float4*)&k_s[jj][cc*4] = *(const float4*)(g_qkv + rowb + 256 + cc*4);
        *(float4*)&v_s[jj][cc*4] = *(const float4*)(g_qkv + rowb + 512 + cc*4);
    }
    __syncthreads();
    {
        int p = t >> 1, half = t & 1;
        int jj = p & 15, h = p >> 4;
        float s = 0.f;
        int cbs = half * 32;
        #pragma unroll
        for (int c = 0; c < 32; ++c) {
            int cc = cbs + c;
            s = fmaf(q_s[h*64+cc], k_s[jj][h*64+cc] + pos_s[jj][cc], s);
        }
        s += __shfl_xor_sync(~0u, s, 1);
        if (half == 0) logit_s[h*16 + jj] = s * 0.125f;
    }
    __syncthreads();
    if (t < 4) {
        int h = t;
        float l[16], mx = -3.402823e38f;
        #pragma unroll
        for (int j = 0; j < 16; ++j) { l[j] = logit_s[h*16+j]; mx = fmaxf(mx, l[j]); }
        float sum = 0.f;
        #pragma unroll
        for (int j = 0; j < 16; ++j) { l[j] = expf(l[j] - mx); sum += l[j]; }
        float inv = 1.f / sum;
        size_t ob = (((size_t)b*NH + h) * NPTS + n) * KNBR;
        #pragma unroll
        for (int j = 0; j < 16; ++j) {
            float a = l[j] * inv;
            attn_s[h*16+j] = a;
            attn_out[ob + j] = a;
        }
    }
    __syncthreads();
    #pragma unroll
    for (int e = t; e < 256; e += 128) {
        int h = e >> 6, c = e & 63;
        float s = 0.f;
        #pragma unroll
        for (int j = 0; j < 16; ++j)
            s = fmaf(attn_s[h*16+j], v_s[j][e] + pos_s[j][c], s);
        float hs = rndbf(s);
        g_mid_h[(size_t)gp * DOUT + e] = __float2bfloat16_rn(s);
        g_mid_l[(size_t)gp * DOUT + e] = __float2bfloat16_rn(s - hs);
    }
}

// ---------------- final: LN(fc2)*g2+b2 + lnq -> out ----------------
__global__ void k_final(const float* __restrict__ g2, const float* __restrict__ b2,
                        float* __restrict__ out) {
    int warp = (blockIdx.x * blockDim.x + threadIdx.x) >> 5;
    int lane = threadIdx.x & 31;
    const float4* row = (const float4*)(g_fc2 + (size_t)warp * DOUT);
    float4 v0 = row[lane*2], v1 = row[lane*2+1];
    float s = v0.x+v0.y+v0.z+v0.w + v1.x+v1.y+v1.z+v1.w;
    #pragma unroll
    for (int o = 16; o; o >>= 1) s += __shfl_xor_sync(~0u, s, o);
    float mu = s * (1.f/256.f);
    float d0x=v0.x-mu, d0y=v0.y-mu, d0z=v0.z-mu, d0w=v0.w-mu;
    float d1x=v1.x-mu, d1y=v1.y-mu, d1z=v1.z-mu, d1w=v1.w-mu;
    float s2 = d0x*d0x+d0y*d0y+d0z*d0z+d0w*d0w + d1x*d1x+d1y*d1y+d1z*d1z+d1w*d1w;
    #pragma unroll
    for (int o = 16; o; o >>= 1) s2 += __shfl_xor_sync(~0u, s2, o);
    float rs = rsqrtf(s2 * (1.f/256.f) + 1e-5f);
    float4 gA = ((const float4*)g2)[lane*2],  gB = ((const float4*)g2)[lane*2+1];
    float4 bA = ((const float4*)b2)[lane*2],  bB = ((const float4*)b2)[lane*2+1];
    const float4* lq = (const float4*)(g_lnq + (size_t)warp * DOUT);
    float4 qA = lq[lane*2], qB = lq[lane*2+1];
    float4 oA, oB;
    oA.x = d0x*rs*gA.x + bA.x + qA.x; oA.y = d0y*rs*gA.y + bA.y + qA.y;
    oA.z = d0z*rs*gA.z + bA.z + qA.z; oA.w = d0w*rs*gA.w + bA.w + qA.w;
    oB.x = d1x*rs*gB.x + bB.x + qB.x; oB.y = d1y*rs*gB.y + bB.y + qB.y;
    oB.z = d1z*rs*gB.z + bB.z + qB.z; oB.w = d1w*rs*gB.w + bB.w + qB.w;
    float4* dst = (float4*)(out + (size_t)warp * DOUT);
    dst[lane*2]   = oA;
    dst[lane*2+1] = oB;
}

// ---------------- host launcher ----------------
extern "C" void kernel_launch(void* const* d_in, const int* in_sizes, int n_in,
                              void* d_out, int out_size) {
    const float* xyz      = (const float*)d_in[0];
    const float* features = (const float*)d_in[1];
    const float* Wq  = (const float*)d_in[2];
    const float* bq  = (const float*)d_in[3];
    const float* Wk  = (const float*)d_in[4];
    const float* bk  = (const float*)d_in[5];
    const float* Wv  = (const float*)d_in[6];
    const float* bv  = (const float*)d_in[7];
    const float* Wp1 = (const float*)d_in[8];
    const float* bp1 = (const float*)d_in[9];
    const float* Wp2 = (const float*)d_in[10];
    const float* bp2 = (const float*)d_in[11];
    const float* Wf1 = (const float*)d_in[12];
    const float* bf1 = (const float*)d_in[13];
    const float* Wf2 = (const float*)d_in[14];
    const float* bf2 = (const float*)d_in[15];
    const float* g1  = (const float*)d_in[16];
    const float* b1  = (const float*)d_in[17];
    const float* g2  = (const float*)d_in[18];
    const float* b2  = (const float*)d_in[19];

    float* out      = (float*)d_out;
    float* attn_out = out + (size_t)ROWS * DOUT;

    #define SYM(p, s) float* p; cudaGetSymbolAddress((void**)&p, s)
    #define SYMB(p, s) __nv_bfloat16* p; cudaGetSymbolAddress((void**)&p, s)
    SYMB(p_feat_h, g_feat_h); SYMB(p_feat_l, g_feat_l);
    SYMB(p_lnf_h,  g_lnf_h);  SYMB(p_lnf_l,  g_lnf_l);
    SYM(p_qkv, g_qkv); SYM(p_lnq, g_lnq); SYM(p_fc2, g_fc2);
    SYMB(p_mid_h, g_mid_h); SYMB(p_mid_l, g_mid_l);
    SYMB(p_fc1_h, g_fc1_h); SYMB(p_fc1_l, g_fc1_l);
    SYMB(p_wqkvT_h, g_wqkvT_h); SYMB(p_wqkvT_l, g_wqkvT_l);
    SYMB(p_wf1T_h, g_wf1T_h);   SYMB(p_wf1T_l, g_wf1T_l);
    SYMB(p_wf2T_h, g_wf2T_h);   SYMB(p_wf2T_l, g_wf2T_l);
    SYM(p_bqkv, g_bqkv);

    static bool attr_done = false;
    if (!attr_done) {
        cudaFuncSetAttribute(k_mgemm<128>, cudaFuncAttributeMaxDynamicSharedMemorySize, MG_SMEM(128));
        cudaFuncSetAttribute(k_knn2,       cudaFuncAttributeMaxDynamicSharedMemorySize, SMEM_KNN);
        attr_done = true;
    }

    // launch 1: merged prep
    k_prep<<<PREP_BLOCKS, 256>>>(xyz, features, Wq, Wk, Wv, Wp2, Wf1, Wf2, g1, b1, bq, bk, bv);
    // launch 2: knn
    {
        dim3 kg(NPTS/16, BATCH);
        k_knn2<<<kg, 512, SMEM_KNN>>>();
    }
    // launch 3: lnq GEMM
    {
        dim3 g(ROWS/128, 2);
        k_mgemm<128><<<g, 256, MG_SMEM(128)>>>(p_lnf_h, p_lnf_l, p_wqkvT_h, p_wqkvT_l,
                                               bq, p_lnq, nullptr, nullptr, DIM, DOUT, 0);
    }
    // launch 4: qkv GEMM (profiler slot)
    {
        dim3 g(ROWS/128, 6);
        k_mgemm<128><<<g, 256, MG_SMEM(128)>>>(p_feat_h, p_feat_l, p_wqkvT_h, p_wqkvT_l,
                                               p_bqkv, p_qkv, nullptr, nullptr, DIM, 768, 0);
    }
    // launch 5: pos (fused h1 + single-bf16 GEMM)
    k_pgemm<<<NROWS/128, 256, SMEM_PG>>>(xyz, Wp1, bp1, bp2);
    // launch 6: attention
    k_attn<<<ROWS, 128>>>(attn_out);
    // launches 7-8: fc1, fc2
    {
        dim3 g(ROWS/128, 2);
        k_mgemm<128><<<g, 256, MG_SMEM(128)>>>(p_mid_h, p_mid_l, p_wf1T_h, p_wf1T_l,
                                               bf1, nullptr, p_fc1_h, p_fc1_l, DOUT, DOUT, 1);
        k_mgemm<128><<<g, 256, MG_SMEM(128)>>>(p_fc1_h, p_fc1_l, p_wf2T_h, p_wf2T_l,
                                               bf2, p_fc2, nullptr, nullptr, DOUT, DOUT, 0);
    }
    // launch 9: final LN + residual
    k_final<<<ROWS/8, 256>>>(g2, b2, out);
}

// round 7
// speedup vs baseline: 1.9085x; 1.0674x over previous
#include <cuda_runtime.h>
#include <cuda_bf16.h>
#include <cstdint>
#include <math.h>

#define BATCH 4
#define NPTS  8192
#define DIM   128
#define DOUT  256
#define NH    4
#define HD    64
#define KNBR  16
#define ROWS  (BATCH*NPTS)          // 32768
#define NROWS (BATCH*NPTS*KNBR)     // 524288

// ---------------- scratch (device globals; no runtime alloc) ----------------
__device__ float4 g_xyzw[ROWS];
__device__ int    g_knn[NROWS];
__device__ __nv_bfloat16 g_feat_h[ROWS*DIM];
__device__ __nv_bfloat16 g_feat_l[ROWS*DIM];
__device__ __nv_bfloat16 g_lnf_h[ROWS*DIM];
__device__ __nv_bfloat16 g_lnf_l[ROWS*DIM];
__device__ float  g_qkv[(size_t)ROWS*768];
__device__ float  g_lnq[ROWS*DOUT];
__device__ __nv_bfloat16 g_posb[(size_t)NROWS*HD];
__device__ __nv_bfloat16 g_mid_h[ROWS*DOUT];
__device__ __nv_bfloat16 g_mid_l[ROWS*DOUT];
__device__ __nv_bfloat16 g_fc1_h[ROWS*DOUT];
__device__ __nv_bfloat16 g_fc1_l[ROWS*DOUT];
__device__ float  g_fc2[ROWS*DOUT];
__device__ __nv_bfloat16 g_wqkvT_h[768*DIM];
__device__ __nv_bfloat16 g_wqkvT_l[768*DIM];
__device__ __nv_bfloat16 g_wp2T_h[HD*HD];
__device__ __nv_bfloat16 g_wf1T_h[DOUT*DOUT];
__device__ __nv_bfloat16 g_wf1T_l[DOUT*DOUT];
__device__ __nv_bfloat16 g_wf2T_h[DOUT*DOUT];
__device__ __nv_bfloat16 g_wf2T_l[DOUT*DOUT];
__device__ float g_bqkv[768];

// ---------------- small helpers ----------------
__device__ __forceinline__ unsigned pk2(float a, float b) {
    __nv_bfloat162 t = __floats2bfloat162_rn(a, b);
    return *(unsigned*)&t;
}
__device__ __forceinline__ float rndbf(float x) {
    return __bfloat162float(__float2bfloat16_rn(x));
}
__device__ __forceinline__ uint32_t smem_u32(const void* p) {
    uint32_t a;
    asm("{ .reg .u64 t; cvta.to.shared.u64 t, %1; cvt.u32.u64 %0, t; }" : "=r"(a) : "l"(p));
    return a;
}
__device__ __forceinline__ uint32_t swz(uint32_t x) { return x ^ ((x >> 3) & 0x70); }

__device__ __forceinline__ void ldsm4(uint32_t* r, uint32_t addr) {
    asm volatile("ldmatrix.sync.aligned.m8n8.x4.shared.b16 {%0,%1,%2,%3}, [%4];"
        : "=r"(r[0]), "=r"(r[1]), "=r"(r[2]), "=r"(r[3]) : "r"(addr));
}
__device__ __forceinline__ void mma16816(float* c, const uint32_t* a, uint32_t b0, uint32_t b1) {
    asm volatile("mma.sync.aligned.m16n8k16.row.col.f32.bf16.bf16.f32 "
        "{%0,%1,%2,%3}, {%4,%5,%6,%7}, {%8,%9}, {%0,%1,%2,%3};"
        : "+f"(c[0]), "+f"(c[1]), "+f"(c[2]), "+f"(c[3])
        : "r"(a[0]), "r"(a[1]), "r"(a[2]), "r"(a[3]), "r"(b0), "r"(b1));
}
#define CP16(dst, src) asm volatile("cp.async.cg.shared.global [%0], [%1], 16;" :: "r"(dst), "l"(src))
#define CP_COMMIT()    asm volatile("cp.async.commit_group;" ::: "memory")
#define CP_WAIT1()     asm volatile("cp.async.wait_group 1;" ::: "memory")

// ---------------- merged prep ----------------
// [0,128) pack | [128,4224) feat-split + ln1 (warp/row) | [4224,4608) WqkvT
// [4608,4624) Wp2T | [4624,4880) Wf1T | [4880,5136) Wf2T | [5136,5139) bias
#define PREP_BLOCKS 5139

__global__ void __launch_bounds__(256) k_prep(
    const float* __restrict__ xyz, const float* __restrict__ features,
    const float* __restrict__ Wq, const float* __restrict__ Wk, const float* __restrict__ Wv,
    const float* __restrict__ Wp2, const float* __restrict__ Wf1, const float* __restrict__ Wf2,
    const float* __restrict__ g1, const float* __restrict__ b1,
    const float* __restrict__ bq, const float* __restrict__ bk, const float* __restrict__ bv)
{
    int bid = blockIdx.x, tid = threadIdx.x;
    if (bid < 128) {
        int i = bid * 256 + tid;
        float x = xyz[i*3+0], y = xyz[i*3+1], z = xyz[i*3+2];
        g_xyzw[i] = make_float4(x, y, z, x*x + y*y + z*z);
    } else if (bid < 4224) {
        int row = (bid - 128) * 8 + (tid >> 5);
        int lane = tid & 31;
        float4 v = ((const float4*)(features + (size_t)row * DIM))[lane];
        int idx = row*32 + lane;
        {
            float hx = rndbf(v.x), hy = rndbf(v.y), hz = rndbf(v.z), hw = rndbf(v.w);
            ((uint2*)g_feat_h)[idx] = make_uint2(pk2(v.x, v.y), pk2(v.z, v.w));
            ((uint2*)g_feat_l)[idx] = make_uint2(pk2(v.x-hx, v.y-hy), pk2(v.z-hz, v.w-hw));
        }
        float s = v.x + v.y + v.z + v.w;
        #pragma unroll
        for (int o = 16; o; o >>= 1) s += __shfl_xor_sync(~0u, s, o);
        float mu = s * (1.f/128.f);
        float dx = v.x-mu, dy = v.y-mu, dz = v.z-mu, dw = v.w-mu;
        float s2 = dx*dx + dy*dy + dz*dz + dw*dw;
        #pragma unroll
        for (int o = 16; o; o >>= 1) s2 += __shfl_xor_sync(~0u, s2, o);
        float rs = rsqrtf(s2 * (1.f/128.f) + 1e-5f);
        float4 gg = ((const float4*)g1)[lane];
        float4 bb = ((const float4*)b1)[lane];
        float rx = dx*rs*gg.x + bb.x, ry = dy*rs*gg.y + bb.y;
        float rz = dz*rs*gg.z + bb.z, rw = dw*rs*gg.w + bb.w;
        float hx = rndbf(rx), hy = rndbf(ry), hz = rndbf(rz), hw = rndbf(rw);
        ((uint2*)g_lnf_h)[idx] = make_uint2(pk2(rx, ry), pk2(rz, rw));
        ((uint2*)g_lnf_l)[idx] = make_uint2(pk2(rx-hx, ry-hy), pk2(rz-hz, rw-hw));
    } else if (bid < 4608) {
        int sec = (bid - 4224) >> 7;
        int i = ((bid - 4224) & 127) * 256 + tid;
        const float* W = sec == 0 ? Wq : (sec == 1 ? Wk : Wv);
        int n = i / DIM, k = i % DIM;
        float x = W[(size_t)k * DOUT + n];
        float hx = rndbf(x);
        g_wqkvT_h[sec*256*DIM + i] = __float2bfloat16_rn(x);
        g_wqkvT_l[sec*256*DIM + i] = __float2bfloat16_rn(x - hx);
    } else if (bid < 4624) {
        int i = (bid - 4608) * 256 + tid;
        int n = i / HD, k = i % HD;
        g_wp2T_h[i] = __float2bfloat16_rn(Wp2[(size_t)k * HD + n]);
    } else if (bid < 4880) {
        int i = (bid - 4624) * 256 + tid;
        int n = i / DOUT, k = i % DOUT;
        float x = Wf1[(size_t)k * DOUT + n];
        float hx = rndbf(x);
        g_wf1T_h[i] = __float2bfloat16_rn(x);
        g_wf1T_l[i] = __float2bfloat16_rn(x - hx);
    } else if (bid < 5136) {
        int i = (bid - 4880) * 256 + tid;
        int n = i / DOUT, k = i % DOUT;
        float x = Wf2[(size_t)k * DOUT + n];
        float hx = rndbf(x);
        g_wf2T_h[i] = __float2bfloat16_rn(x);
        g_wf2T_l[i] = __float2bfloat16_rn(x - hx);
    } else {
        int t = (bid - 5136) * 256 + tid;
        if (t < 256)      g_bqkv[t] = bq[t];
        else if (t < 512) g_bqkv[t] = bk[t-256];
        else              g_bqkv[t] = bv[t-512];
    }
}

// ---------------- KNN ----------------
#define KNN_CAP 256
#define SMEM_KNN (32768 + 16*KNN_CAP*8)

__global__ void __launch_bounds__(512) k_knn2() {
    extern __shared__ char sk[];
    float4* tile = (float4*)sk;
    float*  bkey = (float*)(sk + 32768);
    int*    bidx = (int*)(sk + 32768 + 16*KNN_CAP*4);
    int t = threadIdx.x, lane = t & 31, w = t >> 5;
    int b = blockIdx.y;
    int q = blockIdx.x * 16 + w;
    const float INF = 3.402823e38f;

    float4 me = g_xyzw[b*NPTS + q];
    float qx2 = -2.f*me.x, qy2 = -2.f*me.y, qz2 = -2.f*me.z;

    float T = 0.f;
    int base = 0;
    float* mk = bkey + w*KNN_CAP;
    int*   mi = bidx + w*KNN_CAP;

    for (int ti = 0; ti < 4; ++ti) {
        __syncthreads();
        for (int i = t; i < 2048; i += 512)
            tile[i] = g_xyzw[b*NPTS + ti*2048 + i];
        __syncthreads();

        if (ti == 0) {
            float mn = INF;
            #pragma unroll 8
            for (int i = 0; i < 64; ++i) {
                float4 p = tile[i*32 + lane];
                float d = fmaf(qx2,p.x,fmaf(qy2,p.y,fmaf(qz2,p.z,p.w)));
                mn = fminf(mn, d);
            }
            float v = mn;
            #pragma unroll
            for (int k = 2; k <= 32; k <<= 1) {
                #pragma unroll
                for (int j = k >> 1; j > 0; j >>= 1) {
                    float o = __shfl_xor_sync(~0u, v, j);
                    bool up = ((lane & k) == 0);
                    bool lower = ((lane & j) == 0);
                    v = (lower == up) ? fminf(v, o) : fmaxf(v, o);
                }
            }
            T = __shfl_sync(~0u, v, 15);
        }

        #pragma unroll 4
        for (int c = 0; c < 64; ++c) {
            int j = c*32 + lane;
            float4 p = tile[j];
            float d = fmaf(qx2,p.x,fmaf(qy2,p.y,fmaf(qz2,p.z,p.w)));
            bool pass = (d <= T);
            unsigned m = __ballot_sync(~0u, pass);
            if (pass) {
                int pos = base + __popc(m & ((1u << lane) - 1u));
                if (pos < KNN_CAP) { mk[pos] = d; mi[pos] = ti*2048 + j; }
            }
            base += __popc(m);
        }
    }
    if (base > KNN_CAP) base = KNN_CAP;
    __syncwarp();

    size_t ob = ((size_t)b*NPTS + q) * KNBR;
    for (int r = 0; r < KNBR; ++r) {
        float bk = INF; int bi = 0x7fffffff; int bp = -1;
        for (int i = lane; i < base; i += 32) {
            float kk = mk[i];
            int   ii = mi[i];
            if (kk < bk || (kk == bk && ii < bi)) { bk = kk; bi = ii; bp = i; }
        }
        #pragma unroll
        for (int o = 16; o; o >>= 1) {
            float ok = __shfl_xor_sync(~0u, bk, o);
            int   oi = __shfl_xor_sync(~0u, bi, o);
            int   op = __shfl_xor_sync(~0u, bp, o);
            if (ok < bk || (ok == bk && oi < bi)) { bk = ok; bi = oi; bp = op; }
        }
        if (lane == 0) {
            g_knn[ob + r] = bi;
            if (bp >= 0) mk[bp] = INF;
        }
        __syncwarp();
    }
}

// ---------------- mma GEMM: CTA 128x64, warp 32x32, 2 CTAs/SM, cp.async 2-stage ----------------
// optional merged second problem: blocks bx >= halfx use A2/C2 (ldc2 cols), early-exit c0>=ldc2
#define MG_STGB  24576
#define MG_SMEM  (2*MG_STGB)

__global__ void __launch_bounds__(256, 2) k_mgemm(
    const __nv_bfloat16* __restrict__ Ah, const __nv_bfloat16* __restrict__ Al,
    const __nv_bfloat16* __restrict__ Bh, const __nv_bfloat16* __restrict__ Bl,
    const float* __restrict__ bias,
    float* Cf, __nv_bfloat16* Ch, __nv_bfloat16* Cl,
    int K, int ldc, int relu,
    const __nv_bfloat16* __restrict__ A2h, const __nv_bfloat16* __restrict__ A2l,
    float* C2f, int ldc2, int halfx)
{
    extern __shared__ char sm[];
    uint32_t smb = smem_u32(sm);
    int t = threadIdx.x, lane = t & 31, w = t >> 5;
    int wm = w & 3, wn = w >> 2;
    int bx = blockIdx.x;
    int c0 = blockIdx.y * 64;
    if (A2h != nullptr && bx >= halfx) {
        if (c0 >= ldc2) return;
        Ah = A2h; Al = A2l; Cf = C2f; Ch = nullptr; Cl = nullptr; ldc = ldc2;
        bx -= halfx;
    }
    int r0 = bx * 128;
    int nch = K >> 5;

    float acc[2][4][4];
    #pragma unroll
    for (int i = 0; i < 2; ++i)
        #pragma unroll
        for (int j = 0; j < 4; ++j)
            #pragma unroll
            for (int e = 0; e < 4; ++e) acc[i][j][e] = 0.f;

    int lrow = lane & 15;
    int lcb  = (lane >> 4) * 16;

    auto issue = [&](int c, int stg) {
        int kc = c * 32;
        uint32_t Ab = smb + stg*MG_STGB;
        uint32_t Bb = Ab + 16384;
        #pragma unroll
        for (int i = 0; i < 4; ++i) {
            int e = t + i*256;
            int row = e >> 3, seg = e & 7;
            const __nv_bfloat16* src = (seg < 4 ? Ah : Al) + (size_t)(r0+row)*K + kc + (seg & 3)*8;
            CP16(Ab + swz((uint32_t)row*128 + seg*16), src);
        }
        #pragma unroll
        for (int i = 0; i < 2; ++i) {
            int e = t + i*256;
            int row = e >> 3, seg = e & 7;
            const __nv_bfloat16* src = (seg < 4 ? Bh : Bl) + (size_t)(c0+row)*K + kc + (seg & 3)*8;
            CP16(Bb + swz((uint32_t)row*128 + seg*16), src);
        }
    };

    issue(0, 0); CP_COMMIT();
    issue(1, 1); CP_COMMIT();

    for (int c = 0; c < nch; ++c) {
        CP_WAIT1();
        __syncthreads();
        uint32_t Ab = smb + (c & 1)*MG_STGB;
        uint32_t Bb = Ab + 16384;
        #pragma unroll
        for (int s = 0; s < 2; ++s) {
            int kb = s*32 + lcb;
            uint32_t ah[2][4], al[2][4];
            #pragma unroll
            for (int mb = 0; mb < 2; ++mb) {
                uint32_t ro = (uint32_t)(wm*32 + mb*16 + lrow)*128;
                ldsm4(ah[mb], Ab + swz(ro + kb));
                ldsm4(al[mb], Ab + swz(ro + 64 + kb));
            }
            #pragma unroll
            for (int nb = 0; nb < 2; ++nb) {
                uint32_t bh[4], bl[4];
                uint32_t ro = (uint32_t)(wn*32 + nb*16 + lrow)*128;
                ldsm4(bh, Bb + swz(ro + kb));
                ldsm4(bl, Bb + swz(ro + 64 + kb));
                #pragma unroll
                for (int mb = 0; mb < 2; ++mb) {
                    float* cA = acc[mb][nb*2];
                    float* cB = acc[mb][nb*2+1];
                    mma16816(cA, ah[mb], bh[0], bh[2]);
                    mma16816(cB, ah[mb], bh[1], bh[3]);
                    mma16816(cA, ah[mb], bl[0], bl[2]);
                    mma16816(cB, ah[mb], bl[1], bl[3]);
                    mma16816(cA, al[mb], bh[0], bh[2]);
                    mma16816(cB, al[mb], bh[1], bh[3]);
                }
            }
        }
        __syncthreads();
        if (c + 2 < nch) issue(c + 2, c & 1);
        CP_COMMIT();
    }

    int rbase = r0 + wm*32 + (lane >> 2);
    int cb = c0 + wn*32 + (lane & 3)*2;
    #pragma unroll
    for (int mb = 0; mb < 2; ++mb) {
        #pragma unroll
        for (int nn = 0; nn < 4; ++nn) {
            int col = cb + nn*8;
            float b0 = bias[col], b1 = bias[col+1];
            float v0 = acc[mb][nn][0] + b0, v1 = acc[mb][nn][1] + b1;
            float v2 = acc[mb][nn][2] + b0, v3 = acc[mb][nn][3] + b1;
            if (relu) {
                v0 = fmaxf(v0, 0.f); v1 = fmaxf(v1, 0.f);
                v2 = fmaxf(v2, 0.f); v3 = fmaxf(v3, 0.f);
            }
            size_t ra = (size_t)(rbase + mb*16) * ldc + col;
            size_t rb = (size_t)(rbase + mb*16 + 8) * ldc + col;
            if (Cf) {
                *(float2*)(Cf + ra) = make_float2(v0, v1);
                *(float2*)(Cf + rb) = make_float2(v2, v3);
            }
            if (Ch) {
                float h0 = rndbf(v0), h1 = rndbf(v1), h2 = rndbf(v2), h3 = rndbf(v3);
                *(unsigned*)(Ch + ra) = pk2(v0, v1);
                *(unsigned*)(Cl + ra) = pk2(v0-h0, v1-h1);
                *(unsigned*)(Ch + rb) = pk2(v2, v3);
                *(unsigned*)(Cl + rb) = pk2(v2-h2, v3-h3);
            }
        }
    }
}

// ---------------- fused pos GEMM, single-bf16, bf16 output ----------------
#define PG_A 0
#define PG_B 16384
#define SMEM_PG 24576

__global__ void __launch_bounds__(256) k_pgemm(
    const float* __restrict__ xyz, const float* __restrict__ Wp1,
    const float* __restrict__ bp1, const float* __restrict__ bias)
{
    extern __shared__ char sm[];
    uint32_t smb = smem_u32(sm);
    int t = threadIdx.x, lane = t & 31, w = t >> 5;
    int wm = w & 3, wn = w >> 2;
    int r0 = blockIdx.x * 128;

    #pragma unroll 2
    for (int e = t; e < 512; e += 256) {
        int row = e >> 3, vo = e & 7;
        *(uint4*)(sm + PG_B + swz(row*128 + vo*16)) = *(const uint4*)(g_wp2T_h + row*64 + vo*8);
    }

    {
        int row = t >> 1, ch = t & 1;
        int rr = r0 + row;
        int b = rr >> 17, n = (rr >> 4) & (NPTS - 1);
        int idx = g_knn[rr];
        const float* xb = xyz + (size_t)b * NPTS * 3;
        float rx = xb[idx*3+0] - xb[n*3+0];
        float ry = xb[idx*3+1] - xb[n*3+1];
        float rz = xb[idx*3+2] - xb[n*3+2];
        uint32_t hp[16];
        #pragma unroll
        for (int cc = 0; cc < 32; cc += 2) {
            int c = ch*32 + cc;
            float v0 = fmaf(rx, Wp1[c],   fmaf(ry, Wp1[64+c],   fmaf(rz, Wp1[128+c],   bp1[c])));
            float v1 = fmaf(rx, Wp1[c+1], fmaf(ry, Wp1[64+c+1], fmaf(rz, Wp1[128+c+1], bp1[c+1])));
            hp[cc>>1] = pk2(fmaxf(v0, 0.f), fmaxf(v1, 0.f));
        }
        uint32_t rbyte = (uint32_t)row*128 + ch*64;
        #pragma unroll
        for (int i = 0; i < 4; ++i)
            *(uint4*)(sm + PG_A + swz(rbyte + i*16)) = *(uint4*)&hp[i*4];
    }
    __syncthreads();

    float acc[2][4][4];
    #pragma unroll
    for (int i = 0; i < 2; ++i)
        #pragma unroll
        for (int j = 0; j < 4; ++j)
            #pragma unroll
            for (int e = 0; e < 4; ++e) acc[i][j][e] = 0.f;
    int lrow = lane & 15, lcolb = (lane >> 4) * 16;
    #pragma unroll
    for (int s = 0; s < 4; ++s) {
        int kb = s*32 + lcolb;
        uint32_t ah[2][4];
        #pragma unroll
        for (int mb = 0; mb < 2; ++mb)
            ldsm4(ah[mb], smb + PG_A + swz((uint32_t)(wm*32 + mb*16 + lrow)*128 + kb));
        #pragma unroll
        for (int nb = 0; nb < 2; ++nb) {
            uint32_t bh[4];
            ldsm4(bh, smb + PG_B + swz((uint32_t)(wn*32 + nb*16 + lrow)*128 + kb));
            #pragma unroll
            for (int mb = 0; mb < 2; ++mb) {
                mma16816(acc[mb][nb*2],   ah[mb], bh[0], bh[2]);
                mma16816(acc[mb][nb*2+1], ah[mb], bh[1], bh[3]);
            }
        }
    }

    int rbase = r0 + wm*32 + (lane >> 2);
    int cb = wn*32 + (lane & 3)*2;
    #pragma unroll
    for (int mb = 0; mb < 2; ++mb) {
        #pragma unroll
        for (int nn = 0; nn < 4; ++nn) {
            int col = cb + nn*8;
            float b0 = bias[col], b1 = bias[col+1];
            size_t ra = (size_t)(rbase + mb*16) * HD + col;
            size_t rb = (size_t)(rbase + mb*16 + 8) * HD + col;
            *(unsigned*)(g_posb + ra) = pk2(acc[mb][nn][0] + b0, acc[mb][nn][1] + b1);
            *(unsigned*)(g_posb + rb) = pk2(acc[mb][nn][2] + b0, acc[mb][nn][3] + b1);
        }
    }
}

// ---------------- fused attention (pos in bf16) ----------------
__global__ void __launch_bounds__(128) k_attn(float* __restrict__ attn_out) {
    __shared__ int   idx_s[16];
    __shared__ float pos_s[16][68];
    __shared__ float k_s[16][260];
    __shared__ float v_s[16][260];
    __shared__ float q_s[256];
    __shared__ float logit_s[64];
    __shared__ float attn_s[64];
    int t  = threadIdx.x;
    int gp = blockIdx.x;
    int b  = gp >> 13, n = gp & (NPTS-1);

    if (t < 16) idx_s[t] = g_knn[gp*KNBR + t];
    if (t < 64) ((float4*)q_s)[t] = ((const float4*)(g_qkv + (size_t)gp * 768))[t];
    {
        const uint2* ps = (const uint2*)(g_posb + (size_t)gp * KNBR * HD);
        #pragma unroll
        for (int e = t; e < 256; e += 128) {
            int jj = e >> 4, cc = e & 15;
            uint2 u = ps[e];
            float2 f0 = __bfloat1622float2(*(__nv_bfloat162*)&u.x);
            float2 f1 = __bfloat1622float2(*(__nv_bfloat162*)&u.y);
            *(float4*)&pos_s[jj][cc*4] = make_float4(f0.x, f0.y, f1.x, f1.y);
        }
    }
    __syncthreads();
    #pragma unroll
    for (int e = t; e < 1024; e += 128) {
        int jj = e >> 6, cc = e & 63;
        size_t rowb = ((size_t)b * NPTS + idx_s[jj]) * 768;
        *(float4*)&k_s[jj][cc*4] = *(const float4*)(g_qkv + rowb + 256 + cc*4);
        *(float4*)&v_s[jj][cc*4] = *(const float4*)(g_qkv + rowb + 512 + cc*4);
    }
    __syncthreads();
    {
        int p = t >> 1, half = t & 1;
        int jj = p & 15, h = p >> 4;
        float s = 0.f;
        int cbs = half * 32;
        #pragma unroll
        for (int c = 0; c < 32; ++c) {
            int cc = cbs + c;
            s = fmaf(q_s[h*64+cc], k_s[jj][h*64+cc] + pos_s[jj][cc], s);
        }
        s += __shfl_xor_sync(~0u, s, 1);
        if (half == 0) logit_s[h*16 + jj] = s * 0.125f;
    }
    __syncthreads();
    if (t < 4) {
        int h = t;
        float l[16], mx = -3.402823e38f;
        #pragma unroll
        for (int j = 0; j < 16; ++j) { l[j] = logit_s[h*16+j]; mx = fmaxf(mx, l[j]); }
        float sum = 0.f;
        #pragma unroll
        for (int j = 0; j < 16; ++j) { l[j] = expf(l[j] - mx); sum += l[j]; }
        float inv = 1.f / sum;
        size_t ob = (((size_t)b*NH + h) * NPTS + n) * KNBR;
        #pragma unroll
        for (int j = 0; j < 16; ++j) {
            float a = l[j] * inv;
            attn_s[h*16+j] = a;
            attn_out[ob + j] = a;
        }
    }
    __syncthreads();
    #pragma unroll
    for (int e = t; e < 256; e += 128) {
        int h = e >> 6, c = e & 63;
        float s = 0.f;
        #pragma unroll
        for (int j = 0; j < 16; ++j)
            s = fmaf(attn_s[h*16+j], v_s[j][e] + pos_s[j][c], s);
        float hs = rndbf(s);
        g_mid_h[(size_t)gp * DOUT + e] = __float2bfloat16_rn(s);
        g_mid_l[(size_t)gp * DOUT + e] = __float2bfloat16_rn(s - hs);
    }
}

// ---------------- final: LN(fc2)*g2+b2 + lnq -> out ----------------
__global__ void k_final(const float* __restrict__ g2, const float* __restrict__ b2,
                        float* __restrict__ out) {
    int warp = (blockIdx.x * blockDim.x + threadIdx.x) >> 5;
    int lane = threadIdx.x & 31;
    const float4* row = (const float4*)(g_fc2 + (size_t)warp * DOUT);
    float4 v0 = row[lane*2], v1 = row[lane*2+1];
    float s = v0.x+v0.y+v0.z+v0.w + v1.x+v1.y+v1.z+v1.w;
    #pragma unroll
    for (int o = 16; o; o >>= 1) s += __shfl_xor_sync(~0u, s, o);
    float mu = s * (1.f/256.f);
    float d0x=v0.x-mu, d0y=v0.y-mu, d0z=v0.z-mu, d0w=v0.w-mu;
    float d1x=v1.x-mu, d1y=v1.y-mu, d1z=v1.z-mu, d1w=v1.w-mu;
    float s2 = d0x*d0x+d0y*d0y+d0z*d0z+d0w*d0w + d1x*d1x+d1y*d1y+d1z*d1z+d1w*d1w;
    #pragma unroll
    for (int o = 16; o; o >>= 1) s2 += __shfl_xor_sync(~0u, s2, o);
    float rs = rsqrtf(s2 * (1.f/256.f) + 1e-5f);
    float4 gA = ((const float4*)g2)[lane*2],  gB = ((const float4*)g2)[lane*2+1];
    float4 bA = ((const float4*)b2)[lane*2],  bB = ((const float4*)b2)[lane*2+1];
    const float4* lq = (const float4*)(g_lnq + (size_t)warp * DOUT);
    float4 qA = lq[lane*2], qB = lq[lane*2+1];
    float4 oA, oB;
    oA.x = d0x*rs*gA.x + bA.x + qA.x; oA.y = d0y*rs*gA.y + bA.y + qA.y;
    oA.z = d0z*rs*gA.z + bA.z + qA.z; oA.w = d0w*rs*gA.w + bA.w + qA.w;
    oB.x = d1x*rs*gB.x + bB.x + qB.x; oB.y = d1y*rs*gB.y + bB.y + qB.y;
    oB.z = d1z*rs*gB.z + bB.z + qB.z; oB.w = d1w*rs*gB.w + bB.w + qB.w;
    float4* dst = (float4*)(out + (size_t)warp * DOUT);
    dst[lane*2]   = oA;
    dst[lane*2+1] = oB;
}

// ---------------- host launcher ----------------
extern "C" void kernel_launch(void* const* d_in, const int* in_sizes, int n_in,
                              void* d_out, int out_size) {
    const float* xyz      = (const float*)d_in[0];
    const float* features = (const float*)d_in[1];
    const float* Wq  = (const float*)d_in[2];
    const float* bq  = (const float*)d_in[3];
    const float* Wk  = (const float*)d_in[4];
    const float* bk  = (const float*)d_in[5];
    const float* Wv  = (const float*)d_in[6];
    const float* bv  = (const float*)d_in[7];
    const float* Wp1 = (const float*)d_in[8];
    const float* bp1 = (const float*)d_in[9];
    const float* Wp2 = (const float*)d_in[10];
    const float* bp2 = (const float*)d_in[11];
    const float* Wf1 = (const float*)d_in[12];
    const float* bf1 = (const float*)d_in[13];
    const float* Wf2 = (const float*)d_in[14];
    const float* bf2 = (const float*)d_in[15];
    const float* g1  = (const float*)d_in[16];
    const float* b1  = (const float*)d_in[17];
    const float* g2  = (const float*)d_in[18];
    const float* b2  = (const float*)d_in[19];

    float* out      = (float*)d_out;
    float* attn_out = out + (size_t)ROWS * DOUT;

    #define SYM(p, s) float* p; cudaGetSymbolAddress((void**)&p, s)
    #define SYMB(p, s) __nv_bfloat16* p; cudaGetSymbolAddress((void**)&p, s)
    SYMB(p_feat_h, g_feat_h); SYMB(p_feat_l, g_feat_l);
    SYMB(p_lnf_h,  g_lnf_h);  SYMB(p_lnf_l,  g_lnf_l);
    SYM(p_qkv, g_qkv); SYM(p_lnq, g_lnq); SYM(p_fc2, g_fc2);
    SYMB(p_mid_h, g_mid_h); SYMB(p_mid_l, g_mid_l);
    SYMB(p_fc1_h, g_fc1_h); SYMB(p_fc1_l, g_fc1_l);
    SYMB(p_wqkvT_h, g_wqkvT_h); SYMB(p_wqkvT_l, g_wqkvT_l);
    SYMB(p_wf1T_h, g_wf1T_h);   SYMB(p_wf1T_l, g_wf1T_l);
    SYMB(p_wf2T_h, g_wf2T_h);   SYMB(p_wf2T_l, g_wf2T_l);
    SYM(p_bqkv, g_bqkv);

    static bool attr_done = false;
    if (!attr_done) {
        cudaFuncSetAttribute(k_mgemm, cudaFuncAttributeMaxDynamicSharedMemorySize, MG_SMEM);
        cudaFuncSetAttribute(k_knn2,  cudaFuncAttributeMaxDynamicSharedMemorySize, SMEM_KNN);
        attr_done = true;
    }

    // 1: merged prep
    k_prep<<<PREP_BLOCKS, 256>>>(xyz, features, Wq, Wk, Wv, Wp2, Wf1, Wf2, g1, b1, bq, bk, bv);
    // 2: knn
    {
        dim3 kg(NPTS/16, BATCH);
        k_knn2<<<kg, 512, SMEM_KNN>>>();
    }
    // 3: qkv + lnq merged (M-concat; second half early-exits for c0>=256)
    {
        dim3 g(ROWS/128 * 2, 12);
        k_mgemm<<<g, 256, MG_SMEM>>>(p_feat_h, p_feat_l, p_wqkvT_h, p_wqkvT_l,
                                     p_bqkv, p_qkv, nullptr, nullptr, DIM, 768, 0,
                                     p_lnf_h, p_lnf_l, p_lnq, DOUT, ROWS/128);
    }
    // 4: pos (fused h1 + single-bf16 GEMM)  <- profiler slot
    k_pgemm<<<NROWS/128, 256, SMEM_PG>>>(xyz, Wp1, bp1, bp2);
    // 5: attention
    k_attn<<<ROWS, 128>>>(attn_out);
    // 6-7: fc1, fc2
    {
        dim3 g(ROWS/128, 4);
        k_mgemm<<<g, 256, MG_SMEM>>>(p_mid_h, p_mid_l, p_wf1T_h, p_wf1T_l,
                                     bf1, nullptr, p_fc1_h, p_fc1_l, DOUT, DOUT, 1,
                                     nullptr, nullptr, nullptr, 0, 0);
        k_mgemm<<<g, 256, MG_SMEM>>>(p_fc1_h, p_fc1_l, p_wf2T_h, p_wf2T_l,
                                     bf2, p_fc2, nullptr, nullptr, DOUT, DOUT, 0,
                                     nullptr, nullptr, nullptr, 0, 0);
    }
    // 8: final LN + residual
    k_final<<<ROWS/8, 256>>>(g2, b2, out);
}

// round 8
// speedup vs baseline: 1.9879x; 1.0416x over previous
#include <cuda_runtime.h>
#include <cuda_bf16.h>
#include <cstdint>
#include <math.h>

#define BATCH 4
#define NPTS  8192
#define DIM   128
#define DOUT  256
#define NH    4
#define HD    64
#define KNBR  16
#define ROWS  (BATCH*NPTS)          // 32768
#define NROWS (BATCH*NPTS*KNBR)     // 524288

// ---------------- scratch (device globals; no runtime alloc) ----------------
__device__ float4 g_xyzw[ROWS];
__device__ int    g_knn[NROWS];
__device__ __nv_bfloat16 g_feat_h[ROWS*DIM];
__device__ __nv_bfloat16 g_feat_l[ROWS*DIM];
__device__ __nv_bfloat16 g_lnf_h[ROWS*DIM];
__device__ __nv_bfloat16 g_lnf_l[ROWS*DIM];
__device__ float  g_qkv[(size_t)ROWS*768];
__device__ float  g_lnq[ROWS*DOUT];
__device__ __nv_bfloat16 g_posb[(size_t)NROWS*HD];
__device__ __nv_bfloat16 g_mid_h[ROWS*DOUT];
__device__ __nv_bfloat16 g_mid_l[ROWS*DOUT];
__device__ __nv_bfloat16 g_fc1_h[ROWS*DOUT];
__device__ __nv_bfloat16 g_fc1_l[ROWS*DOUT];
__device__ float  g_fc2[ROWS*DOUT];
__device__ __nv_bfloat16 g_wqkvT_h[768*DIM];
__device__ __nv_bfloat16 g_wqkvT_l[768*DIM];
__device__ __nv_bfloat16 g_wp2T_h[HD*HD];
__device__ __nv_bfloat16 g_wf1T_h[DOUT*DOUT];
__device__ __nv_bfloat16 g_wf1T_l[DOUT*DOUT];
__device__ __nv_bfloat16 g_wf2T_h[DOUT*DOUT];
__device__ __nv_bfloat16 g_wf2T_l[DOUT*DOUT];
__device__ float g_bqkv[768];

// ---------------- small helpers ----------------
__device__ __forceinline__ unsigned pk2(float a, float b) {
    __nv_bfloat162 t = __floats2bfloat162_rn(a, b);
    return *(unsigned*)&t;
}
__device__ __forceinline__ float rndbf(float x) {
    return __bfloat162float(__float2bfloat16_rn(x));
}
__device__ __forceinline__ uint32_t smem_u32(const void* p) {
    uint32_t a;
    asm("{ .reg .u64 t; cvta.to.shared.u64 t, %1; cvt.u32.u64 %0, t; }" : "=r"(a) : "l"(p));
    return a;
}
__device__ __forceinline__ uint32_t swz(uint32_t x) { return x ^ ((x >> 3) & 0x70); }

__device__ __forceinline__ void ldsm4(uint32_t* r, uint32_t addr) {
    asm volatile("ldmatrix.sync.aligned.m8n8.x4.shared.b16 {%0,%1,%2,%3}, [%4];"
        : "=r"(r[0]), "=r"(r[1]), "=r"(r[2]), "=r"(r[3]) : "r"(addr));
}
__device__ __forceinline__ void mma16816(float* c, const uint32_t* a, uint32_t b0, uint32_t b1) {
    asm volatile("mma.sync.aligned.m16n8k16.row.col.f32.bf16.bf16.f32 "
        "{%0,%1,%2,%3}, {%4,%5,%6,%7}, {%8,%9}, {%0,%1,%2,%3};"
        : "+f"(c[0]), "+f"(c[1]), "+f"(c[2]), "+f"(c[3])
        : "r"(a[0]), "r"(a[1]), "r"(a[2]), "r"(a[3]), "r"(b0), "r"(b1));
}
#define CP16(dst, src) asm volatile("cp.async.cg.shared.global [%0], [%1], 16;" :: "r"(dst), "l"(src))
#define CP_COMMIT()    asm volatile("cp.async.commit_group;" ::: "memory")
#define CP_WAIT1()     asm volatile("cp.async.wait_group 1;" ::: "memory")

// ---------------- merged prep ----------------
// [0,128) pack | [128,4224) feat-split + ln1 | [4224,4248) WqkvT tiles
// [4248,4249) Wp2T | [4249,4265) Wf1T | [4265,4281) Wf2T | [4281,4284) bias
#define PREP_BLOCKS 4284

__device__ __forceinline__ void tileT(const float* __restrict__ W,
                                      __nv_bfloat16* Th, __nv_bfloat16* Tl,
                                      int Kd, int Nd, int k0, int n0,
                                      int tid, float (*ts)[65]) {
    #pragma unroll
    for (int i = 0; i < 16; ++i) {
        int e = tid + i*256;
        int r = e >> 6, c = e & 63;
        ts[r][c] = W[(size_t)(k0 + r) * Nd + n0 + c];
    }
    __syncthreads();
    #pragma unroll
    for (int i = 0; i < 16; ++i) {
        int e = tid + i*256;
        int kk = e & 63, nn = e >> 6;
        float x = ts[kk][nn];
        size_t o = (size_t)(n0 + nn) * Kd + k0 + kk;
        float hx = rndbf(x);
        Th[o] = __float2bfloat16_rn(x);
        if (Tl) Tl[o] = __float2bfloat16_rn(x - hx);
    }
}

__global__ void __launch_bounds__(256) k_prep(
    const float* __restrict__ xyz, const float* __restrict__ features,
    const float* __restrict__ Wq, const float* __restrict__ Wk, const float* __restrict__ Wv,
    const float* __restrict__ Wp2, const float* __restrict__ Wf1, const float* __restrict__ Wf2,
    const float* __restrict__ g1, const float* __restrict__ b1,
    const float* __restrict__ bq, const float* __restrict__ bk, const float* __restrict__ bv)
{
    __shared__ float ts[64][65];
    int bid = blockIdx.x, tid = threadIdx.x;
    if (bid < 128) {
        int i = bid * 256 + tid;
        float x = xyz[i*3+0], y = xyz[i*3+1], z = xyz[i*3+2];
        g_xyzw[i] = make_float4(x, y, z, x*x + y*y + z*z);
    } else if (bid < 4224) {
        int row = (bid - 128) * 8 + (tid >> 5);
        int lane = tid & 31;
        float4 v = ((const float4*)(features + (size_t)row * DIM))[lane];
        int idx = row*32 + lane;
        {
            float hx = rndbf(v.x), hy = rndbf(v.y), hz = rndbf(v.z), hw = rndbf(v.w);
            ((uint2*)g_feat_h)[idx] = make_uint2(pk2(v.x, v.y), pk2(v.z, v.w));
            ((uint2*)g_feat_l)[idx] = make_uint2(pk2(v.x-hx, v.y-hy), pk2(v.z-hz, v.w-hw));
        }
        float s = v.x + v.y + v.z + v.w;
        #pragma unroll
        for (int o = 16; o; o >>= 1) s += __shfl_xor_sync(~0u, s, o);
        float mu = s * (1.f/128.f);
        float dx = v.x-mu, dy = v.y-mu, dz = v.z-mu, dw = v.w-mu;
        float s2 = dx*dx + dy*dy + dz*dz + dw*dw;
        #pragma unroll
        for (int o = 16; o; o >>= 1) s2 += __shfl_xor_sync(~0u, s2, o);
        float rs = rsqrtf(s2 * (1.f/128.f) + 1e-5f);
        float4 gg = ((const float4*)g1)[lane];
        float4 bb = ((const float4*)b1)[lane];
        float rx = dx*rs*gg.x + bb.x, ry = dy*rs*gg.y + bb.y;
        float rz = dz*rs*gg.z + bb.z, rw = dw*rs*gg.w + bb.w;
        float hx = rndbf(rx), hy = rndbf(ry), hz = rndbf(rz), hw = rndbf(rw);
        ((uint2*)g_lnf_h)[idx] = make_uint2(pk2(rx, ry), pk2(rz, rw));
        ((uint2*)g_lnf_l)[idx] = make_uint2(pk2(rx-hx, ry-hy), pk2(rz-hz, rw-hw));
    } else if (bid < 4248) {
        int b2 = bid - 4224;
        int m = b2 >> 3, tt = b2 & 7;
        const float* W = m == 0 ? Wq : (m == 1 ? Wk : Wv);
        tileT(W, g_wqkvT_h + m*256*DIM, g_wqkvT_l + m*256*DIM,
              DIM, DOUT, (tt & 1)*64, (tt >> 1)*64, tid, ts);
    } else if (bid < 4249) {
        tileT(Wp2, g_wp2T_h, nullptr, HD, HD, 0, 0, tid, ts);
    } else if (bid < 4265) {
        int b2 = bid - 4249;
        tileT(Wf1, g_wf1T_h, g_wf1T_l, DOUT, DOUT, (b2 & 3)*64, (b2 >> 2)*64, tid, ts);
    } else if (bid < 4281) {
        int b2 = bid - 4265;
        tileT(Wf2, g_wf2T_h, g_wf2T_l, DOUT, DOUT, (b2 & 3)*64, (b2 >> 2)*64, tid, ts);
    } else {
        int t = (bid - 4281) * 256 + tid;
        if (t < 256)      g_bqkv[t] = bq[t];
        else if (t < 512) g_bqkv[t] = bk[t-256];
        else              g_bqkv[t] = bv[t-512];
    }
}

// ---------------- KNN ----------------
#define KNN_CAP 256
#define SMEM_KNN (32768 + 16*KNN_CAP*8)

__global__ void __launch_bounds__(512) k_knn2() {
    extern __shared__ char sk[];
    float4* tile = (float4*)sk;
    float*  bkey = (float*)(sk + 32768);
    int*    bidx = (int*)(sk + 32768 + 16*KNN_CAP*4);
    int t = threadIdx.x, lane = t & 31, w = t >> 5;
    int b = blockIdx.y;
    int q = blockIdx.x * 16 + w;
    const float INF = 3.402823e38f;

    float4 me = g_xyzw[b*NPTS + q];
    float qx2 = -2.f*me.x, qy2 = -2.f*me.y, qz2 = -2.f*me.z;

    float T = 0.f;
    int base = 0;
    float* mk = bkey + w*KNN_CAP;
    int*   mi = bidx + w*KNN_CAP;

    for (int ti = 0; ti < 4; ++ti) {
        __syncthreads();
        for (int i = t; i < 2048; i += 512)
            tile[i] = g_xyzw[b*NPTS + ti*2048 + i];
        __syncthreads();

        if (ti == 0) {
            float mn = INF;
            #pragma unroll 8
            for (int i = 0; i < 64; ++i) {
                float4 p = tile[i*32 + lane];
                float d = fmaf(qx2,p.x,fmaf(qy2,p.y,fmaf(qz2,p.z,p.w)));
                mn = fminf(mn, d);
            }
            float v = mn;
            #pragma unroll
            for (int k = 2; k <= 32; k <<= 1) {
                #pragma unroll
                for (int j = k >> 1; j > 0; j >>= 1) {
                    float o = __shfl_xor_sync(~0u, v, j);
                    bool up = ((lane & k) == 0);
                    bool lower = ((lane & j) == 0);
                    v = (lower == up) ? fminf(v, o) : fmaxf(v, o);
                }
            }
            T = __shfl_sync(~0u, v, 15);
        }

        #pragma unroll 4
        for (int c = 0; c < 64; ++c) {
            int j = c*32 + lane;
            float4 p = tile[j];
            float d = fmaf(qx2,p.x,fmaf(qy2,p.y,fmaf(qz2,p.z,p.w)));
            bool pass = (d <= T);
            unsigned m = __ballot_sync(~0u, pass);
            if (pass) {
                int pos = base + __popc(m & ((1u << lane) - 1u));
                if (pos < KNN_CAP) { mk[pos] = d; mi[pos] = ti*2048 + j; }
            }
            base += __popc(m);
        }
    }
    if (base > KNN_CAP) base = KNN_CAP;
    __syncwarp();

    size_t ob = ((size_t)b*NPTS + q) * KNBR;
    for (int r = 0; r < KNBR; ++r) {
        float bk = INF; int bi = 0x7fffffff; int bp = -1;
        for (int i = lane; i < base; i += 32) {
            float kk = mk[i];
            int   ii = mi[i];
            if (kk < bk || (kk == bk && ii < bi)) { bk = kk; bi = ii; bp = i; }
        }
        #pragma unroll
        for (int o = 16; o; o >>= 1) {
            float ok = __shfl_xor_sync(~0u, bk, o);
            int   oi = __shfl_xor_sync(~0u, bi, o);
            int   op = __shfl_xor_sync(~0u, bp, o);
            if (ok < bk || (ok == bk && oi < bi)) { bk = ok; bi = oi; bp = op; }
        }
        if (lane == 0) {
            g_knn[ob + r] = bi;
            if (bp >= 0) mk[bp] = INF;
        }
        __syncwarp();
    }
}

// ---------------- mma GEMM: CTA 128x64, warp 32x32, 2 CTAs/SM, cp.async 2-stage ----------------
#define MG_STGB  24576
#define MG_SMEM  (2*MG_STGB)

__global__ void __launch_bounds__(256, 2) k_mgemm(
    const __nv_bfloat16* __restrict__ Ah, const __nv_bfloat16* __restrict__ Al,
    const __nv_bfloat16* __restrict__ Bh, const __nv_bfloat16* __restrict__ Bl,
    const float* __restrict__ bias,
    float* Cf, __nv_bfloat16* Ch, __nv_bfloat16* Cl,
    int K, int ldc, int relu,
    const __nv_bfloat16* __restrict__ A2h, const __nv_bfloat16* __restrict__ A2l,
    float* C2f, int ldc2, int halfx)
{
    extern __shared__ char sm[];
    uint32_t smb = smem_u32(sm);
    int t = threadIdx.x, lane = t & 31, w = t >> 5;
    int wm = w & 3, wn = w >> 2;
    int bx = blockIdx.x;
    int c0 = blockIdx.y * 64;
    if (A2h != nullptr && bx >= halfx) {
        if (c0 >= ldc2) return;
        Ah = A2h; Al = A2l; Cf = C2f; Ch = nullptr; Cl = nullptr; ldc = ldc2;
        bx -= halfx;
    }
    int r0 = bx * 128;
    int nch = K >> 5;

    float acc[2][4][4];
    #pragma unroll
    for (int i = 0; i < 2; ++i)
        #pragma unroll
        for (int j = 0; j < 4; ++j)
            #pragma unroll
            for (int e = 0; e < 4; ++e) acc[i][j][e] = 0.f;

    int lrow = lane & 15;
    int lcb  = (lane >> 4) * 16;

    auto issue = [&](int c, int stg) {
        int kc = c * 32;
        uint32_t Ab = smb + stg*MG_STGB;
        uint32_t Bb = Ab + 16384;
        #pragma unroll
        for (int i = 0; i < 4; ++i) {
            int e = t + i*256;
            int row = e >> 3, seg = e & 7;
            const __nv_bfloat16* src = (seg < 4 ? Ah : Al) + (size_t)(r0+row)*K + kc + (seg & 3)*8;
            CP16(Ab + swz((uint32_t)row*128 + seg*16), src);
        }
        #pragma unroll
        for (int i = 0; i < 2; ++i) {
            int e = t + i*256;
            int row = e >> 3, seg = e & 7;
            const __nv_bfloat16* src = (seg < 4 ? Bh : Bl) + (size_t)(c0+row)*K + kc + (seg & 3)*8;
            CP16(Bb + swz((uint32_t)row*128 + seg*16), src);
        }
    };

    issue(0, 0); CP_COMMIT();
    issue(1, 1); CP_COMMIT();

    for (int c = 0; c < nch; ++c) {
        CP_WAIT1();
        __syncthreads();
        uint32_t Ab = smb + (c & 1)*MG_STGB;
        uint32_t Bb = Ab + 16384;
        #pragma unroll
        for (int s = 0; s < 2; ++s) {
            int kb = s*32 + lcb;
            uint32_t ah[2][4], al[2][4];
            #pragma unroll
            for (int mb = 0; mb < 2; ++mb) {
                uint32_t ro = (uint32_t)(wm*32 + mb*16 + lrow)*128;
                ldsm4(ah[mb], Ab + swz(ro + kb));
                ldsm4(al[mb], Ab + swz(ro + 64 + kb));
            }
            #pragma unroll
            for (int nb = 0; nb < 2; ++nb) {
                uint32_t bh[4], bl[4];
                uint32_t ro = (uint32_t)(wn*32 + nb*16 + lrow)*128;
                ldsm4(bh, Bb + swz(ro + kb));
                ldsm4(bl, Bb + swz(ro + 64 + kb));
                #pragma unroll
                for (int mb = 0; mb < 2; ++mb) {
                    float* cA = acc[mb][nb*2];
                    float* cB = acc[mb][nb*2+1];
                    mma16816(cA, ah[mb], bh[0], bh[2]);
                    mma16816(cB, ah[mb], bh[1], bh[3]);
                    mma16816(cA, ah[mb], bl[0], bl[2]);
                    mma16816(cB, ah[mb], bl[1], bl[3]);
                    mma16816(cA, al[mb], bh[0], bh[2]);
                    mma16816(cB, al[mb], bh[1], bh[3]);
                }
            }
        }
        __syncthreads();
        if (c + 2 < nch) issue(c + 2, c & 1);
        CP_COMMIT();
    }

    int rbase = r0 + wm*32 + (lane >> 2);
    int cb = c0 + wn*32 + (lane & 3)*2;
    #pragma unroll
    for (int mb = 0; mb < 2; ++mb) {
        #pragma unroll
        for (int nn = 0; nn < 4; ++nn) {
            int col = cb + nn*8;
            float b0 = bias[col], b1 = bias[col+1];
            float v0 = acc[mb][nn][0] + b0, v1 = acc[mb][nn][1] + b1;
            float v2 = acc[mb][nn][2] + b0, v3 = acc[mb][nn][3] + b1;
            if (relu) {
                v0 = fmaxf(v0, 0.f); v1 = fmaxf(v1, 0.f);
                v2 = fmaxf(v2, 0.f); v3 = fmaxf(v3, 0.f);
            }
            size_t ra = (size_t)(rbase + mb*16) * ldc + col;
            size_t rb = (size_t)(rbase + mb*16 + 8) * ldc + col;
            if (Cf) {
                *(float2*)(Cf + ra) = make_float2(v0, v1);
                *(float2*)(Cf + rb) = make_float2(v2, v3);
            }
            if (Ch) {
                float h0 = rndbf(v0), h1 = rndbf(v1), h2 = rndbf(v2), h3 = rndbf(v3);
                *(unsigned*)(Ch + ra) = pk2(v0, v1);
                *(unsigned*)(Cl + ra) = pk2(v0-h0, v1-h1);
                *(unsigned*)(Ch + rb) = pk2(v2, v3);
                *(unsigned*)(Cl + rb) = pk2(v2-h2, v3-h3);
            }
        }
    }
}

// ---------------- fused pos GEMM: smem Wp1, float4 xyzw, bf16 out ----------------
#define PG_A 0
#define PG_B 16384
#define PG_W 24576
#define SMEM_PG (24576 + 1024)

__global__ void __launch_bounds__(256) k_pgemm(
    const float* __restrict__ Wp1, const float* __restrict__ bp1,
    const float* __restrict__ bias)
{
    extern __shared__ char sm[];
    uint32_t smb = smem_u32(sm);
    float* ws = (float*)(sm + PG_W);       // [192] Wp1 + [64] bp1
    int t = threadIdx.x, lane = t & 31, w = t >> 5;
    int wm = w & 3, wn = w >> 2;
    int r0 = blockIdx.x * 128;

    if (t < 192) ws[t] = Wp1[t];
    else ws[t] = bp1[t - 192];
    #pragma unroll 2
    for (int e = t; e < 512; e += 256) {
        int row = e >> 3, vo = e & 7;
        *(uint4*)(sm + PG_B + swz(row*128 + vo*16)) = *(const uint4*)(g_wp2T_h + row*64 + vo*8);
    }
    __syncthreads();

    {
        int row = t >> 1, ch = t & 1;
        int rr = r0 + row;
        int b = rr >> 17, n = (rr >> 4) & (NPTS - 1);
        int idx = g_knn[rr];
        float4 nbp = g_xyzw[(b << 13) + idx];
        float4 ctp = g_xyzw[(b << 13) + n];
        float rx = nbp.x - ctp.x, ry = nbp.y - ctp.y, rz = nbp.z - ctp.z;
        uint32_t hp[16];
        #pragma unroll
        for (int cc = 0; cc < 32; cc += 2) {
            int c = ch*32 + cc;
            float v0 = fmaf(rx, ws[c],   fmaf(ry, ws[64+c],   fmaf(rz, ws[128+c],   ws[192+c])));
            float v1 = fmaf(rx, ws[c+1], fmaf(ry, ws[64+c+1], fmaf(rz, ws[128+c+1], ws[192+c+1])));
            hp[cc>>1] = pk2(fmaxf(v0, 0.f), fmaxf(v1, 0.f));
        }
        uint32_t rbyte = (uint32_t)row*128 + ch*64;
        #pragma unroll
        for (int i = 0; i < 4; ++i)
            *(uint4*)(sm + PG_A + swz(rbyte + i*16)) = *(uint4*)&hp[i*4];
    }
    __syncthreads();

    float acc[2][4][4];
    #pragma unroll
    for (int i = 0; i < 2; ++i)
        #pragma unroll
        for (int j = 0; j < 4; ++j)
            #pragma unroll
            for (int e = 0; e < 4; ++e) acc[i][j][e] = 0.f;
    int lrow = lane & 15, lcolb = (lane >> 4) * 16;
    #pragma unroll
    for (int s = 0; s < 4; ++s) {
        int kb = s*32 + lcolb;
        uint32_t ah[2][4];
        #pragma unroll
        for (int mb = 0; mb < 2; ++mb)
            ldsm4(ah[mb], smb + PG_A + swz((uint32_t)(wm*32 + mb*16 + lrow)*128 + kb));
        #pragma unroll
        for (int nb = 0; nb < 2; ++nb) {
            uint32_t bh[4];
            ldsm4(bh, smb + PG_B + swz((uint32_t)(wn*32 + nb*16 + lrow)*128 + kb));
            #pragma unroll
            for (int mb = 0; mb < 2; ++mb) {
                mma16816(acc[mb][nb*2],   ah[mb], bh[0], bh[2]);
                mma16816(acc[mb][nb*2+1], ah[mb], bh[1], bh[3]);
            }
        }
    }

    int rbase = r0 + wm*32 + (lane >> 2);
    int cb = wn*32 + (lane & 3)*2;
    #pragma unroll
    for (int mb = 0; mb < 2; ++mb) {
        #pragma unroll
        for (int nn = 0; nn < 4; ++nn) {
            int col = cb + nn*8;
            float b0 = bias[col], b1 = bias[col+1];
            size_t ra = (size_t)(rbase + mb*16) * HD + col;
            size_t rb = (size_t)(rbase + mb*16 + 8) * HD + col;
            *(unsigned*)(g_posb + ra) = pk2(acc[mb][nn][0] + b0, acc[mb][nn][1] + b1);
            *(unsigned*)(g_posb + rb) = pk2(acc[mb][nn][2] + b0, acc[mb][nn][3] + b1);
        }
    }
}

// ---------------- fused attention ----------------
__global__ void __launch_bounds__(128) k_attn(float* __restrict__ attn_out) {
    __shared__ int   idx_s[16];
    __shared__ float pos_s[16][68];
    __shared__ float k_s[16][260];
    __shared__ float v_s[16][260];
    __shared__ float q_s[256];
    __shared__ float logit_s[64];
    __shared__ float attn_s[64];
    int t  = threadIdx.x;
    int gp = blockIdx.x;
    int b  = gp >> 13, n = gp & (NPTS-1);

    if (t < 16) idx_s[t] = g_knn[gp*KNBR + t];
    if (t < 64) ((float4*)q_s)[t] = ((const float4*)(g_qkv + (size_t)gp * 768))[t];
    {
        const uint2* ps = (const uint2*)(g_posb + (size_t)gp * KNBR * HD);
        #pragma unroll
        for (int e = t; e < 256; e += 128) {
            int jj = e >> 4, cc = e & 15;
            uint2 u = ps[e];
            float2 f0 = __bfloat1622float2(*(__nv_bfloat162*)&u.x);
            float2 f1 = __bfloat1622float2(*(__nv_bfloat162*)&u.y);
            *(float4*)&pos_s[jj][cc*4] = make_float4(f0.x, f0.y, f1.x, f1.y);
        }
    }
    __syncthreads();
    #pragma unroll
    for (int e = t; e < 1024; e += 128) {
        int jj = e >> 6, cc = e & 63;
        size_t rowb = ((size_t)b * NPTS + idx_s[jj]) * 768;
        *(float4*)&k_s[jj][cc*4] = *(const float4*)(g_qkv + rowb + 256 + cc*4);
        *(float4*)&v_s[jj][cc*4] = *(const float4*)(g_qkv + rowb + 512 + cc*4);
    }
    __syncthreads();
    {
        int p = t >> 1, half = t & 1;
        int jj = p & 15, h = p >> 4;
        float s = 0.f;
        int cbs = half * 32;
        #pragma unroll
        for (int c = 0; c < 32; ++c) {
            int cc = cbs + c;
            s = fmaf(q_s[h*64+cc], k_s[jj][h*64+cc] + pos_s[jj][cc], s);
        }
        s += __shfl_xor_sync(~0u, s, 1);
        if (half == 0) logit_s[h*16 + jj] = s * 0.125f;
    }
    __syncthreads();
    if (t < 4) {
        int h = t;
        float l[16], mx = -3.402823e38f;
        #pragma unroll
        for (int j = 0; j < 16; ++j) { l[j] = logit_s[h*16+j]; mx = fmaxf(mx, l[j]); }
        float sum = 0.f;
        #pragma unroll
        for (int j = 0; j < 16; ++j) { l[j] = expf(l[j] - mx); sum += l[j]; }
        float inv = 1.f / sum;
        size_t ob = (((size_t)b*NH + h) * NPTS + n) * KNBR;
        #pragma unroll
        for (int j = 0; j < 16; ++j) {
            float a = l[j] * inv;
            attn_s[h*16+j] = a;
            attn_out[ob + j] = a;
        }
    }
    __syncthreads();
    #pragma unroll
    for (int e = t; e < 256; e += 128) {
        int h = e >> 6, c = e & 63;
        float s = 0.f;
        #pragma unroll
        for (int j = 0; j < 16; ++j)
            s = fmaf(attn_s[h*16+j], v_s[j][e] + pos_s[j][c], s);
        float hs = rndbf(s);
        g_mid_h[(size_t)gp * DOUT + e] = __float2bfloat16_rn(s);
        g_mid_l[(size_t)gp * DOUT + e] = __float2bfloat16_rn(s - hs);
    }
}

// ---------------- final: LN(fc2)*g2+b2 + lnq -> out ----------------
__global__ void k_final(const float* __restrict__ g2, const float* __restrict__ b2,
                        float* __restrict__ out) {
    int warp = (blockIdx.x * blockDim.x + threadIdx.x) >> 5;
    int lane = threadIdx.x & 31;
    const float4* row = (const float4*)(g_fc2 + (size_t)warp * DOUT);
    float4 v0 = row[lane*2], v1 = row[lane*2+1];
    float s = v0.x+v0.y+v0.z+v0.w + v1.x+v1.y+v1.z+v1.w;
    #pragma unroll
    for (int o = 16; o; o >>= 1) s += __shfl_xor_sync(~0u, s, o);
    float mu = s * (1.f/256.f);
    float d0x=v0.x-mu, d0y=v0.y-mu, d0z=v0.z-mu, d0w=v0.w-mu;
    float d1x=v1.x-mu, d1y=v1.y-mu, d1z=v1.z-mu, d1w=v1.w-mu;
    float s2 = d0x*d0x+d0y*d0y+d0z*d0z+d0w*d0w + d1x*d1x+d1y*d1y+d1z*d1z+d1w*d1w;
    #pragma unroll
    for (int o = 16; o; o >>= 1) s2 += __shfl_xor_sync(~0u, s2, o);
    float rs = rsqrtf(s2 * (1.f/256.f) + 1e-5f);
    float4 gA = ((const float4*)g2)[lane*2],  gB = ((const float4*)g2)[lane*2+1];
    float4 bA = ((const float4*)b2)[lane*2],  bB = ((const float4*)b2)[lane*2+1];
    const float4* lq = (const float4*)(g_lnq + (size_t)warp * DOUT);
    float4 qA = lq[lane*2], qB = lq[lane*2+1];
    float4 oA, oB;
    oA.x = d0x*rs*gA.x + bA.x + qA.x; oA.y = d0y*rs*gA.y + bA.y + qA.y;
    oA.z = d0z*rs*gA.z + bA.z + qA.z; oA.w = d0w*rs*gA.w + bA.w + qA.w;
    oB.x = d1x*rs*gB.x + bB.x + qB.x; oB.y = d1y*rs*gB.y + bB.y + qB.y;
    oB.z = d1z*rs*gB.z + bB.z + qB.z; oB.w = d1w*rs*gB.w + bB.w + qB.w;
    float4* dst = (float4*)(out + (size_t)warp * DOUT);
    dst[lane*2]   = oA;
    dst[lane*2+1] = oB;
}

// ---------------- host launcher ----------------
extern "C" void kernel_launch(void* const* d_in, const int* in_sizes, int n_in,
                              void* d_out, int out_size) {
    const float* xyz      = (const float*)d_in[0];
    const float* features = (const float*)d_in[1];
    const float* Wq  = (const float*)d_in[2];
    const float* bq  = (const float*)d_in[3];
    const float* Wk  = (const float*)d_in[4];
    const float* bk  = (const float*)d_in[5];
    const float* Wv  = (const float*)d_in[6];
    const float* bv  = (const float*)d_in[7];
    const float* Wp1 = (const float*)d_in[8];
    const float* bp1 = (const float*)d_in[9];
    const float* Wp2 = (const float*)d_in[10];
    const float* bp2 = (const float*)d_in[11];
    const float* Wf1 = (const float*)d_in[12];
    const float* bf1 = (const float*)d_in[13];
    const float* Wf2 = (const float*)d_in[14];
    const float* bf2 = (const float*)d_in[15];
    const float* g1  = (const float*)d_in[16];
    const float* b1  = (const float*)d_in[17];
    const float* g2  = (const float*)d_in[18];
    const float* b2  = (const float*)d_in[19];

    float* out      = (float*)d_out;
    float* attn_out = out + (size_t)ROWS * DOUT;

    #define SYM(p, s) float* p; cudaGetSymbolAddress((void**)&p, s)
    #define SYMB(p, s) __nv_bfloat16* p; cudaGetSymbolAddress((void**)&p, s)
    SYMB(p_feat_h, g_feat_h); SYMB(p_feat_l, g_feat_l);
    SYMB(p_lnf_h,  g_lnf_h);  SYMB(p_lnf_l,  g_lnf_l);
    SYM(p_qkv, g_qkv); SYM(p_lnq, g_lnq); SYM(p_fc2, g_fc2);
    SYMB(p_mid_h, g_mid_h); SYMB(p_mid_l, g_mid_l);
    SYMB(p_fc1_h, g_fc1_h); SYMB(p_fc1_l, g_fc1_l);
    SYMB(p_wqkvT_h, g_wqkvT_h); SYMB(p_wqkvT_l, g_wqkvT_l);
    SYMB(p_wf1T_h, g_wf1T_h);   SYMB(p_wf1T_l, g_wf1T_l);
    SYMB(p_wf2T_h, g_wf2T_h);   SYMB(p_wf2T_l, g_wf2T_l);
    SYM(p_bqkv, g_bqkv);

    static cudaStream_t s2 = nullptr;
    static cudaEvent_t evPrep = nullptr, evSide = nullptr;
    static bool attr_done = false;
    if (!attr_done) {
        cudaFuncSetAttribute(k_mgemm, cudaFuncAttributeMaxDynamicSharedMemorySize, MG_SMEM);
        cudaFuncSetAttribute(k_knn2,  cudaFuncAttributeMaxDynamicSharedMemorySize, SMEM_KNN);
        cudaFuncSetAttribute(k_pgemm, cudaFuncAttributeMaxDynamicSharedMemorySize, SMEM_PG);
        cudaStreamCreateWithFlags(&s2, cudaStreamNonBlocking);
        cudaEventCreateWithFlags(&evPrep, cudaEventDisableTiming);
        cudaEventCreateWithFlags(&evSide, cudaEventDisableTiming);
        attr_done = true;
    }

    // 1: merged prep (default stream)
    k_prep<<<PREP_BLOCKS, 256>>>(xyz, features, Wq, Wk, Wv, Wp2, Wf1, Wf2, g1, b1, bq, bk, bv);
    cudaEventRecord(evPrep, 0);

    // side branch (s2): knn -> pos
    cudaStreamWaitEvent(s2, evPrep, 0);
    {
        dim3 kg(NPTS/16, BATCH);
        k_knn2<<<kg, 512, SMEM_KNN, s2>>>();
    }
    k_pgemm<<<NROWS/128, 256, SMEM_PG, s2>>>(Wp1, bp1, bp2);
    cudaEventRecord(evSide, s2);

    // main branch (default): qkv + lnq merged GEMM
    {
        dim3 g(ROWS/128 * 2, 12);
        k_mgemm<<<g, 256, MG_SMEM>>>(p_feat_h, p_feat_l, p_wqkvT_h, p_wqkvT_l,
                                     p_bqkv, p_qkv, nullptr, nullptr, DIM, 768, 0,
                                     p_lnf_h, p_lnf_l, p_lnq, DOUT, ROWS/128);
    }

    // join, then attention
    cudaStreamWaitEvent(0, evSide, 0);
    k_attn<<<ROWS, 128>>>(attn_out);

    // fc1, fc2
    {
        dim3 g(ROWS/128, 4);
        k_mgemm<<<g, 256, MG_SMEM>>>(p_mid_h, p_mid_l, p_wf1T_h, p_wf1T_l,
                                     bf1, nullptr, p_fc1_h, p_fc1_l, DOUT, DOUT, 1,
                                     nullptr, nullptr, nullptr, 0, 0);
        k_mgemm<<<g, 256, MG_SMEM>>>(p_fc1_h, p_fc1_l, p_wf2T_h, p_wf2T_l,
                                     bf2, p_fc2, nullptr, nullptr, DOUT, DOUT, 0,
                                     nullptr, nullptr, nullptr, 0, 0);
    }

    // final LN + residual
    k_final<<<ROWS/8, 256>>>(g2, b2, out);
}

// round 9
// speedup vs baseline: 2.1278x; 1.0704x over previous
#include <cuda_runtime.h>
#include <cuda_bf16.h>
#include <cstdint>
#include <math.h>

#define BATCH 4
#define NPTS  8192
#define DIM   128
#define DOUT  256
#define NH    4
#define HD    64
#define KNBR  16
#define ROWS  (BATCH*NPTS)          // 32768
#define NROWS (BATCH*NPTS*KNBR)     // 524288

// ---------------- scratch (device globals; no runtime alloc) ----------------
__device__ float4 g_xyzw[ROWS];
__device__ int    g_knn[NROWS];
__device__ __nv_bfloat16 g_feat_h[ROWS*DIM];
__device__ __nv_bfloat16 g_feat_l[ROWS*DIM];
__device__ __nv_bfloat16 g_lnf_h[ROWS*DIM];
__device__ __nv_bfloat16 g_lnf_l[ROWS*DIM];
__device__ float  g_qkv[(size_t)ROWS*768];
__device__ float  g_lnq[ROWS*DOUT];
__device__ __nv_bfloat16 g_posb[(size_t)NROWS*HD];
__device__ __nv_bfloat16 g_mid_h[ROWS*DOUT];
__device__ __nv_bfloat16 g_mid_l[ROWS*DOUT];
__device__ __nv_bfloat16 g_fc1_h[ROWS*DOUT];
__device__ __nv_bfloat16 g_fc1_l[ROWS*DOUT];
__device__ float  g_fc2[ROWS*DOUT];
__device__ __nv_bfloat16 g_wqkvT_h[768*DIM];
__device__ __nv_bfloat16 g_wqkvT_l[768*DIM];
__device__ __nv_bfloat16 g_wp2T_h[HD*HD];
__device__ __nv_bfloat16 g_wf1T_h[DOUT*DOUT];
__device__ __nv_bfloat16 g_wf1T_l[DOUT*DOUT];
__device__ __nv_bfloat16 g_wf2T_h[DOUT*DOUT];
__device__ __nv_bfloat16 g_wf2T_l[DOUT*DOUT];
__device__ float g_bqkv[768];

// ---------------- small helpers ----------------
__device__ __forceinline__ unsigned pk2(float a, float b) {
    __nv_bfloat162 t = __floats2bfloat162_rn(a, b);
    return *(unsigned*)&t;
}
__device__ __forceinline__ float rndbf(float x) {
    return __bfloat162float(__float2bfloat16_rn(x));
}
__device__ __forceinline__ uint32_t smem_u32(const void* p) {
    uint32_t a;
    asm("{ .reg .u64 t; cvta.to.shared.u64 t, %1; cvt.u32.u64 %0, t; }" : "=r"(a) : "l"(p));
    return a;
}
__device__ __forceinline__ uint32_t swz(uint32_t x) { return x ^ ((x >> 3) & 0x70); }

__device__ __forceinline__ void ldsm4(uint32_t* r, uint32_t addr) {
    asm volatile("ldmatrix.sync.aligned.m8n8.x4.shared.b16 {%0,%1,%2,%3}, [%4];"
        : "=r"(r[0]), "=r"(r[1]), "=r"(r[2]), "=r"(r[3]) : "r"(addr));
}
__device__ __forceinline__ void mma16816(float* c, const uint32_t* a, uint32_t b0, uint32_t b1) {
    asm volatile("mma.sync.aligned.m16n8k16.row.col.f32.bf16.bf16.f32 "
        "{%0,%1,%2,%3}, {%4,%5,%6,%7}, {%8,%9}, {%0,%1,%2,%3};"
        : "+f"(c[0]), "+f"(c[1]), "+f"(c[2]), "+f"(c[3])
        : "r"(a[0]), "r"(a[1]), "r"(a[2]), "r"(a[3]), "r"(b0), "r"(b1));
}
#define CP16(dst, src) asm volatile("cp.async.cg.shared.global [%0], [%1], 16;" :: "r"(dst), "l"(src))
#define CP_COMMIT()    asm volatile("cp.async.commit_group;" ::: "memory")
#define CP_WAIT1()     asm volatile("cp.async.wait_group 1;" ::: "memory")

// ---------------- merged prep ----------------
#define PREP_BLOCKS 4284

__device__ __forceinline__ void tileT(const float* __restrict__ W,
                                      __nv_bfloat16* Th, __nv_bfloat16* Tl,
                                      int Kd, int Nd, int k0, int n0,
                                      int tid, float (*ts)[65]) {
    #pragma unroll
    for (int i = 0; i < 16; ++i) {
        int e = tid + i*256;
        int r = e >> 6, c = e & 63;
        ts[r][c] = W[(size_t)(k0 + r) * Nd + n0 + c];
    }
    __syncthreads();
    #pragma unroll
    for (int i = 0; i < 16; ++i) {
        int e = tid + i*256;
        int kk = e & 63, nn = e >> 6;
        float x = ts[kk][nn];
        size_t o = (size_t)(n0 + nn) * Kd + k0 + kk;
        float hx = rndbf(x);
        Th[o] = __float2bfloat16_rn(x);
        if (Tl) Tl[o] = __float2bfloat16_rn(x - hx);
    }
}

__global__ void __launch_bounds__(256) k_prep(
    const float* __restrict__ xyz, const float* __restrict__ features,
    const float* __restrict__ Wq, const float* __restrict__ Wk, const float* __restrict__ Wv,
    const float* __restrict__ Wp2, const float* __restrict__ Wf1, const float* __restrict__ Wf2,
    const float* __restrict__ g1, const float* __restrict__ b1,
    const float* __restrict__ bq, const float* __restrict__ bk, const float* __restrict__ bv)
{
    __shared__ float ts[64][65];
    int bid = blockIdx.x, tid = threadIdx.x;
    if (bid < 128) {
        int i = bid * 256 + tid;
        float x = xyz[i*3+0], y = xyz[i*3+1], z = xyz[i*3+2];
        g_xyzw[i] = make_float4(x, y, z, x*x + y*y + z*z);
    } else if (bid < 4224) {
        int row = (bid - 128) * 8 + (tid >> 5);
        int lane = tid & 31;
        float4 v = ((const float4*)(features + (size_t)row * DIM))[lane];
        int idx = row*32 + lane;
        {
            float hx = rndbf(v.x), hy = rndbf(v.y), hz = rndbf(v.z), hw = rndbf(v.w);
            ((uint2*)g_feat_h)[idx] = make_uint2(pk2(v.x, v.y), pk2(v.z, v.w));
            ((uint2*)g_feat_l)[idx] = make_uint2(pk2(v.x-hx, v.y-hy), pk2(v.z-hz, v.w-hw));
        }
        float s = v.x + v.y + v.z + v.w;
        #pragma unroll
        for (int o = 16; o; o >>= 1) s += __shfl_xor_sync(~0u, s, o);
        float mu = s * (1.f/128.f);
        float dx = v.x-mu, dy = v.y-mu, dz = v.z-mu, dw = v.w-mu;
        float s2 = dx*dx + dy*dy + dz*dz + dw*dw;
        #pragma unroll
        for (int o = 16; o; o >>= 1) s2 += __shfl_xor_sync(~0u, s2, o);
        float rs = rsqrtf(s2 * (1.f/128.f) + 1e-5f);
        float4 gg = ((const float4*)g1)[lane];
        float4 bb = ((const float4*)b1)[lane];
        float rx = dx*rs*gg.x + bb.x, ry = dy*rs*gg.y + bb.y;
        float rz = dz*rs*gg.z + bb.z, rw = dw*rs*gg.w + bb.w;
        float hx = rndbf(rx), hy = rndbf(ry), hz = rndbf(rz), hw = rndbf(rw);
        ((uint2*)g_lnf_h)[idx] = make_uint2(pk2(rx, ry), pk2(rz, rw));
        ((uint2*)g_lnf_l)[idx] = make_uint2(pk2(rx-hx, ry-hy), pk2(rz-hz, rw-hw));
    } else if (bid < 4248) {
        int b2 = bid - 4224;
        int m = b2 >> 3, tt = b2 & 7;
        const float* W = m == 0 ? Wq : (m == 1 ? Wk : Wv);
        tileT(W, g_wqkvT_h + m*256*DIM, g_wqkvT_l + m*256*DIM,
              DIM, DOUT, (tt & 1)*64, (tt >> 1)*64, tid, ts);
    } else if (bid < 4249) {
        tileT(Wp2, g_wp2T_h, nullptr, HD, HD, 0, 0, tid, ts);
    } else if (bid < 4265) {
        int b2 = bid - 4249;
        tileT(Wf1, g_wf1T_h, g_wf1T_l, DOUT, DOUT, (b2 & 3)*64, (b2 >> 2)*64, tid, ts);
    } else if (bid < 4281) {
        int b2 = bid - 4265;
        tileT(Wf2, g_wf2T_h, g_wf2T_l, DOUT, DOUT, (b2 & 3)*64, (b2 >> 2)*64, tid, ts);
    } else {
        int t = (bid - 4281) * 256 + tid;
        if (t < 256)      g_bqkv[t] = bq[t];
        else if (t < 512) g_bqkv[t] = bk[t-256];
        else              g_bqkv[t] = bv[t-512];
    }
}

// ---------------- KNN ----------------
#define KNN_CAP 256
#define SMEM_KNN (32768 + 16*KNN_CAP*8)

__global__ void __launch_bounds__(512) k_knn2() {
    extern __shared__ char sk[];
    float4* tile = (float4*)sk;
    float*  bkey = (float*)(sk + 32768);
    int*    bidx = (int*)(sk + 32768 + 16*KNN_CAP*4);
    int t = threadIdx.x, lane = t & 31, w = t >> 5;
    int b = blockIdx.y;
    int q = blockIdx.x * 16 + w;
    const float INF = 3.402823e38f;

    float4 me = g_xyzw[b*NPTS + q];
    float qx2 = -2.f*me.x, qy2 = -2.f*me.y, qz2 = -2.f*me.z;

    float T = 0.f;
    int base = 0;
    float* mk = bkey + w*KNN_CAP;
    int*   mi = bidx + w*KNN_CAP;

    for (int ti = 0; ti < 4; ++ti) {
        __syncthreads();
        for (int i = t; i < 2048; i += 512)
            tile[i] = g_xyzw[b*NPTS + ti*2048 + i];
        __syncthreads();

        if (ti == 0) {
            float mn = INF;
            #pragma unroll 8
            for (int i = 0; i < 64; ++i) {
                float4 p = tile[i*32 + lane];
                float d = fmaf(qx2,p.x,fmaf(qy2,p.y,fmaf(qz2,p.z,p.w)));
                mn = fminf(mn, d);
            }
            float v = mn;
            #pragma unroll
            for (int k = 2; k <= 32; k <<= 1) {
                #pragma unroll
                for (int j = k >> 1; j > 0; j >>= 1) {
                    float o = __shfl_xor_sync(~0u, v, j);
                    bool up = ((lane & k) == 0);
                    bool lower = ((lane & j) == 0);
                    v = (lower == up) ? fminf(v, o) : fmaxf(v, o);
                }
            }
            T = __shfl_sync(~0u, v, 15);
        }

        #pragma unroll 4
        for (int c = 0; c < 64; ++c) {
            int j = c*32 + lane;
            float4 p = tile[j];
            float d = fmaf(qx2,p.x,fmaf(qy2,p.y,fmaf(qz2,p.z,p.w)));
            bool pass = (d <= T);
            unsigned m = __ballot_sync(~0u, pass);
            if (pass) {
                int pos = base + __popc(m & ((1u << lane) - 1u));
                if (pos < KNN_CAP) { mk[pos] = d; mi[pos] = ti*2048 + j; }
            }
            base += __popc(m);
        }
    }
    if (base > KNN_CAP) base = KNN_CAP;
    __syncwarp();

    size_t ob = ((size_t)b*NPTS + q) * KNBR;
    for (int r = 0; r < KNBR; ++r) {
        float bk = INF; int bi = 0x7fffffff; int bp = -1;
        for (int i = lane; i < base; i += 32) {
            float kk = mk[i];
            int   ii = mi[i];
            if (kk < bk || (kk == bk && ii < bi)) { bk = kk; bi = ii; bp = i; }
        }
        #pragma unroll
        for (int o = 16; o; o >>= 1) {
            float ok = __shfl_xor_sync(~0u, bk, o);
            int   oi = __shfl_xor_sync(~0u, bi, o);
            int   op = __shfl_xor_sync(~0u, bp, o);
            if (ok < bk || (ok == bk && oi < bi)) { bk = ok; bi = oi; bp = op; }
        }
        if (lane == 0) {
            g_knn[ob + r] = bi;
            if (bp >= 0) mk[bp] = INF;
        }
        __syncwarp();
    }
}

// ---------------- mma GEMM: CTA 128x64, warp 32x32, 2 CTAs/SM, cp.async 2-stage ----------------
#define MG_STGB  24576
#define MG_SMEM  (2*MG_STGB)

__global__ void __launch_bounds__(256, 2) k_mgemm(
    const __nv_bfloat16* __restrict__ Ah, const __nv_bfloat16* __restrict__ Al,
    const __nv_bfloat16* __restrict__ Bh, const __nv_bfloat16* __restrict__ Bl,
    const float* __restrict__ bias,
    float* Cf, __nv_bfloat16* Ch, __nv_bfloat16* Cl,
    int K, int ldc, int relu)
{
    extern __shared__ char sm[];
    uint32_t smb = smem_u32(sm);
    int t = threadIdx.x, lane = t & 31, w = t >> 5;
    int wm = w & 3, wn = w >> 2;
    int c0 = blockIdx.y * 64;
    int r0 = blockIdx.x * 128;
    int nch = K >> 5;

    float acc[2][4][4];
    #pragma unroll
    for (int i = 0; i < 2; ++i)
        #pragma unroll
        for (int j = 0; j < 4; ++j)
            #pragma unroll
            for (int e = 0; e < 4; ++e) acc[i][j][e] = 0.f;

    int lrow = lane & 15;
    int lcb  = (lane >> 4) * 16;

    auto issue = [&](int c, int stg) {
        int kc = c * 32;
        uint32_t Ab = smb + stg*MG_STGB;
        uint32_t Bb = Ab + 16384;
        #pragma unroll
        for (int i = 0; i < 4; ++i) {
            int e = t + i*256;
            int row = e >> 3, seg = e & 7;
            const __nv_bfloat16* src = (seg < 4 ? Ah : Al) + (size_t)(r0+row)*K + kc + (seg & 3)*8;
            CP16(Ab + swz((uint32_t)row*128 + seg*16), src);
        }
        #pragma unroll
        for (int i = 0; i < 2; ++i) {
            int e = t + i*256;
            int row = e >> 3, seg = e & 7;
            const __nv_bfloat16* src = (seg < 4 ? Bh : Bl) + (size_t)(c0+row)*K + kc + (seg & 3)*8;
            CP16(Bb + swz((uint32_t)row*128 + seg*16), src);
        }
    };

    issue(0, 0); CP_COMMIT();
    issue(1, 1); CP_COMMIT();

    for (int c = 0; c < nch; ++c) {
        CP_WAIT1();
        __syncthreads();
        uint32_t Ab = smb + (c & 1)*MG_STGB;
        uint32_t Bb = Ab + 16384;
        #pragma unroll
        for (int s = 0; s < 2; ++s) {
            int kb = s*32 + lcb;
            uint32_t ah[2][4], al[2][4];
            #pragma unroll
            for (int mb = 0; mb < 2; ++mb) {
                uint32_t ro = (uint32_t)(wm*32 + mb*16 + lrow)*128;
                ldsm4(ah[mb], Ab + swz(ro + kb));
                ldsm4(al[mb], Ab + swz(ro + 64 + kb));
            }
            #pragma unroll
            for (int nb = 0; nb < 2; ++nb) {
                uint32_t bh[4], bl[4];
                uint32_t ro = (uint32_t)(wn*32 + nb*16 + lrow)*128;
                ldsm4(bh, Bb + swz(ro + kb));
                ldsm4(bl, Bb + swz(ro + 64 + kb));
                #pragma unroll
                for (int mb = 0; mb < 2; ++mb) {
                    float* cA = acc[mb][nb*2];
                    float* cB = acc[mb][nb*2+1];
                    mma16816(cA, ah[mb], bh[0], bh[2]);
                    mma16816(cB, ah[mb], bh[1], bh[3]);
                    mma16816(cA, ah[mb], bl[0], bl[2]);
                    mma16816(cB, ah[mb], bl[1], bl[3]);
                    mma16816(cA, al[mb], bh[0], bh[2]);
                    mma16816(cB, al[mb], bh[1], bh[3]);
                }
            }
        }
        __syncthreads();
        if (c + 2 < nch) issue(c + 2, c & 1);
        CP_COMMIT();
    }

    int rbase = r0 + wm*32 + (lane >> 2);
    int cb = c0 + wn*32 + (lane & 3)*2;
    #pragma unroll
    for (int mb = 0; mb < 2; ++mb) {
        #pragma unroll
        for (int nn = 0; nn < 4; ++nn) {
            int col = cb + nn*8;
            float b0 = bias[col], b1 = bias[col+1];
            float v0 = acc[mb][nn][0] + b0, v1 = acc[mb][nn][1] + b1;
            float v2 = acc[mb][nn][2] + b0, v3 = acc[mb][nn][3] + b1;
            if (relu) {
                v0 = fmaxf(v0, 0.f); v1 = fmaxf(v1, 0.f);
                v2 = fmaxf(v2, 0.f); v3 = fmaxf(v3, 0.f);
            }
            size_t ra = (size_t)(rbase + mb*16) * ldc + col;
            size_t rb = (size_t)(rbase + mb*16 + 8) * ldc + col;
            if (Cf) {
                *(float2*)(Cf + ra) = make_float2(v0, v1);
                *(float2*)(Cf + rb) = make_float2(v2, v3);
            }
            if (Ch) {
                float h0 = rndbf(v0), h1 = rndbf(v1), h2 = rndbf(v2), h3 = rndbf(v3);
                *(unsigned*)(Ch + ra) = pk2(v0, v1);
                *(unsigned*)(Cl + ra) = pk2(v0-h0, v1-h1);
                *(unsigned*)(Ch + rb) = pk2(v2, v3);
                *(unsigned*)(Cl + rb) = pk2(v2-h2, v3-h3);
            }
        }
    }
}

// ---------------- fused pos GEMM: smem Wp1, float4 xyzw, bf16 out ----------------
#define PG_A 0
#define PG_B 16384
#define PG_W 24576
#define SMEM_PG (24576 + 1024)

__global__ void __launch_bounds__(256) k_pgemm(
    const float* __restrict__ Wp1, const float* __restrict__ bp1,
    const float* __restrict__ bias)
{
    extern __shared__ char sm[];
    uint32_t smb = smem_u32(sm);
    float* ws = (float*)(sm + PG_W);
    int t = threadIdx.x, lane = t & 31, w = t >> 5;
    int wm = w & 3, wn = w >> 2;
    int r0 = blockIdx.x * 128;

    if (t < 192) ws[t] = Wp1[t];
    else ws[t] = bp1[t - 192];
    #pragma unroll 2
    for (int e = t; e < 512; e += 256) {
        int row = e >> 3, vo = e & 7;
        *(uint4*)(sm + PG_B + swz(row*128 + vo*16)) = *(const uint4*)(g_wp2T_h + row*64 + vo*8);
    }
    __syncthreads();

    {
        int row = t >> 1, ch = t & 1;
        int rr = r0 + row;
        int b = rr >> 17, n = (rr >> 4) & (NPTS - 1);
        int idx = g_knn[rr];
        float4 nbp = g_xyzw[(b << 13) + idx];
        float4 ctp = g_xyzw[(b << 13) + n];
        float rx = nbp.x - ctp.x, ry = nbp.y - ctp.y, rz = nbp.z - ctp.z;
        uint32_t hp[16];
        #pragma unroll
        for (int cc = 0; cc < 32; cc += 2) {
            int c = ch*32 + cc;
            float v0 = fmaf(rx, ws[c],   fmaf(ry, ws[64+c],   fmaf(rz, ws[128+c],   ws[192+c])));
            float v1 = fmaf(rx, ws[c+1], fmaf(ry, ws[64+c+1], fmaf(rz, ws[128+c+1], ws[192+c+1])));
            hp[cc>>1] = pk2(fmaxf(v0, 0.f), fmaxf(v1, 0.f));
        }
        uint32_t rbyte = (uint32_t)row*128 + ch*64;
        #pragma unroll
        for (int i = 0; i < 4; ++i)
            *(uint4*)(sm + PG_A + swz(rbyte + i*16)) = *(uint4*)&hp[i*4];
    }
    __syncthreads();

    float acc[2][4][4];
    #pragma unroll
    for (int i = 0; i < 2; ++i)
        #pragma unroll
        for (int j = 0; j < 4; ++j)
            #pragma unroll
            for (int e = 0; e < 4; ++e) acc[i][j][e] = 0.f;
    int lrow = lane & 15, lcolb = (lane >> 4) * 16;
    #pragma unroll
    for (int s = 0; s < 4; ++s) {
        int kb = s*32 + lcolb;
        uint32_t ah[2][4];
        #pragma unroll
        for (int mb = 0; mb < 2; ++mb)
            ldsm4(ah[mb], smb + PG_A + swz((uint32_t)(wm*32 + mb*16 + lrow)*128 + kb));
        #pragma unroll
        for (int nb = 0; nb < 2; ++nb) {
            uint32_t bh[4];
            ldsm4(bh, smb + PG_B + swz((uint32_t)(wn*32 + nb*16 + lrow)*128 + kb));
            #pragma unroll
            for (int mb = 0; mb < 2; ++mb) {
                mma16816(acc[mb][nb*2],   ah[mb], bh[0], bh[2]);
                mma16816(acc[mb][nb*2+1], ah[mb], bh[1], bh[3]);
            }
        }
    }

    int rbase = r0 + wm*32 + (lane >> 2);
    int cb = wn*32 + (lane & 3)*2;
    #pragma unroll
    for (int mb = 0; mb < 2; ++mb) {
        #pragma unroll
        for (int nn = 0; nn < 4; ++nn) {
            int col = cb + nn*8;
            float b0 = bias[col], b1 = bias[col+1];
            size_t ra = (size_t)(rbase + mb*16) * HD + col;
            size_t rb = (size_t)(rbase + mb*16 + 8) * HD + col;
            *(unsigned*)(g_posb + ra) = pk2(acc[mb][nn][0] + b0, acc[mb][nn][1] + b1);
            *(unsigned*)(g_posb + rb) = pk2(acc[mb][nn][2] + b0, acc[mb][nn][3] + b1);
        }
    }
}

// ---------------- fused attention: no k/v smem roundtrip waste, parallel softmax ----------------
__global__ void __launch_bounds__(128) k_attn(float* __restrict__ attn_out) {
    __shared__ int   idx_s[16];
    __shared__ float pos_s[16][68];
    __shared__ float k_s[16][260];
    __shared__ float q_s[256];
    __shared__ float logit_s[64];
    __shared__ float attn_s[64];
    int t  = threadIdx.x;
    int gp = blockIdx.x;
    int b  = gp >> 13, n = gp & (NPTS-1);

    if (t < 16) idx_s[t] = g_knn[gp*KNBR + t];
    if (t < 64) ((float4*)q_s)[t] = ((const float4*)(g_qkv + (size_t)gp * 768))[t];
    {
        const uint2* ps = (const uint2*)(g_posb + (size_t)gp * KNBR * HD);
        #pragma unroll
        for (int e = t; e < 256; e += 128) {
            int jj = e >> 4, cc = e & 15;
            uint2 u = ps[e];
            float2 f0 = __bfloat1622float2(*(__nv_bfloat162*)&u.x);
            float2 f1 = __bfloat1622float2(*(__nv_bfloat162*)&u.y);
            *(float4*)&pos_s[jj][cc*4] = make_float4(f0.x, f0.y, f1.x, f1.y);
        }
    }
    __syncthreads();
    // gather k only (v read direct in the weighted-sum phase)
    #pragma unroll
    for (int e = t; e < 1024; e += 128) {
        int jj = e >> 6, cc = e & 63;
        size_t rowb = ((size_t)b * NPTS + idx_s[jj]) * 768;
        *(float4*)&k_s[jj][cc*4] = *(const float4*)(g_qkv + rowb + 256 + cc*4);
    }
    __syncthreads();
    {
        int p = t >> 1, half = t & 1;
        int jj = p & 15, h = p >> 4;
        float s = 0.f;
        int cbs = half * 32;
        #pragma unroll
        for (int c = 0; c < 32; ++c) {
            int cc = cbs + c;
            s = fmaf(q_s[h*64+cc], k_s[jj][h*64+cc] + pos_s[jj][cc], s);
        }
        s += __shfl_xor_sync(~0u, s, 1);
        if (half == 0) logit_s[h*16 + jj] = s * 0.125f;
    }
    __syncthreads();
    // parallel softmax: 64 threads = 4 heads x 16 neighbors; 16-lane segment reductions
    if (t < 64) {
        int h2 = t >> 4, j2 = t & 15;
        float l = logit_s[t];
        float mx = l;
        #pragma unroll
        for (int o = 8; o; o >>= 1) mx = fmaxf(mx, __shfl_xor_sync(~0u, mx, o));
        float ex = expf(l - mx);
        float sum = ex;
        #pragma unroll
        for (int o = 8; o; o >>= 1) sum += __shfl_xor_sync(~0u, sum, o);
        float a = ex / sum;
        attn_s[t] = a;
        attn_out[(((size_t)b*NH + h2) * NPTS + n) * KNBR + j2] = a;
    }
    __syncthreads();
    // weighted sum: v loaded directly from global (each element consumed once)
    #pragma unroll
    for (int ee = 0; ee < 2; ++ee) {
        int e = t + ee*128;
        int h3 = e >> 6, c = e & 63;
        float s = 0.f;
        #pragma unroll
        for (int j = 0; j < 16; ++j) {
            float v = g_qkv[((size_t)b * NPTS + idx_s[j]) * 768 + 512 + e];
            s = fmaf(attn_s[h3*16 + j], v + pos_s[j][c], s);
        }
        float hs = rndbf(s);
        g_mid_h[(size_t)gp * DOUT + e] = __float2bfloat16_rn(s);
        g_mid_l[(size_t)gp * DOUT + e] = __float2bfloat16_rn(s - hs);
    }
}

// ---------------- final: LN(fc2)*g2+b2 + lnq -> out ----------------
__global__ void k_final(const float* __restrict__ g2, const float* __restrict__ b2,
                        float* __restrict__ out) {
    int warp = (blockIdx.x * blockDim.x + threadIdx.x) >> 5;
    int lane = threadIdx.x & 31;
    const float4* row = (const float4*)(g_fc2 + (size_t)warp * DOUT);
    float4 v0 = row[lane*2], v1 = row[lane*2+1];
    float s = v0.x+v0.y+v0.z+v0.w + v1.x+v1.y+v1.z+v1.w;
    #pragma unroll
    for (int o = 16; o; o >>= 1) s += __shfl_xor_sync(~0u, s, o);
    float mu = s * (1.f/256.f);
    float d0x=v0.x-mu, d0y=v0.y-mu, d0z=v0.z-mu, d0w=v0.w-mu;
    float d1x=v1.x-mu, d1y=v1.y-mu, d1z=v1.z-mu, d1w=v1.w-mu;
    float s2 = d0x*d0x+d0y*d0y+d0z*d0z+d0w*d0w + d1x*d1x+d1y*d1y+d1z*d1z+d1w*d1w;
    #pragma unroll
    for (int o = 16; o; o >>= 1) s2 += __shfl_xor_sync(~0u, s2, o);
    float rs = rsqrtf(s2 * (1.f/256.f) + 1e-5f);
    float4 gA = ((const float4*)g2)[lane*2],  gB = ((const float4*)g2)[lane*2+1];
    float4 bA = ((const float4*)b2)[lane*2],  bB = ((const float4*)b2)[lane*2+1];
    const float4* lq = (const float4*)(g_lnq + (size_t)warp * DOUT);
    float4 qA = lq[lane*2], qB = lq[lane*2+1];
    float4 oA, oB;
    oA.x = d0x*rs*gA.x + bA.x + qA.x; oA.y = d0y*rs*gA.y + bA.y + qA.y;
    oA.z = d0z*rs*gA.z + bA.z + qA.z; oA.w = d0w*rs*gA.w + bA.w + qA.w;
    oB.x = d1x*rs*gB.x + bB.x + qB.x; oB.y = d1y*rs*gB.y + bB.y + qB.y;
    oB.z = d1z*rs*gB.z + bB.z + qB.z; oB.w = d1w*rs*gB.w + bB.w + qB.w;
    float4* dst = (float4*)(out + (size_t)warp * DOUT);
    dst[lane*2]   = oA;
    dst[lane*2+1] = oB;
}

// ---------------- host launcher ----------------
extern "C" void kernel_launch(void* const* d_in, const int* in_sizes, int n_in,
                              void* d_out, int out_size) {
    const float* xyz      = (const float*)d_in[0];
    const float* features = (const float*)d_in[1];
    const float* Wq  = (const float*)d_in[2];
    const float* bq  = (const float*)d_in[3];
    const float* Wk  = (const float*)d_in[4];
    const float* bk  = (const float*)d_in[5];
    const float* Wv  = (const float*)d_in[6];
    const float* bv  = (const float*)d_in[7];
    const float* Wp1 = (const float*)d_in[8];
    const float* bp1 = (const float*)d_in[9];
    const float* Wp2 = (const float*)d_in[10];
    const float* bp2 = (const float*)d_in[11];
    const float* Wf1 = (const float*)d_in[12];
    const float* bf1 = (const float*)d_in[13];
    const float* Wf2 = (const float*)d_in[14];
    const float* bf2 = (const float*)d_in[15];
    const float* g1  = (const float*)d_in[16];
    const float* b1  = (const float*)d_in[17];
    const float* g2  = (const float*)d_in[18];
    const float* b2  = (const float*)d_in[19];

    float* out      = (float*)d_out;
    float* attn_out = out + (size_t)ROWS * DOUT;

    #define SYM(p, s) float* p; cudaGetSymbolAddress((void**)&p, s)
    #define SYMB(p, s) __nv_bfloat16* p; cudaGetSymbolAddress((void**)&p, s)
    SYMB(p_feat_h, g_feat_h); SYMB(p_feat_l, g_feat_l);
    SYMB(p_lnf_h,  g_lnf_h);  SYMB(p_lnf_l,  g_lnf_l);
    SYM(p_qkv, g_qkv); SYM(p_lnq, g_lnq); SYM(p_fc2, g_fc2);
    SYMB(p_mid_h, g_mid_h); SYMB(p_mid_l, g_mid_l);
    SYMB(p_fc1_h, g_fc1_h); SYMB(p_fc1_l, g_fc1_l);
    SYMB(p_wqkvT_h, g_wqkvT_h); SYMB(p_wqkvT_l, g_wqkvT_l);
    SYMB(p_wf1T_h, g_wf1T_h);   SYMB(p_wf1T_l, g_wf1T_l);
    SYMB(p_wf2T_h, g_wf2T_h);   SYMB(p_wf2T_l, g_wf2T_l);
    SYM(p_bqkv, g_bqkv);

    static cudaStream_t s2 = nullptr;
    static cudaEvent_t evPrep = nullptr, evSide = nullptr, evLnq = nullptr;
    static bool attr_done = false;
    if (!attr_done) {
        cudaFuncSetAttribute(k_mgemm, cudaFuncAttributeMaxDynamicSharedMemorySize, MG_SMEM);
        cudaFuncSetAttribute(k_knn2,  cudaFuncAttributeMaxDynamicSharedMemorySize, SMEM_KNN);
        cudaFuncSetAttribute(k_pgemm, cudaFuncAttributeMaxDynamicSharedMemorySize, SMEM_PG);
        cudaStreamCreateWithFlags(&s2, cudaStreamNonBlocking);
        cudaEventCreateWithFlags(&evPrep, cudaEventDisableTiming);
        cudaEventCreateWithFlags(&evSide, cudaEventDisableTiming);
        cudaEventCreateWithFlags(&evLnq, cudaEventDisableTiming);
        attr_done = true;
    }

    // 1: merged prep (default)
    k_prep<<<PREP_BLOCKS, 256>>>(xyz, features, Wq, Wk, Wv, Wp2, Wf1, Wf2, g1, b1, bq, bk, bv);
    cudaEventRecord(evPrep, 0);

    // side branch (s2): knn -> pos, then lnq (only needed by k_final)
    cudaStreamWaitEvent(s2, evPrep, 0);
    {
        dim3 kg(NPTS/16, BATCH);
        k_knn2<<<kg, 512, SMEM_KNN, s2>>>();
    }
    k_pgemm<<<NROWS/128, 256, SMEM_PG, s2>>>(Wp1, bp1, bp2);
    cudaEventRecord(evSide, s2);

    // main branch (default): qkv GEMM (clean grid, no empty blocks)
    {
        dim3 g(ROWS/128, 12);
        k_mgemm<<<g, 256, MG_SMEM>>>(p_feat_h, p_feat_l, p_wqkvT_h, p_wqkvT_l,
                                     p_bqkv, p_qkv, nullptr, nullptr, DIM, 768, 0);
    }

    // lnq GEMM on side stream (overlaps with attn/fc)
    {
        dim3 g(ROWS/128, 4);
        k_mgemm<<<g, 256, MG_SMEM, s2>>>(p_lnf_h, p_lnf_l, p_wqkvT_h, p_wqkvT_l,
                                         bq, p_lnq, nullptr, nullptr, DIM, DOUT, 0);
    }
    cudaEventRecord(evLnq, s2);

    // join (knn+pos ready), then attention
    cudaStreamWaitEvent(0, evSide, 0);
    k_attn<<<ROWS, 128>>>(attn_out);

    // fc1, fc2
    {
        dim3 g(ROWS/128, 4);
        k_mgemm<<<g, 256, MG_SMEM>>>(p_mid_h, p_mid_l, p_wf1T_h, p_wf1T_l,
                                     bf1, nullptr, p_fc1_h, p_fc1_l, DOUT, DOUT, 1);
        k_mgemm<<<g, 256, MG_SMEM>>>(p_fc1_h, p_fc1_l, p_wf2T_h, p_wf2T_l,
                                     bf2, p_fc2, nullptr, nullptr, DOUT, DOUT, 0);
    }

    // final LN + residual (needs lnq)
    cudaStreamWaitEvent(0, evLnq, 0);
    k_final<<<ROWS/8, 256>>>(g2, b2, out);
}